// round 1
// baseline (speedup 1.0000x reference)
#include <cuda_runtime.h>

#define NB   64
#define NL   512
#define NH   400
#define NEN  256
#define NEL  128
#define NLB  128
#define L1   513
#define NT   (NB * L1)     /* 32832 = 513*64 (tiles of 64 exact) */
#define ENCW 768

/* output layout (flattened tuple, float32):
   [0, 32768)          pred_heads[:,1:]
   [32768, 65536)      pred_lbl[:,1:]
   [65536, 98368)      labels1 (B x 513)
   [98368]             node_nll
   [98369]             label_nll                                   */
#define OUT_PH 0
#define OUT_PL 32768
#define OUT_LB 65536
#define OUT_NN 98368
#define OUT_LN 98369

/* -------- scratch (device globals; no allocation allowed) -------- */
__device__ float g_enc[(size_t)NT * ENCW];      /* enh|enm|elh|elm  */
__device__ float g_tmp[(size_t)NT * NEN];       /* enh @ ba_U       */
__device__ float g_dh[NT];
__device__ float g_em[NT];
__device__ float g_S[(size_t)NB * L1 * L1];     /* node scores      */
__device__ int   g_pred[NT];
__device__ float g_sg[(size_t)NLB * NT];        /* gold lbl scores (bilinear+Wl part) */
__device__ float g_sp[(size_t)NLB * NT];        /* pred lbl scores  */
__device__ float g_lin[(size_t)NLB * NT];       /* elm@Wr^T + b     */
__device__ float g_partA[17 * 64];              /* node nll partials */
__device__ float g_partB[129];                  /* label nll partials */

__device__ __forceinline__ float elu1(float x) { return x > 0.f ? x : expm1f(x); }
/* log(mask1[h]+mask1[m] + 1e-45) for mask sums in {0,1,2} (fp32 semantics) */
__device__ __forceinline__ float logmask(int s) {
    return s == 0 ? -103.27893f : (s == 1 ? 0.f : 0.69314718f);
}

/* ================= K1: fused encoder GEMM + ELU =================
   Y[t, 0:768] = elu([sentinel;memory_bank] @ [Wenh|Wenm|Welh|Welm] + bias)
   M=32832, N=768, K=400. 64x64x16 tiles, 4x4 per thread.            */
__global__ __launch_bounds__(256) void k_enc(
    const float* __restrict__ mem, const float* __restrict__ sent,
    const float* __restrict__ Wenh, const float* __restrict__ benh,
    const float* __restrict__ Wenm, const float* __restrict__ benm,
    const float* __restrict__ Welh, const float* __restrict__ belh,
    const float* __restrict__ Welm, const float* __restrict__ belm)
{
    __shared__ float As[16][64];
    __shared__ float Bs[16][64];
    const int tid = threadIdx.x;
    const int nb = blockIdx.y * 64;
    const float* W; const float* bias; int ldw, c0;
    if (nb < 256)      { W = Wenh; bias = benh; ldw = NEN; c0 = nb; }
    else if (nb < 512) { W = Wenm; bias = benm; ldw = NEN; c0 = nb - 256; }
    else if (nb < 640) { W = Welh; bias = belh; ldw = NEL; c0 = nb - 512; }
    else               { W = Welm; bias = belm; ldw = NEL; c0 = nb - 640; }

    const int ar = tid >> 2, ac = (tid & 3) * 4;        /* A: row, k-offset */
    const int t  = blockIdx.x * 64 + ar;
    const int b  = t / L1, l = t % L1;
    const float* arow = (l == 0) ? sent : (mem + ((size_t)b * NL + (l - 1)) * NH);
    const int bkr = tid >> 4, bnc = (tid & 15) * 4;     /* B: k-row, n-col */
    const float* brow = W + c0 + bnc;
    const int ty = tid >> 4, tx = tid & 15;
    float acc[4][4] = {};

    for (int k0 = 0; k0 < NH; k0 += 16) {
        float4 av = *(const float4*)(arow + k0 + ac);
        As[ac + 0][ar] = av.x; As[ac + 1][ar] = av.y;
        As[ac + 2][ar] = av.z; As[ac + 3][ar] = av.w;
        float4 bv = *(const float4*)(brow + (size_t)(k0 + bkr) * ldw);
        *(float4*)&Bs[bkr][bnc] = bv;
        __syncthreads();
#pragma unroll
        for (int k = 0; k < 16; k++) {
            float a[4], bb[4];
#pragma unroll
            for (int i = 0; i < 4; i++) a[i]  = As[k][ty * 4 + i];
#pragma unroll
            for (int j = 0; j < 4; j++) bb[j] = Bs[k][tx * 4 + j];
#pragma unroll
            for (int i = 0; i < 4; i++)
#pragma unroll
                for (int j = 0; j < 4; j++) acc[i][j] += a[i] * bb[j];
        }
        __syncthreads();
    }
    const int trow = blockIdx.x * 64 + ty * 4;
#pragma unroll
    for (int i = 0; i < 4; i++) {
        float4 v;
        v.x = elu1(acc[i][0] + bias[c0 + tx * 4 + 0]);
        v.y = elu1(acc[i][1] + bias[c0 + tx * 4 + 1]);
        v.z = elu1(acc[i][2] + bias[c0 + tx * 4 + 2]);
        v.w = elu1(acc[i][3] + bias[c0 + tx * 4 + 3]);
        *(float4*)&g_enc[(size_t)(trow + i) * ENCW + nb + tx * 4] = v;
    }
}

/* ================= K2: tmp = enh @ ba_U ================= */
__global__ __launch_bounds__(256) void k_tmp(const float* __restrict__ baU)
{
    __shared__ float As[16][64];
    __shared__ float Bs[16][64];
    const int tid = threadIdx.x;
    const int nb = blockIdx.y * 64;
    const int ar = tid >> 2, ac = (tid & 3) * 4;
    const int t = blockIdx.x * 64 + ar;
    const float* arow = g_enc + (size_t)t * ENCW;       /* enh cols 0..255 */
    const int bkr = tid >> 4, bnc = (tid & 15) * 4;
    const int ty = tid >> 4, tx = tid & 15;
    float acc[4][4] = {};
    for (int k0 = 0; k0 < NEN; k0 += 16) {
        float4 av = *(const float4*)(arow + k0 + ac);
        As[ac + 0][ar] = av.x; As[ac + 1][ar] = av.y;
        As[ac + 2][ar] = av.z; As[ac + 3][ar] = av.w;
        float4 bv = *(const float4*)(baU + (size_t)(k0 + bkr) * NEN + nb + bnc);
        *(float4*)&Bs[bkr][bnc] = bv;
        __syncthreads();
#pragma unroll
        for (int k = 0; k < 16; k++) {
            float a[4], bb[4];
#pragma unroll
            for (int i = 0; i < 4; i++) a[i]  = As[k][ty * 4 + i];
#pragma unroll
            for (int j = 0; j < 4; j++) bb[j] = Bs[k][tx * 4 + j];
#pragma unroll
            for (int i = 0; i < 4; i++)
#pragma unroll
                for (int j = 0; j < 4; j++) acc[i][j] += a[i] * bb[j];
        }
        __syncthreads();
    }
    const int trow = blockIdx.x * 64 + ty * 4;
#pragma unroll
    for (int i = 0; i < 4; i++)
        *(float4*)&g_tmp[(size_t)(trow + i) * NEN + nb + tx * 4] = *(float4*)acc[i];
}

/* ============ K2b: dh = enh . ba_Wd, em = enm . ba_We ============ */
__global__ __launch_bounds__(256) void k_dotvec(
    const float* __restrict__ Wd, const float* __restrict__ We)
{
    const int gw = (blockIdx.x * blockDim.x + threadIdx.x) >> 5;
    const int lane = threadIdx.x & 31;
    if (gw >= NT) return;
    const float* r = g_enc + (size_t)gw * ENCW;
    float s1 = 0.f, s2 = 0.f;
#pragma unroll
    for (int k = lane; k < NEN; k += 32) {
        s1 += r[k] * Wd[k];
        s2 += r[256 + k] * We[k];
    }
#pragma unroll
    for (int o = 16; o; o >>= 1) {
        s1 += __shfl_xor_sync(0xffffffffu, s1, o);
        s2 += __shfl_xor_sync(0xffffffffu, s2, o);
    }
    if (!lane) { g_dh[gw] = s1; g_em[gw] = s2; }
}

/* ========== K3: S[b,h,m] = tmp[b,h] . enm[b,m] + dh + em + b ========== */
__global__ __launch_bounds__(256) void k_nodescore(const float* __restrict__ bab)
{
    __shared__ float As[16][64];
    __shared__ float Bs[16][64];
    const int tid = threadIdx.x;
    const int b = blockIdx.z;
    const int h0 = blockIdx.x * 64, m0 = blockIdx.y * 64;
    const int ar = tid >> 2, ac = (tid & 3) * 4;
    const int hA = h0 + ar, mB = m0 + ar;
    const bool aok = hA < L1, bok = mB < L1;
    const float* arow = g_tmp + (size_t)(b * L1 + (aok ? hA : 0)) * NEN;
    const float* brow = g_enc + (size_t)(b * L1 + (bok ? mB : 0)) * ENCW + 256;
    const int ty = tid >> 4, tx = tid & 15;
    float acc[4][4] = {};
    for (int k0 = 0; k0 < NEN; k0 += 16) {
        float4 av = aok ? *(const float4*)(arow + k0 + ac) : make_float4(0, 0, 0, 0);
        float4 bv = bok ? *(const float4*)(brow + k0 + ac) : make_float4(0, 0, 0, 0);
        As[ac + 0][ar] = av.x; As[ac + 1][ar] = av.y;
        As[ac + 2][ar] = av.z; As[ac + 3][ar] = av.w;
        Bs[ac + 0][ar] = bv.x; Bs[ac + 1][ar] = bv.y;
        Bs[ac + 2][ar] = bv.z; Bs[ac + 3][ar] = bv.w;
        __syncthreads();
#pragma unroll
        for (int k = 0; k < 16; k++) {
            float a[4], bb[4];
#pragma unroll
            for (int i = 0; i < 4; i++) a[i]  = As[k][ty * 4 + i];
#pragma unroll
            for (int j = 0; j < 4; j++) bb[j] = Bs[k][tx * 4 + j];
#pragma unroll
            for (int i = 0; i < 4; i++)
#pragma unroll
                for (int j = 0; j < 4; j++) acc[i][j] += a[i] * bb[j];
        }
        __syncthreads();
    }
    const float bb0 = bab[0];
#pragma unroll
    for (int i = 0; i < 4; i++) {
        int h = h0 + ty * 4 + i;
        if (h >= L1) continue;
        float dh = g_dh[b * L1 + h];
#pragma unroll
        for (int j = 0; j < 4; j++) {
            int m = m0 + tx * 4 + j;
            if (m >= L1) continue;
            g_S[((size_t)b * L1 + h) * L1 + m] = acc[i][j] + dh + g_em[b * L1 + m] + bb0;
        }
    }
}

/* ==== K4: per-column logsumexp over heads + gold pick + decode argmax ==== */
__global__ __launch_bounds__(256) void k_node_reduce(
    const int* __restrict__ eheads, const int* __restrict__ mask,
    float* __restrict__ out)
{
    const int b = blockIdx.y;
    const int m0 = blockIdx.x * 32;
    const int tid = threadIdx.x, lane = tid & 31, w = tid >> 5;
    __shared__ int mk[L1];
    __shared__ float s_max[8][32], s_sum[8][32], s_bv[8][32];
    __shared__ int s_bi[8][32];
    for (int i = tid; i < L1; i += 256) mk[i] = (i == 0) ? 0 : mask[b * NL + i - 1];
    __syncthreads();

    const int m = m0 + lane;
    const bool mv = m < L1;
    const int msafe = mv ? m : (L1 - 1);
    const int mm_ = mk[msafe];
    const float* Sb = g_S + (size_t)b * L1 * L1;

    float rmax = -1e30f, rsum = 0.f, bv = -1e30f;
    int bi = 0x7fffffff;
    for (int h = w; h < L1; h += 8) {
        float s = Sb[(size_t)h * L1 + msafe];
        int mh = mk[h];
        float x = s + logmask(mh + mm_);
        if (x > rmax) { rsum = rsum * expf(rmax - x) + 1.f; rmax = x; }
        else            rsum += expf(x - rmax);
        float dv = s + (1.f - (float)mh) * (-1e8f);
        if (h != msafe && dv > bv) { bv = dv; bi = h; }
    }
    s_max[w][lane] = rmax; s_sum[w][lane] = rsum;
    s_bv[w][lane] = bv;    s_bi[w][lane] = bi;
    __syncthreads();

    if (w == 0) {
        float tm = -1e30f;
#pragma unroll
        for (int i = 0; i < 8; i++) tm = fmaxf(tm, s_max[i][lane]);
        float ts = 0.f;
#pragma unroll
        for (int i = 0; i < 8; i++) ts += s_sum[i][lane] * expf(s_max[i][lane] - tm);
        float lse = tm + logf(ts);
        int gh = (msafe == 0) ? 0 : eheads[b * NL + msafe - 1];
        float xg = Sb[(size_t)gh * L1 + msafe] + logmask(mk[gh] + mm_);
        float bbv = -1e30f; int bbi = 0x7fffffff;
#pragma unroll
        for (int i = 0; i < 8; i++) {
            float v = s_bv[i][lane]; int ix = s_bi[i][lane];
            if (v > bbv || (v == bbv && ix < bbi)) { bbv = v; bbi = ix; }
        }
        float contrib = 0.f;
        if (mv) {
            g_pred[b * L1 + m] = bbi;
            if (m >= 1) {
                out[OUT_PH + (size_t)b * NL + m - 1] = (float)bbi;
                contrib = -(xg - lse);
            }
        }
#pragma unroll
        for (int o = 16; o; o >>= 1) contrib += __shfl_xor_sync(0xffffffffu, contrib, o);
        if (lane == 0) g_partA[blockIdx.y * 17 + blockIdx.x] = contrib;
    }
}

/* ===== K5: label bilinear, one n per block.y, 64-token tiles.
   M[t,d] = sum_e U[n,d,e]*elm[t,e]; sg = G.(M+Wl), sp = P.(M+Wl) ===== */
__global__ __launch_bounds__(256) void k_bilin(
    const float* __restrict__ U, const float* __restrict__ Wl,
    const int* __restrict__ eheads)
{
    __shared__ float As[16][64];     /* [e][token] */
    __shared__ float Bs[16][128];    /* [e][d]     */
    const int tid = threadIdx.x;
    const int n = blockIdx.y;
    const int t0 = blockIdx.x * 64;
    const int ar = tid >> 2, ac = (tid & 3) * 4;
    const float* arow = g_enc + (size_t)(t0 + ar) * ENCW + 640;   /* elm */
    const int dB = tid >> 1, eB = (tid & 1) * 8;
    const float* Ub = U + ((size_t)n * NEL + dB) * NEL + eB;
    const int ty = tid >> 4, tx = tid & 15;
    float acc[4][8] = {};
    for (int e0 = 0; e0 < NEL; e0 += 16) {
        float4 av = *(const float4*)(arow + e0 + ac);
        As[ac + 0][ar] = av.x; As[ac + 1][ar] = av.y;
        As[ac + 2][ar] = av.z; As[ac + 3][ar] = av.w;
        float4 u0 = *(const float4*)(Ub + e0);
        float4 u1 = *(const float4*)(Ub + e0 + 4);
        Bs[eB + 0][dB] = u0.x; Bs[eB + 1][dB] = u0.y;
        Bs[eB + 2][dB] = u0.z; Bs[eB + 3][dB] = u0.w;
        Bs[eB + 4][dB] = u1.x; Bs[eB + 5][dB] = u1.y;
        Bs[eB + 6][dB] = u1.z; Bs[eB + 7][dB] = u1.w;
        __syncthreads();
#pragma unroll
        for (int k = 0; k < 16; k++) {
            float a[4], bb[8];
#pragma unroll
            for (int i = 0; i < 4; i++) a[i]  = As[k][ty * 4 + i];
#pragma unroll
            for (int j = 0; j < 8; j++) bb[j] = Bs[k][tx * 8 + j];
#pragma unroll
            for (int i = 0; i < 4; i++)
#pragma unroll
                for (int j = 0; j < 8; j++) acc[i][j] += a[i] * bb[j];
        }
        __syncthreads();
    }
    float4 wl0 = *(const float4*)(Wl + n * NEL + tx * 8);
    float4 wl1 = *(const float4*)(Wl + n * NEL + tx * 8 + 4);
    float wl[8] = { wl0.x, wl0.y, wl0.z, wl0.w, wl1.x, wl1.y, wl1.z, wl1.w };
    float pg[4], pp[4];
#pragma unroll
    for (int i = 0; i < 4; i++) {
        int t = t0 + ty * 4 + i;
        int b = t / L1, l = t % L1;
        int gh = (l == 0) ? 0 : eheads[b * NL + l - 1];
        const float* Gr = g_enc + (size_t)(b * L1 + gh) * ENCW + 512 + tx * 8;
        int ph = g_pred[t];
        const float* Pr = g_enc + (size_t)(b * L1 + ph) * ENCW + 512 + tx * 8;
        float4 gA = *(const float4*)Gr, gB = *(const float4*)(Gr + 4);
        float4 pA = *(const float4*)Pr, pB = *(const float4*)(Pr + 4);
        float g8[8] = { gA.x, gA.y, gA.z, gA.w, gB.x, gB.y, gB.z, gB.w };
        float p8[8] = { pA.x, pA.y, pA.z, pA.w, pB.x, pB.y, pB.z, pB.w };
        float sg = 0.f, sp = 0.f;
#pragma unroll
        for (int j = 0; j < 8; j++) {
            float c2 = acc[i][j] + wl[j];
            sg += g8[j] * c2;
            sp += p8[j] * c2;
        }
        pg[i] = sg; pp[i] = sp;
    }
#pragma unroll
    for (int o = 8; o; o >>= 1) {
#pragma unroll
        for (int i = 0; i < 4; i++) {
            pg[i] += __shfl_xor_sync(0xffffffffu, pg[i], o);
            pp[i] += __shfl_xor_sync(0xffffffffu, pp[i], o);
        }
    }
    if (tx == 0) {
#pragma unroll
        for (int i = 0; i < 4; i++) {
            int t = t0 + ty * 4 + i;
            g_sg[(size_t)n * NT + t] = pg[i];
            g_sp[(size_t)n * NT + t] = pp[i];
        }
    }
}

/* ===== K5b: lin[n,t] = elm[t] . Wr[n] + lbl_b[n] ===== */
__global__ __launch_bounds__(256) void k_lin(
    const float* __restrict__ Wr, const float* __restrict__ lb)
{
    __shared__ float As[16][64];
    __shared__ float Bs[16][64];
    const int tid = threadIdx.x;
    const int t0 = blockIdx.x * 64, n0 = blockIdx.y * 64;
    const int ar = tid >> 2, ac = (tid & 3) * 4;
    const float* arow = g_enc + (size_t)(t0 + ar) * ENCW + 640;
    const float* brow = Wr + (size_t)(n0 + ar) * NEL;
    const int ty = tid >> 4, tx = tid & 15;
    float acc[4][4] = {};
    for (int k0 = 0; k0 < NEL; k0 += 16) {
        float4 av = *(const float4*)(arow + k0 + ac);
        float4 bv = *(const float4*)(brow + k0 + ac);
        As[ac + 0][ar] = av.x; As[ac + 1][ar] = av.y;
        As[ac + 2][ar] = av.z; As[ac + 3][ar] = av.w;
        Bs[ac + 0][ar] = bv.x; Bs[ac + 1][ar] = bv.y;
        Bs[ac + 2][ar] = bv.z; Bs[ac + 3][ar] = bv.w;
        __syncthreads();
#pragma unroll
        for (int k = 0; k < 16; k++) {
            float a[4], bb[4];
#pragma unroll
            for (int i = 0; i < 4; i++) a[i]  = As[k][ty * 4 + i];
#pragma unroll
            for (int j = 0; j < 4; j++) bb[j] = Bs[k][tx * 4 + j];
#pragma unroll
            for (int i = 0; i < 4; i++)
#pragma unroll
                for (int j = 0; j < 4; j++) acc[i][j] += a[i] * bb[j];
        }
        __syncthreads();
    }
#pragma unroll
    for (int i = 0; i < 4; i++) {
        int t = t0 + ty * 4 + i;
#pragma unroll
        for (int j = 0; j < 4; j++) {
            int nn = n0 + tx * 4 + j;
            g_lin[(size_t)nn * NT + t] = acc[i][j] + lb[nn];
        }
    }
}

/* ===== K6: label log-softmax over n (gold pick) + max over n (pred) ===== */
__global__ __launch_bounds__(256) void k_lbl_reduce(
    const int* __restrict__ elabels, float* __restrict__ out)
{
    __shared__ float red[256];
    const int t = blockIdx.x * 256 + threadIdx.x;
    float contrib = 0.f;
    if (t < NT) {
        int b = t / L1, l = t % L1;
        int lab = (l == 0) ? 0 : elabels[b * NL + l - 1];
        float mg = -1e30f, sg = 0.f, mp = -1e30f, xlab = 0.f;
        for (int n = 0; n < NLB; n++) {
            float lin = g_lin[(size_t)n * NT + t];
            float xg = g_sg[(size_t)n * NT + t] + lin;
            float xp = g_sp[(size_t)n * NT + t] + lin;
            if (n == lab) xlab = xg;
            if (xg > mg) { sg = sg * expf(mg - xg) + 1.f; mg = xg; }
            else           sg += expf(xg - mg);
            mp = fmaxf(mp, xp);
        }
        float ll = xlab - (mg + logf(sg));
        if (l >= 1) {
            contrib = -ll;
            out[OUT_PL + (size_t)b * NL + l - 1] = mp;
        }
    }
    red[threadIdx.x] = contrib;
    __syncthreads();
    for (int s = 128; s; s >>= 1) {
        if (threadIdx.x < s) red[threadIdx.x] += red[threadIdx.x + s];
        __syncthreads();
    }
    if (!threadIdx.x) g_partB[blockIdx.x] = red[0];
}

/* ===== K7: labels1 output + deterministic NLL finalize ===== */
__global__ __launch_bounds__(256) void k_final(
    const int* __restrict__ elabels, float* __restrict__ out)
{
    const int i = blockIdx.x * 256 + threadIdx.x;
    if (i < NT) {
        int b = i / L1, l = i % L1;
        out[OUT_LB + i] = (l == 0) ? 0.f : (float)elabels[b * NL + l - 1];
    }
    if (i == 0) {
        float s = 0.f;
        for (int k = 0; k < 17 * 64; k++) s += g_partA[k];
        out[OUT_NN] = s;
        float s2 = 0.f;
        for (int k = 0; k < 129; k++) s2 += g_partB[k];
        out[OUT_LN] = s2;
    }
}

extern "C" void kernel_launch(void* const* d_in, const int* in_sizes, int n_in,
                              void* d_out, int out_size)
{
    const float* mem    = (const float*)d_in[0];
    const int*   eheads = (const int*)d_in[1];
    const int*   elabs  = (const int*)d_in[2];
    /* d_in[3] = corefs: unused by reference */
    const int*   mask   = (const int*)d_in[4];
    const float* sent   = (const float*)d_in[5];
    const float* Wenh = (const float*)d_in[6];  const float* benh = (const float*)d_in[7];
    const float* Wenm = (const float*)d_in[8];  const float* benm = (const float*)d_in[9];
    const float* Welh = (const float*)d_in[10]; const float* belh = (const float*)d_in[11];
    const float* Welm = (const float*)d_in[12]; const float* belm = (const float*)d_in[13];
    const float* baU  = (const float*)d_in[14];
    const float* baWd = (const float*)d_in[15];
    const float* baWe = (const float*)d_in[16];
    const float* bab  = (const float*)d_in[17];
    const float* lU   = (const float*)d_in[18];
    const float* lWl  = (const float*)d_in[19];
    const float* lWr  = (const float*)d_in[20];
    const float* lb   = (const float*)d_in[21];
    float* out = (float*)d_out;

    k_enc<<<dim3(513, 12), 256>>>(mem, sent, Wenh, benh, Wenm, benm,
                                  Welh, belh, Welm, belm);
    k_tmp<<<dim3(513, 4), 256>>>(baU);
    k_dotvec<<<4104, 256>>>(baWd, baWe);
    k_nodescore<<<dim3(9, 9, 64), 256>>>(bab);
    k_node_reduce<<<dim3(17, 64), 256>>>(eheads, mask, out);
    k_lin<<<dim3(513, 2), 256>>>(lWr, lb);
    k_bilin<<<dim3(513, 128), 256>>>(lU, lWl, eheads);
    k_lbl_reduce<<<129, 256>>>(elabs, out);
    k_final<<<129, 256>>>(elabs, out);
}

// round 3
// speedup vs baseline: 2.4670x; 2.4670x over previous
#include <cuda_runtime.h>

#define NB   64
#define NL   512
#define NH   400
#define NEN  256
#define NEL  128
#define NLB  128
#define L1   513
#define NT   (NB * L1)     /* 32832 */
#define ENCW 768
#define TILE_T 128
#define NTILES 257         /* ceil(32832/128) */

/* output layout (flattened tuple, float32) */
#define OUT_PH 0
#define OUT_PL 32768
#define OUT_LB 65536
#define OUT_NN 98368
#define OUT_LN 98369

/* -------- scratch (device globals; no allocation allowed) -------- */
__device__ float g_enc[(size_t)NT * ENCW];      /* enh|enm|elh|elm  */
__device__ float g_tmp[(size_t)NT * NEN];       /* enh @ ba_U       */
__device__ float g_dh[NT];
__device__ float g_em[NT];
__device__ float g_S[(size_t)NB * L1 * L1];     /* node scores      */
__device__ int   g_pred[NT];
__device__ float g_sg[(size_t)NLB * NT];        /* gold label bilinear+Wl part */
__device__ float g_sp[(size_t)NLB * NT];        /* pred label part  */
__device__ float g_lin[(size_t)NLB * NT];       /* elm@Wr^T + b     */
__device__ float g_partA[17 * 64];
__device__ float g_partB[129];

__device__ __forceinline__ float elu1(float x) { return x > 0.f ? x : expm1f(x); }
__device__ __forceinline__ float logmask(int s) {
    return s == 0 ? -103.27893f : (s == 1 ? 0.f : 0.69314718f);
}
__device__ __forceinline__ unsigned f2tf32(float v) {
    unsigned t;
    asm("cvt.rna.tf32.f32 %0, %1;" : "=r"(t) : "f"(v));
    return t;
}
__device__ __forceinline__ void mma_tf32(float* c, unsigned a0, unsigned a1,
                                         unsigned a2, unsigned a3,
                                         unsigned b0, unsigned b1) {
    asm volatile(
        "mma.sync.aligned.m16n8k8.row.col.f32.tf32.tf32.f32 "
        "{%0,%1,%2,%3}, {%4,%5,%6,%7}, {%8,%9}, {%0,%1,%2,%3};\n"
        : "+f"(c[0]), "+f"(c[1]), "+f"(c[2]), "+f"(c[3])
        : "r"(a0), "r"(a1), "r"(a2), "r"(a3), "r"(b0), "r"(b1));
}

/* ================= K1: fused encoder GEMM + ELU ================= */
__global__ __launch_bounds__(256) void k_enc(
    const float* __restrict__ mem, const float* __restrict__ sent,
    const float* __restrict__ Wenh, const float* __restrict__ benh,
    const float* __restrict__ Wenm, const float* __restrict__ benm,
    const float* __restrict__ Welh, const float* __restrict__ belh,
    const float* __restrict__ Welm, const float* __restrict__ belm)
{
    __shared__ float As[16][64];
    __shared__ float Bs[16][64];
    const int tid = threadIdx.x;
    const int nb = blockIdx.y * 64;
    const float* W; const float* bias; int ldw, c0;
    if (nb < 256)      { W = Wenh; bias = benh; ldw = NEN; c0 = nb; }
    else if (nb < 512) { W = Wenm; bias = benm; ldw = NEN; c0 = nb - 256; }
    else if (nb < 640) { W = Welh; bias = belh; ldw = NEL; c0 = nb - 512; }
    else               { W = Welm; bias = belm; ldw = NEL; c0 = nb - 640; }

    const int ar = tid >> 2, ac = (tid & 3) * 4;
    const int t  = blockIdx.x * 64 + ar;
    const int b  = t / L1, l = t % L1;
    const float* arow = (l == 0) ? sent : (mem + ((size_t)b * NL + (l - 1)) * NH);
    const int bkr = tid >> 4, bnc = (tid & 15) * 4;
    const float* brow = W + c0 + bnc;
    const int ty = tid >> 4, tx = tid & 15;
    float acc[4][4] = {};

    for (int k0 = 0; k0 < NH; k0 += 16) {
        float4 av = *(const float4*)(arow + k0 + ac);
        As[ac + 0][ar] = av.x; As[ac + 1][ar] = av.y;
        As[ac + 2][ar] = av.z; As[ac + 3][ar] = av.w;
        float4 bv = *(const float4*)(brow + (size_t)(k0 + bkr) * ldw);
        *(float4*)&Bs[bkr][bnc] = bv;
        __syncthreads();
#pragma unroll
        for (int k = 0; k < 16; k++) {
            float a[4], bb[4];
#pragma unroll
            for (int i = 0; i < 4; i++) a[i]  = As[k][ty * 4 + i];
#pragma unroll
            for (int j = 0; j < 4; j++) bb[j] = Bs[k][tx * 4 + j];
#pragma unroll
            for (int i = 0; i < 4; i++)
#pragma unroll
                for (int j = 0; j < 4; j++) acc[i][j] += a[i] * bb[j];
        }
        __syncthreads();
    }
    const int trow = blockIdx.x * 64 + ty * 4;
#pragma unroll
    for (int i = 0; i < 4; i++) {
        float4 v;
        v.x = elu1(acc[i][0] + bias[c0 + tx * 4 + 0]);
        v.y = elu1(acc[i][1] + bias[c0 + tx * 4 + 1]);
        v.z = elu1(acc[i][2] + bias[c0 + tx * 4 + 2]);
        v.w = elu1(acc[i][3] + bias[c0 + tx * 4 + 3]);
        *(float4*)&g_enc[(size_t)(trow + i) * ENCW + nb + tx * 4] = v;
    }
}

/* ================= K2: tmp = enh @ ba_U ================= */
__global__ __launch_bounds__(256) void k_tmp(const float* __restrict__ baU)
{
    __shared__ float As[16][64];
    __shared__ float Bs[16][64];
    const int tid = threadIdx.x;
    const int nb = blockIdx.y * 64;
    const int ar = tid >> 2, ac = (tid & 3) * 4;
    const int t = blockIdx.x * 64 + ar;
    const float* arow = g_enc + (size_t)t * ENCW;
    const int bkr = tid >> 4, bnc = (tid & 15) * 4;
    const int ty = tid >> 4, tx = tid & 15;
    float acc[4][4] = {};
    for (int k0 = 0; k0 < NEN; k0 += 16) {
        float4 av = *(const float4*)(arow + k0 + ac);
        As[ac + 0][ar] = av.x; As[ac + 1][ar] = av.y;
        As[ac + 2][ar] = av.z; As[ac + 3][ar] = av.w;
        float4 bv = *(const float4*)(baU + (size_t)(k0 + bkr) * NEN + nb + bnc);
        *(float4*)&Bs[bkr][bnc] = bv;
        __syncthreads();
#pragma unroll
        for (int k = 0; k < 16; k++) {
            float a[4], bb[4];
#pragma unroll
            for (int i = 0; i < 4; i++) a[i]  = As[k][ty * 4 + i];
#pragma unroll
            for (int j = 0; j < 4; j++) bb[j] = Bs[k][tx * 4 + j];
#pragma unroll
            for (int i = 0; i < 4; i++)
#pragma unroll
                for (int j = 0; j < 4; j++) acc[i][j] += a[i] * bb[j];
        }
        __syncthreads();
    }
    const int trow = blockIdx.x * 64 + ty * 4;
#pragma unroll
    for (int i = 0; i < 4; i++)
        *(float4*)&g_tmp[(size_t)(trow + i) * NEN + nb + tx * 4] = *(float4*)acc[i];
}

/* ============ K2b: dh = enh . ba_Wd, em = enm . ba_We ============ */
__global__ __launch_bounds__(256) void k_dotvec(
    const float* __restrict__ Wd, const float* __restrict__ We)
{
    const int gw = (blockIdx.x * blockDim.x + threadIdx.x) >> 5;
    const int lane = threadIdx.x & 31;
    if (gw >= NT) return;
    const float* r = g_enc + (size_t)gw * ENCW;
    float s1 = 0.f, s2 = 0.f;
#pragma unroll
    for (int k = lane; k < NEN; k += 32) {
        s1 += r[k] * Wd[k];
        s2 += r[256 + k] * We[k];
    }
#pragma unroll
    for (int o = 16; o; o >>= 1) {
        s1 += __shfl_xor_sync(0xffffffffu, s1, o);
        s2 += __shfl_xor_sync(0xffffffffu, s2, o);
    }
    if (!lane) { g_dh[gw] = s1; g_em[gw] = s2; }
}

/* ========== K3: S[b,h,m] = tmp[b,h] . enm[b,m] + dh + em + b ========== */
__global__ __launch_bounds__(256) void k_nodescore(const float* __restrict__ bab)
{
    __shared__ float As[16][64];
    __shared__ float Bs[16][64];
    const int tid = threadIdx.x;
    const int b = blockIdx.z;
    const int h0 = blockIdx.x * 64, m0 = blockIdx.y * 64;
    const int ar = tid >> 2, ac = (tid & 3) * 4;
    const int hA = h0 + ar, mB = m0 + ar;
    const bool aok = hA < L1, bok = mB < L1;
    const float* arow = g_tmp + (size_t)(b * L1 + (aok ? hA : 0)) * NEN;
    const float* brow = g_enc + (size_t)(b * L1 + (bok ? mB : 0)) * ENCW + 256;
    const int ty = tid >> 4, tx = tid & 15;
    float acc[4][4] = {};
    for (int k0 = 0; k0 < NEN; k0 += 16) {
        float4 av = aok ? *(const float4*)(arow + k0 + ac) : make_float4(0, 0, 0, 0);
        float4 bv = bok ? *(const float4*)(brow + k0 + ac) : make_float4(0, 0, 0, 0);
        As[ac + 0][ar] = av.x; As[ac + 1][ar] = av.y;
        As[ac + 2][ar] = av.z; As[ac + 3][ar] = av.w;
        Bs[ac + 0][ar] = bv.x; Bs[ac + 1][ar] = bv.y;
        Bs[ac + 2][ar] = bv.z; Bs[ac + 3][ar] = bv.w;
        __syncthreads();
#pragma unroll
        for (int k = 0; k < 16; k++) {
            float a[4], bb[4];
#pragma unroll
            for (int i = 0; i < 4; i++) a[i]  = As[k][ty * 4 + i];
#pragma unroll
            for (int j = 0; j < 4; j++) bb[j] = Bs[k][tx * 4 + j];
#pragma unroll
            for (int i = 0; i < 4; i++)
#pragma unroll
                for (int j = 0; j < 4; j++) acc[i][j] += a[i] * bb[j];
        }
        __syncthreads();
    }
    const float bb0 = bab[0];
#pragma unroll
    for (int i = 0; i < 4; i++) {
        int h = h0 + ty * 4 + i;
        if (h >= L1) continue;
        float dh = g_dh[b * L1 + h];
#pragma unroll
        for (int j = 0; j < 4; j++) {
            int m = m0 + tx * 4 + j;
            if (m >= L1) continue;
            g_S[((size_t)b * L1 + h) * L1 + m] = acc[i][j] + dh + g_em[b * L1 + m] + bb0;
        }
    }
}

/* ==== K4: per-column logsumexp over heads + gold pick + decode argmax ==== */
__global__ __launch_bounds__(256) void k_node_reduce(
    const int* __restrict__ eheads, const int* __restrict__ mask,
    float* __restrict__ out)
{
    const int b = blockIdx.y;
    const int m0 = blockIdx.x * 32;
    const int tid = threadIdx.x, lane = tid & 31, w = tid >> 5;
    __shared__ int mk[L1];
    __shared__ float s_max[8][32], s_sum[8][32], s_bv[8][32];
    __shared__ int s_bi[8][32];
    for (int i = tid; i < L1; i += 256) mk[i] = (i == 0) ? 0 : mask[b * NL + i - 1];
    __syncthreads();

    const int m = m0 + lane;
    const bool mv = m < L1;
    const int msafe = mv ? m : (L1 - 1);
    const int mm_ = mk[msafe];
    const float* Sb = g_S + (size_t)b * L1 * L1;

    float rmax = -1e30f, rsum = 0.f, bv = -1e30f;
    int bi = 0x7fffffff;
    for (int h = w; h < L1; h += 8) {
        float s = Sb[(size_t)h * L1 + msafe];
        int mh = mk[h];
        float x = s + logmask(mh + mm_);
        if (x > rmax) { rsum = rsum * expf(rmax - x) + 1.f; rmax = x; }
        else            rsum += expf(x - rmax);
        float dv = s + (1.f - (float)mh) * (-1e8f);
        if (h != msafe && dv > bv) { bv = dv; bi = h; }
    }
    s_max[w][lane] = rmax; s_sum[w][lane] = rsum;
    s_bv[w][lane] = bv;    s_bi[w][lane] = bi;
    __syncthreads();

    if (w == 0) {
        float tm = -1e30f;
#pragma unroll
        for (int i = 0; i < 8; i++) tm = fmaxf(tm, s_max[i][lane]);
        float ts = 0.f;
#pragma unroll
        for (int i = 0; i < 8; i++) ts += s_sum[i][lane] * expf(s_max[i][lane] - tm);
        float lse = tm + logf(ts);
        int gh = (msafe == 0) ? 0 : eheads[b * NL + msafe - 1];
        float xg = Sb[(size_t)gh * L1 + msafe] + logmask(mk[gh] + mm_);
        float bbv = -1e30f; int bbi = 0x7fffffff;
#pragma unroll
        for (int i = 0; i < 8; i++) {
            float v = s_bv[i][lane]; int ix = s_bi[i][lane];
            if (v > bbv || (v == bbv && ix < bbi)) { bbv = v; bbi = ix; }
        }
        float contrib = 0.f;
        if (mv) {
            g_pred[b * L1 + m] = bbi;
            if (m >= 1) {
                out[OUT_PH + (size_t)b * NL + m - 1] = (float)bbi;
                contrib = -(xg - lse);
            }
        }
#pragma unroll
        for (int o = 16; o; o >>= 1) contrib += __shfl_xor_sync(0xffffffffu, contrib, o);
        if (lane == 0) g_partA[blockIdx.y * 17 + blockIdx.x] = contrib;
    }
}

/* ===== K5: label bilinear via mma.sync tf32 (HMMA).
   CTA = (token tile 128, n). D[t,d] = elm[t,:] . U[n,d,:].
   Epilogue: sg = G.(D+Wl), sp = P.(D+Wl).                       ===== */
#define BSTR 68                        /* padded smem stride (floats) */
#define SMB_A 0                        /* 128*68 u32 */
#define SMB_B (128 * BSTR)             /* 128*68 u32 */
#define SMB_WL (2 * 128 * BSTR)        /* 128 f32 */
#define SMB_TOTAL ((2 * 128 * BSTR + 128) * 4)

__global__ __launch_bounds__(256) void k_bilin_mma(
    const float* __restrict__ U, const float* __restrict__ Wl,
    const int* __restrict__ eheads)
{
    extern __shared__ unsigned sm[];
    unsigned* As = sm + SMB_A;
    unsigned* Bs = sm + SMB_B;
    float* Wls = (float*)(sm + SMB_WL);
    const int tid = threadIdx.x;
    const int lane = tid & 31, w = tid >> 5;
    const int q = lane & 3, oct = lane >> 2;
    const int n = blockIdx.y;
    const int t0 = blockIdx.x * TILE_T;

    if (tid < 128) Wls[tid] = Wl[n * NEL + tid];

    float acc[16][4] = {};
    const int lrow = (tid >> 4);          /* 0..15 */
    const int lcol = (tid & 15) * 4;      /* 0..60 */

    for (int c = 0; c < 2; c++) {
        __syncthreads();
#pragma unroll
        for (int p = 0; p < 8; p++) {
            const int row = p * 16 + lrow;
            const int t = t0 + row;
            float4 av = (t < NT)
                ? *(const float4*)(g_enc + (size_t)t * ENCW + 640 + c * 64 + lcol)
                : make_float4(0, 0, 0, 0);
            uint4 ua;
            ua.x = f2tf32(av.x); ua.y = f2tf32(av.y);
            ua.z = f2tf32(av.z); ua.w = f2tf32(av.w);
            *(uint4*)&As[row * BSTR + lcol] = ua;
            float4 bv = *(const float4*)(U + ((size_t)n * NEL + row) * NEL + c * 64 + lcol);
            uint4 ub;
            ub.x = f2tf32(bv.x); ub.y = f2tf32(bv.y);
            ub.z = f2tf32(bv.z); ub.w = f2tf32(bv.w);
            *(uint4*)&Bs[row * BSTR + lcol] = ub;
        }
        __syncthreads();
        const int r0 = w * 16 + oct;
#pragma unroll
        for (int kb = 0; kb < 64; kb += 8) {
            unsigned a0 = As[r0 * BSTR + kb + q];
            unsigned a1 = As[(r0 + 8) * BSTR + kb + q];
            unsigned a2 = As[r0 * BSTR + kb + q + 4];
            unsigned a3 = As[(r0 + 8) * BSTR + kb + q + 4];
#pragma unroll
            for (int nt = 0; nt < 16; nt++) {
                unsigned b0 = Bs[(nt * 8 + oct) * BSTR + kb + q];
                unsigned b1 = Bs[(nt * 8 + oct) * BSTR + kb + q + 4];
                mma_tf32(acc[nt], a0, a1, a2, a3, b0, b1);
            }
        }
    }

    /* epilogue: rows r0 = w*16+oct, r1 = r0+8 */
    const int r0 = w * 16 + oct, r1 = r0 + 8;
    const int ta = t0 + r0, tb = t0 + r1;
    const bool va = ta < NT, vb = tb < NT;
    const int tca = va ? ta : 0, tcb = vb ? tb : 0;
    const int ba = tca / L1, la = tca - ba * L1;
    const int bb_ = tcb / L1, lb_ = tcb - bb_ * L1;
    const int gha = (la == 0) ? 0 : eheads[ba * NL + la - 1];
    const int ghb = (lb_ == 0) ? 0 : eheads[bb_ * NL + lb_ - 1];
    const int pha = g_pred[tca], phb = g_pred[tcb];
    const float* grow0 = g_enc + (size_t)(ba * L1 + gha) * ENCW + 512;
    const float* prow0 = g_enc + (size_t)(ba * L1 + pha) * ENCW + 512;
    const float* grow1 = g_enc + (size_t)(bb_ * L1 + ghb) * ENCW + 512;
    const float* prow1 = g_enc + (size_t)(bb_ * L1 + phb) * ENCW + 512;

    float sg0 = 0.f, sp0 = 0.f, sg1 = 0.f, sp1 = 0.f;
#pragma unroll
    for (int nt = 0; nt < 16; nt++) {
        const int c0 = nt * 8 + q * 2;
        const float w0 = Wls[c0], w1 = Wls[c0 + 1];
        float2 g0 = *(const float2*)(grow0 + c0);
        float2 p0 = *(const float2*)(prow0 + c0);
        float2 g1 = *(const float2*)(grow1 + c0);
        float2 p1 = *(const float2*)(prow1 + c0);
        float d00 = acc[nt][0] + w0, d01 = acc[nt][1] + w1;
        float d10 = acc[nt][2] + w0, d11 = acc[nt][3] + w1;
        sg0 += d00 * g0.x + d01 * g0.y;  sp0 += d00 * p0.x + d01 * p0.y;
        sg1 += d10 * g1.x + d11 * g1.y;  sp1 += d10 * p1.x + d11 * p1.y;
    }
#pragma unroll
    for (int o = 1; o <= 2; o <<= 1) {
        sg0 += __shfl_xor_sync(0xffffffffu, sg0, o);
        sp0 += __shfl_xor_sync(0xffffffffu, sp0, o);
        sg1 += __shfl_xor_sync(0xffffffffu, sg1, o);
        sp1 += __shfl_xor_sync(0xffffffffu, sp1, o);
    }
    if (q == 0) {
        if (va) { g_sg[(size_t)n * NT + ta] = sg0; g_sp[(size_t)n * NT + ta] = sp0; }
        if (vb) { g_sg[(size_t)n * NT + tb] = sg1; g_sp[(size_t)n * NT + tb] = sp1; }
    }
}

/* ===== K5b: lin[n,t] = elm[t] . Wr[n] + lbl_b[n] ===== */
__global__ __launch_bounds__(256) void k_lin(
    const float* __restrict__ Wr, const float* __restrict__ lb)
{
    __shared__ float As[16][64];
    __shared__ float Bs[16][64];
    const int tid = threadIdx.x;
    const int t0 = blockIdx.x * 64, n0 = blockIdx.y * 64;
    const int ar = tid >> 2, ac = (tid & 3) * 4;
    const float* arow = g_enc + (size_t)(t0 + ar) * ENCW + 640;
    const float* brow = Wr + (size_t)(n0 + ar) * NEL;
    const int ty = tid >> 4, tx = tid & 15;
    float acc[4][4] = {};
    for (int k0 = 0; k0 < NEL; k0 += 16) {
        float4 av = *(const float4*)(arow + k0 + ac);
        float4 bv = *(const float4*)(brow + k0 + ac);
        As[ac + 0][ar] = av.x; As[ac + 1][ar] = av.y;
        As[ac + 2][ar] = av.z; As[ac + 3][ar] = av.w;
        Bs[ac + 0][ar] = bv.x; Bs[ac + 1][ar] = bv.y;
        Bs[ac + 2][ar] = bv.z; Bs[ac + 3][ar] = bv.w;
        __syncthreads();
#pragma unroll
        for (int k = 0; k < 16; k++) {
            float a[4], bb[4];
#pragma unroll
            for (int i = 0; i < 4; i++) a[i]  = As[k][ty * 4 + i];
#pragma unroll
            for (int j = 0; j < 4; j++) bb[j] = Bs[k][tx * 4 + j];
#pragma unroll
            for (int i = 0; i < 4; i++)
#pragma unroll
                for (int j = 0; j < 4; j++) acc[i][j] += a[i] * bb[j];
        }
        __syncthreads();
    }
#pragma unroll
    for (int i = 0; i < 4; i++) {
        int t = t0 + ty * 4 + i;
#pragma unroll
        for (int j = 0; j < 4; j++) {
            int nn = n0 + tx * 4 + j;
            g_lin[(size_t)nn * NT + t] = acc[i][j] + lb[nn];
        }
    }
}

/* ===== K6: label log-softmax over n (gold pick) + max over n (pred) ===== */
__global__ __launch_bounds__(256) void k_lbl_reduce(
    const int* __restrict__ elabels, float* __restrict__ out)
{
    __shared__ float red[256];
    const int t = blockIdx.x * 256 + threadIdx.x;
    float contrib = 0.f;
    if (t < NT) {
        int b = t / L1, l = t % L1;
        int lab = (l == 0) ? 0 : elabels[b * NL + l - 1];
        float mg = -1e30f, sg = 0.f, mp = -1e30f, xlab = 0.f;
        for (int n = 0; n < NLB; n++) {
            float lin = g_lin[(size_t)n * NT + t];
            float xg = g_sg[(size_t)n * NT + t] + lin;
            float xp = g_sp[(size_t)n * NT + t] + lin;
            if (n == lab) xlab = xg;
            if (xg > mg) { sg = sg * expf(mg - xg) + 1.f; mg = xg; }
            else           sg += expf(xg - mg);
            mp = fmaxf(mp, xp);
        }
        float ll = xlab - (mg + logf(sg));
        if (l >= 1) {
            contrib = -ll;
            out[OUT_PL + (size_t)b * NL + l - 1] = mp;
        }
    }
    red[threadIdx.x] = contrib;
    __syncthreads();
    for (int s = 128; s; s >>= 1) {
        if (threadIdx.x < s) red[threadIdx.x] += red[threadIdx.x + s];
        __syncthreads();
    }
    if (!threadIdx.x) g_partB[blockIdx.x] = red[0];
}

/* ===== K7: labels1 output + deterministic NLL finalize ===== */
__global__ __launch_bounds__(256) void k_final(
    const int* __restrict__ elabels, float* __restrict__ out)
{
    const int i = blockIdx.x * 256 + threadIdx.x;
    if (i < NT) {
        int b = i / L1, l = i % L1;
        out[OUT_LB + i] = (l == 0) ? 0.f : (float)elabels[b * NL + l - 1];
    }
    if (i == 0) {
        float s = 0.f;
        for (int k = 0; k < 17 * 64; k++) s += g_partA[k];
        out[OUT_NN] = s;
        float s2 = 0.f;
        for (int k = 0; k < 129; k++) s2 += g_partB[k];
        out[OUT_LN] = s2;
    }
}

extern "C" void kernel_launch(void* const* d_in, const int* in_sizes, int n_in,
                              void* d_out, int out_size)
{
    const float* mem    = (const float*)d_in[0];
    const int*   eheads = (const int*)d_in[1];
    const int*   elabs  = (const int*)d_in[2];
    const int*   mask   = (const int*)d_in[4];
    const float* sent   = (const float*)d_in[5];
    const float* Wenh = (const float*)d_in[6];  const float* benh = (const float*)d_in[7];
    const float* Wenm = (const float*)d_in[8];  const float* benm = (const float*)d_in[9];
    const float* Welh = (const float*)d_in[10]; const float* belh = (const float*)d_in[11];
    const float* Welm = (const float*)d_in[12]; const float* belm = (const float*)d_in[13];
    const float* baU  = (const float*)d_in[14];
    const float* baWd = (const float*)d_in[15];
    const float* baWe = (const float*)d_in[16];
    const float* bab  = (const float*)d_in[17];
    const float* lU   = (const float*)d_in[18];
    const float* lWl  = (const float*)d_in[19];
    const float* lWr  = (const float*)d_in[20];
    const float* lb   = (const float*)d_in[21];
    float* out = (float*)d_out;

    cudaFuncSetAttribute(k_bilin_mma, cudaFuncAttributeMaxDynamicSharedMemorySize,
                         SMB_TOTAL);

    k_enc<<<dim3(513, 12), 256>>>(mem, sent, Wenh, benh, Wenm, benm,
                                  Welh, belh, Welm, belm);
    k_tmp<<<dim3(513, 4), 256>>>(baU);
    k_dotvec<<<4104, 256>>>(baWd, baWe);
    k_nodescore<<<dim3(9, 9, 64), 256>>>(bab);
    k_node_reduce<<<dim3(17, 64), 256>>>(eheads, mask, out);
    k_lin<<<dim3(513, 2), 256>>>(lWr, lb);
    k_bilin_mma<<<dim3(NTILES, NLB), 256, SMB_TOTAL>>>(lU, lWl, eheads);
    k_lbl_reduce<<<129, 256>>>(elabs, out);
    k_final<<<129, 256>>>(elabs, out);
}

// round 4
// speedup vs baseline: 2.6875x; 1.0894x over previous
#include <cuda_runtime.h>

#define NB   64
#define NL   512
#define NH   400
#define NEN  256
#define NEL  128
#define NLB  128
#define L1   513
#define NT   (NB * L1)     /* 32832 */
#define ENCW 768
#define TILE_T 128
#define NTILES 257         /* ceil(32832/128) */

/* output layout (flattened tuple, float32) */
#define OUT_PH 0
#define OUT_PL 32768
#define OUT_LB 65536
#define OUT_NN 98368
#define OUT_LN 98369

/* -------- scratch (device globals; no allocation allowed) -------- */
__device__ float g_enc[(size_t)NT * ENCW];      /* enh|enm|elh|elm  */
__device__ float g_tmp[(size_t)NT * NEN];       /* enh @ ba_U       */
__device__ float g_dh[NT];
__device__ float g_em[NT];
__device__ float g_S[(size_t)NB * L1 * L1];     /* node scores      */
__device__ int   g_pred[NT];
__device__ float g_sg[(size_t)NLB * NT];
__device__ float g_sp[(size_t)NLB * NT];
__device__ float g_lin[(size_t)NLB * NT];
__device__ float g_partA[17 * 64];
__device__ float g_partB[129];
__device__ float g_WT[768 * NH];                /* W concat, transposed [col][k] */
__device__ float g_biasC[768];
__device__ float g_baUT[NEN * NEN];             /* ba_U^T [n][k] */

__device__ __forceinline__ float elu1(float x) { return x > 0.f ? x : expm1f(x); }
__device__ __forceinline__ float logmask(int s) {
    return s == 0 ? -103.27893f : (s == 1 ? 0.f : 0.69314718f);
}
__device__ __forceinline__ unsigned f2tf32(float v) {
    unsigned t;
    asm("cvt.rna.tf32.f32 %0, %1;" : "=r"(t) : "f"(v));
    return t;
}
__device__ __forceinline__ void mma_tf32(float* c, unsigned a0, unsigned a1,
                                         unsigned a2, unsigned a3,
                                         unsigned b0, unsigned b1) {
    asm volatile(
        "mma.sync.aligned.m16n8k8.row.col.f32.tf32.tf32.f32 "
        "{%0,%1,%2,%3}, {%4,%5,%6,%7}, {%8,%9}, {%0,%1,%2,%3};\n"
        : "+f"(c[0]), "+f"(c[1]), "+f"(c[2]), "+f"(c[3])
        : "r"(a0), "r"(a1), "r"(a2), "r"(a3), "r"(b0), "r"(b1));
}
__device__ __forceinline__ void split2(float4 v, uint4& h, uint4& l) {
    h.x = f2tf32(v.x); l.x = f2tf32(v.x - __uint_as_float(h.x));
    h.y = f2tf32(v.y); l.y = f2tf32(v.y - __uint_as_float(h.y));
    h.z = f2tf32(v.z); l.z = f2tf32(v.z - __uint_as_float(h.z));
    h.w = f2tf32(v.w); l.w = f2tf32(v.w - __uint_as_float(h.w));
}

/* ===== K0: weight transposes (one-shot per launch, ~3MB traffic) ===== */
__global__ __launch_bounds__(256) void k_trans(
    const float* __restrict__ Wenh, const float* __restrict__ Wenm,
    const float* __restrict__ Welh, const float* __restrict__ Welm,
    const float* __restrict__ benh, const float* __restrict__ benm,
    const float* __restrict__ belh, const float* __restrict__ belm,
    const float* __restrict__ baU)
{
    const int i = blockIdx.x * 256 + threadIdx.x;
    if (i < 768 * NH) {
        const int k = i / 768, j = i % 768;      /* read coalesced over j */
        float v;
        if (j < 256)      v = Wenh[k * NEN + j];
        else if (j < 512) v = Wenm[k * NEN + j - 256];
        else if (j < 640) v = Welh[k * NEL + j - 512];
        else              v = Welm[k * NEL + j - 640];
        g_WT[(size_t)j * NH + k] = v;
        if (k == 0)
            g_biasC[j] = (j < 256) ? benh[j] : (j < 512) ? benm[j - 256]
                       : (j < 640) ? belh[j - 512] : belm[j - 640];
    } else {
        const int i2 = i - 768 * NH;
        if (i2 < NEN * NEN) {
            const int k = i2 / NEN, n = i2 % NEN;
            g_baUT[(size_t)n * NEN + k] = baU[k * NEN + n];
        }
    }
}

/* ===== 3xTF32 GEMM skeleton constants ===== */
#define ESTR 36                               /* pad: 36 mod 32 = 4 -> conflict-free */
#define SME_BYTES (4 * 128 * ESTR * 4)        /* Ah|Al|Bh|Bl = 73728 B */

/* ===== K1: encoder GEMM + ELU, 3xtf32. grid (257, 6) ===== */
__global__ __launch_bounds__(256) void k_enc_mma(
    const float* __restrict__ mem, const float* __restrict__ sent)
{
    extern __shared__ unsigned smu[];
    unsigned* Ah = smu;
    unsigned* Al = smu + 128 * ESTR;
    unsigned* Bh = smu + 2 * 128 * ESTR;
    unsigned* Bl = smu + 3 * 128 * ESTR;
    const int tid = threadIdx.x, lane = tid & 31, w = tid >> 5;
    const int q = lane & 3, oct = lane >> 2;
    const int t0 = blockIdx.x * 128;
    const int nb = blockIdx.y * 128;

    const int srow = tid >> 1, skg = (tid & 1) * 16;
    const int ta = t0 + srow;
    const bool aval = ta < NT;
    const int bA = aval ? ta / L1 : 0, lA = aval ? ta % L1 : 0;
    const float* aptr = (lA == 0) ? sent : (mem + ((size_t)bA * NL + (lA - 1)) * NH);
    const float* bptr = g_WT + (size_t)(nb + srow) * NH;

    float acc[16][4] = {};
    for (int k0 = 0; k0 < NH; k0 += 32) {
#pragma unroll
        for (int g = 0; g < 4; g++) {
            const int k = skg + g * 4, gk = k0 + k;
            const bool kok = gk < NH;
            float4 va = (aval && kok) ? *(const float4*)(aptr + gk) : make_float4(0, 0, 0, 0);
            float4 vb = kok ? *(const float4*)(bptr + gk) : make_float4(0, 0, 0, 0);
            uint4 ha, la, hb, lb;
            split2(va, ha, la); split2(vb, hb, lb);
            *(uint4*)&Ah[srow * ESTR + k] = ha;
            *(uint4*)&Al[srow * ESTR + k] = la;
            *(uint4*)&Bh[srow * ESTR + k] = hb;
            *(uint4*)&Bl[srow * ESTR + k] = lb;
        }
        __syncthreads();
        const int r0 = w * 16 + oct;
#pragma unroll
        for (int kb = 0; kb < 32; kb += 8) {
            const unsigned ah0 = Ah[r0 * ESTR + kb + q],     ah1 = Ah[(r0 + 8) * ESTR + kb + q];
            const unsigned ah2 = Ah[r0 * ESTR + kb + q + 4], ah3 = Ah[(r0 + 8) * ESTR + kb + q + 4];
            const unsigned al0 = Al[r0 * ESTR + kb + q],     al1 = Al[(r0 + 8) * ESTR + kb + q];
            const unsigned al2 = Al[r0 * ESTR + kb + q + 4], al3 = Al[(r0 + 8) * ESTR + kb + q + 4];
#pragma unroll
            for (int nt = 0; nt < 16; nt++) {
                const int cb = (nt * 8 + oct) * ESTR + kb;
                const unsigned bh0 = Bh[cb + q], bh1 = Bh[cb + q + 4];
                const unsigned bl0 = Bl[cb + q], bl1 = Bl[cb + q + 4];
                mma_tf32(acc[nt], ah0, ah1, ah2, ah3, bh0, bh1);
                mma_tf32(acc[nt], ah0, ah1, ah2, ah3, bl0, bl1);
                mma_tf32(acc[nt], al0, al1, al2, al3, bh0, bh1);
            }
        }
        __syncthreads();
    }
    const int r0 = w * 16 + oct;
    const int tA = t0 + r0, tB = tA + 8;
#pragma unroll
    for (int nt = 0; nt < 16; nt++) {
        const int c = nt * 8 + q * 2;
        const float b0 = g_biasC[nb + c], b1 = g_biasC[nb + c + 1];
        if (tA < NT) {
            float2 v; v.x = elu1(acc[nt][0] + b0); v.y = elu1(acc[nt][1] + b1);
            *(float2*)&g_enc[(size_t)tA * ENCW + nb + c] = v;
        }
        if (tB < NT) {
            float2 v; v.x = elu1(acc[nt][2] + b0); v.y = elu1(acc[nt][3] + b1);
            *(float2*)&g_enc[(size_t)tB * ENCW + nb + c] = v;
        }
    }
}

/* ===== K2: tmp = enh @ ba_U, 3xtf32. grid (257, 2) ===== */
__global__ __launch_bounds__(256) void k_tmp_mma()
{
    extern __shared__ unsigned smu[];
    unsigned* Ah = smu;
    unsigned* Al = smu + 128 * ESTR;
    unsigned* Bh = smu + 2 * 128 * ESTR;
    unsigned* Bl = smu + 3 * 128 * ESTR;
    const int tid = threadIdx.x, lane = tid & 31, w = tid >> 5;
    const int q = lane & 3, oct = lane >> 2;
    const int t0 = blockIdx.x * 128;
    const int nb = blockIdx.y * 128;

    const int srow = tid >> 1, skg = (tid & 1) * 16;
    const int ta = t0 + srow;
    const float* aptr = g_enc + (size_t)(ta < NT ? ta : 0) * ENCW;   /* enh */
    const float* bptr = g_baUT + (size_t)(nb + srow) * NEN;

    float acc[16][4] = {};
    for (int k0 = 0; k0 < NEN; k0 += 32) {
#pragma unroll
        for (int g = 0; g < 4; g++) {
            const int k = skg + g * 4;
            float4 va = *(const float4*)(aptr + k0 + k);
            float4 vb = *(const float4*)(bptr + k0 + k);
            uint4 ha, la, hb, lb;
            split2(va, ha, la); split2(vb, hb, lb);
            *(uint4*)&Ah[srow * ESTR + k] = ha;
            *(uint4*)&Al[srow * ESTR + k] = la;
            *(uint4*)&Bh[srow * ESTR + k] = hb;
            *(uint4*)&Bl[srow * ESTR + k] = lb;
        }
        __syncthreads();
        const int r0 = w * 16 + oct;
#pragma unroll
        for (int kb = 0; kb < 32; kb += 8) {
            const unsigned ah0 = Ah[r0 * ESTR + kb + q],     ah1 = Ah[(r0 + 8) * ESTR + kb + q];
            const unsigned ah2 = Ah[r0 * ESTR + kb + q + 4], ah3 = Ah[(r0 + 8) * ESTR + kb + q + 4];
            const unsigned al0 = Al[r0 * ESTR + kb + q],     al1 = Al[(r0 + 8) * ESTR + kb + q];
            const unsigned al2 = Al[r0 * ESTR + kb + q + 4], al3 = Al[(r0 + 8) * ESTR + kb + q + 4];
#pragma unroll
            for (int nt = 0; nt < 16; nt++) {
                const int cb = (nt * 8 + oct) * ESTR + kb;
                const unsigned bh0 = Bh[cb + q], bh1 = Bh[cb + q + 4];
                const unsigned bl0 = Bl[cb + q], bl1 = Bl[cb + q + 4];
                mma_tf32(acc[nt], ah0, ah1, ah2, ah3, bh0, bh1);
                mma_tf32(acc[nt], ah0, ah1, ah2, ah3, bl0, bl1);
                mma_tf32(acc[nt], al0, al1, al2, al3, bh0, bh1);
            }
        }
        __syncthreads();
    }
    const int r0 = w * 16 + oct;
    const int tA = t0 + r0, tB = tA + 8;
#pragma unroll
    for (int nt = 0; nt < 16; nt++) {
        const int c = nt * 8 + q * 2;
        if (tA < NT)
            *(float2*)&g_tmp[(size_t)tA * NEN + nb + c] = make_float2(acc[nt][0], acc[nt][1]);
        if (tB < NT)
            *(float2*)&g_tmp[(size_t)tB * NEN + nb + c] = make_float2(acc[nt][2], acc[nt][3]);
    }
}

/* ===== K3: node scores, 3xtf32. grid (5, 5, 64) ===== */
__global__ __launch_bounds__(256) void k_ns_mma(const float* __restrict__ bab)
{
    extern __shared__ unsigned smu[];
    unsigned* Ah = smu;
    unsigned* Al = smu + 128 * ESTR;
    unsigned* Bh = smu + 2 * 128 * ESTR;
    unsigned* Bl = smu + 3 * 128 * ESTR;
    const int tid = threadIdx.x, lane = tid & 31, w = tid >> 5;
    const int q = lane & 3, oct = lane >> 2;
    const int b = blockIdx.z;
    const int h0 = blockIdx.x * 128, m0 = blockIdx.y * 128;

    const int srow = tid >> 1, skg = (tid & 1) * 16;
    int hr = h0 + srow; if (hr > 512) hr = 512;
    int mr = m0 + srow; if (mr > 512) mr = 512;
    const float* aptr = g_tmp + (size_t)(b * L1 + hr) * NEN;
    const float* bptr = g_enc + (size_t)(b * L1 + mr) * ENCW + 256;  /* enm */

    float acc[16][4] = {};
    for (int k0 = 0; k0 < NEN; k0 += 32) {
#pragma unroll
        for (int g = 0; g < 4; g++) {
            const int k = skg + g * 4;
            float4 va = *(const float4*)(aptr + k0 + k);
            float4 vb = *(const float4*)(bptr + k0 + k);
            uint4 ha, la, hb, lb;
            split2(va, ha, la); split2(vb, hb, lb);
            *(uint4*)&Ah[srow * ESTR + k] = ha;
            *(uint4*)&Al[srow * ESTR + k] = la;
            *(uint4*)&Bh[srow * ESTR + k] = hb;
            *(uint4*)&Bl[srow * ESTR + k] = lb;
        }
        __syncthreads();
        const int r0 = w * 16 + oct;
#pragma unroll
        for (int kb = 0; kb < 32; kb += 8) {
            const unsigned ah0 = Ah[r0 * ESTR + kb + q],     ah1 = Ah[(r0 + 8) * ESTR + kb + q];
            const unsigned ah2 = Ah[r0 * ESTR + kb + q + 4], ah3 = Ah[(r0 + 8) * ESTR + kb + q + 4];
            const unsigned al0 = Al[r0 * ESTR + kb + q],     al1 = Al[(r0 + 8) * ESTR + kb + q];
            const unsigned al2 = Al[r0 * ESTR + kb + q + 4], al3 = Al[(r0 + 8) * ESTR + kb + q + 4];
#pragma unroll
            for (int nt = 0; nt < 16; nt++) {
                const int cb = (nt * 8 + oct) * ESTR + kb;
                const unsigned bh0 = Bh[cb + q], bh1 = Bh[cb + q + 4];
                const unsigned bl0 = Bl[cb + q], bl1 = Bl[cb + q + 4];
                mma_tf32(acc[nt], ah0, ah1, ah2, ah3, bh0, bh1);
                mma_tf32(acc[nt], ah0, ah1, ah2, ah3, bl0, bl1);
                mma_tf32(acc[nt], al0, al1, al2, al3, bh0, bh1);
            }
        }
        __syncthreads();
    }
    const int r0 = w * 16 + oct;
    const int hA = h0 + r0, hB = hA + 8;
    const float bb0 = __ldg(bab);
    const float dhA = (hA <= 512) ? g_dh[b * L1 + hA] : 0.f;
    const float dhB = (hB <= 512) ? g_dh[b * L1 + hB] : 0.f;
    float* Sb = g_S + (size_t)b * L1 * L1;
#pragma unroll
    for (int nt = 0; nt < 16; nt++) {
        const int m = m0 + nt * 8 + q * 2;
        if (m <= 512) {
            const float em0 = g_em[b * L1 + m];
            if (hA <= 512) Sb[(size_t)hA * L1 + m] = acc[nt][0] + dhA + em0 + bb0;
            if (hB <= 512) Sb[(size_t)hB * L1 + m] = acc[nt][2] + dhB + em0 + bb0;
        }
        if (m + 1 <= 512) {
            const float em1 = g_em[b * L1 + m + 1];
            if (hA <= 512) Sb[(size_t)hA * L1 + m + 1] = acc[nt][1] + dhA + em1 + bb0;
            if (hB <= 512) Sb[(size_t)hB * L1 + m + 1] = acc[nt][3] + dhB + em1 + bb0;
        }
    }
}

/* ============ K2b: dh = enh . ba_Wd, em = enm . ba_We ============ */
__global__ __launch_bounds__(256) void k_dotvec(
    const float* __restrict__ Wd, const float* __restrict__ We)
{
    const int gw = (blockIdx.x * blockDim.x + threadIdx.x) >> 5;
    const int lane = threadIdx.x & 31;
    if (gw >= NT) return;
    const float* r = g_enc + (size_t)gw * ENCW;
    float s1 = 0.f, s2 = 0.f;
#pragma unroll
    for (int k = lane; k < NEN; k += 32) {
        s1 += r[k] * Wd[k];
        s2 += r[256 + k] * We[k];
    }
#pragma unroll
    for (int o = 16; o; o >>= 1) {
        s1 += __shfl_xor_sync(0xffffffffu, s1, o);
        s2 += __shfl_xor_sync(0xffffffffu, s2, o);
    }
    if (!lane) { g_dh[gw] = s1; g_em[gw] = s2; }
}

/* ==== K4: per-column logsumexp over heads + gold pick + decode argmax ==== */
__global__ __launch_bounds__(256) void k_node_reduce(
    const int* __restrict__ eheads, const int* __restrict__ mask,
    float* __restrict__ out)
{
    const int b = blockIdx.y;
    const int m0 = blockIdx.x * 32;
    const int tid = threadIdx.x, lane = tid & 31, w = tid >> 5;
    __shared__ int mk[L1];
    __shared__ float s_max[8][32], s_sum[8][32], s_bv[8][32];
    __shared__ int s_bi[8][32];
    for (int i = tid; i < L1; i += 256) mk[i] = (i == 0) ? 0 : mask[b * NL + i - 1];
    __syncthreads();

    const int m = m0 + lane;
    const bool mv = m < L1;
    const int msafe = mv ? m : (L1 - 1);
    const int mm_ = mk[msafe];
    const float* Sb = g_S + (size_t)b * L1 * L1;

    float rmax = -1e30f, rsum = 0.f, bv = -1e30f;
    int bi = 0x7fffffff;
    for (int h = w; h < L1; h += 8) {
        float s = Sb[(size_t)h * L1 + msafe];
        int mh = mk[h];
        float x = s + logmask(mh + mm_);
        if (x > rmax) { rsum = rsum * expf(rmax - x) + 1.f; rmax = x; }
        else            rsum += expf(x - rmax);
        float dv = s + (1.f - (float)mh) * (-1e8f);
        if (h != msafe && dv > bv) { bv = dv; bi = h; }
    }
    s_max[w][lane] = rmax; s_sum[w][lane] = rsum;
    s_bv[w][lane] = bv;    s_bi[w][lane] = bi;
    __syncthreads();

    if (w == 0) {
        float tm = -1e30f;
#pragma unroll
        for (int i = 0; i < 8; i++) tm = fmaxf(tm, s_max[i][lane]);
        float ts = 0.f;
#pragma unroll
        for (int i = 0; i < 8; i++) ts += s_sum[i][lane] * expf(s_max[i][lane] - tm);
        float lse = tm + logf(ts);
        int gh = (msafe == 0) ? 0 : eheads[b * NL + msafe - 1];
        float xg = Sb[(size_t)gh * L1 + msafe] + logmask(mk[gh] + mm_);
        float bbv = -1e30f; int bbi = 0x7fffffff;
#pragma unroll
        for (int i = 0; i < 8; i++) {
            float v = s_bv[i][lane]; int ix = s_bi[i][lane];
            if (v > bbv || (v == bbv && ix < bbi)) { bbv = v; bbi = ix; }
        }
        float contrib = 0.f;
        if (mv) {
            g_pred[b * L1 + m] = bbi;
            if (m >= 1) {
                out[OUT_PH + (size_t)b * NL + m - 1] = (float)bbi;
                contrib = -(xg - lse);
            }
        }
#pragma unroll
        for (int o = 16; o; o >>= 1) contrib += __shfl_xor_sync(0xffffffffu, contrib, o);
        if (lane == 0) g_partA[blockIdx.y * 17 + blockIdx.x] = contrib;
    }
}

/* ===== K5: label bilinear via mma.sync tf32 (single precision) ===== */
#define BSTR 68
#define SMB_A 0
#define SMB_B (128 * BSTR)
#define SMB_WL (2 * 128 * BSTR)
#define SMB_TOTAL ((2 * 128 * BSTR + 128) * 4)

__global__ __launch_bounds__(256) void k_bilin_mma(
    const float* __restrict__ U, const float* __restrict__ Wl,
    const int* __restrict__ eheads)
{
    extern __shared__ unsigned sm[];
    unsigned* As = sm + SMB_A;
    unsigned* Bs = sm + SMB_B;
    float* Wls = (float*)(sm + SMB_WL);
    const int tid = threadIdx.x;
    const int lane = tid & 31, w = tid >> 5;
    const int q = lane & 3, oct = lane >> 2;
    const int n = blockIdx.y;
    const int t0 = blockIdx.x * TILE_T;

    if (tid < 128) Wls[tid] = Wl[n * NEL + tid];

    float acc[16][4] = {};
    const int lrow = (tid >> 4);
    const int lcol = (tid & 15) * 4;

    for (int c = 0; c < 2; c++) {
        __syncthreads();
#pragma unroll
        for (int p = 0; p < 8; p++) {
            const int row = p * 16 + lrow;
            const int t = t0 + row;
            float4 av = (t < NT)
                ? *(const float4*)(g_enc + (size_t)t * ENCW + 640 + c * 64 + lcol)
                : make_float4(0, 0, 0, 0);
            uint4 ua;
            ua.x = f2tf32(av.x); ua.y = f2tf32(av.y);
            ua.z = f2tf32(av.z); ua.w = f2tf32(av.w);
            *(uint4*)&As[row * BSTR + lcol] = ua;
            float4 bv = *(const float4*)(U + ((size_t)n * NEL + row) * NEL + c * 64 + lcol);
            uint4 ub;
            ub.x = f2tf32(bv.x); ub.y = f2tf32(bv.y);
            ub.z = f2tf32(bv.z); ub.w = f2tf32(bv.w);
            *(uint4*)&Bs[row * BSTR + lcol] = ub;
        }
        __syncthreads();
        const int r0 = w * 16 + oct;
#pragma unroll
        for (int kb = 0; kb < 64; kb += 8) {
            unsigned a0 = As[r0 * BSTR + kb + q];
            unsigned a1 = As[(r0 + 8) * BSTR + kb + q];
            unsigned a2 = As[r0 * BSTR + kb + q + 4];
            unsigned a3 = As[(r0 + 8) * BSTR + kb + q + 4];
#pragma unroll
            for (int nt = 0; nt < 16; nt++) {
                unsigned b0 = Bs[(nt * 8 + oct) * BSTR + kb + q];
                unsigned b1 = Bs[(nt * 8 + oct) * BSTR + kb + q + 4];
                mma_tf32(acc[nt], a0, a1, a2, a3, b0, b1);
            }
        }
    }

    const int r0 = w * 16 + oct, r1 = r0 + 8;
    const int ta = t0 + r0, tb = t0 + r1;
    const bool va = ta < NT, vb = tb < NT;
    const int tca = va ? ta : 0, tcb = vb ? tb : 0;
    const int ba = tca / L1, la = tca - ba * L1;
    const int bb_ = tcb / L1, lb_ = tcb - bb_ * L1;
    const int gha = (la == 0) ? 0 : eheads[ba * NL + la - 1];
    const int ghb = (lb_ == 0) ? 0 : eheads[bb_ * NL + lb_ - 1];
    const int pha = g_pred[tca], phb = g_pred[tcb];
    const float* grow0 = g_enc + (size_t)(ba * L1 + gha) * ENCW + 512;
    const float* prow0 = g_enc + (size_t)(ba * L1 + pha) * ENCW + 512;
    const float* grow1 = g_enc + (size_t)(bb_ * L1 + ghb) * ENCW + 512;
    const float* prow1 = g_enc + (size_t)(bb_ * L1 + phb) * ENCW + 512;

    float sg0 = 0.f, sp0 = 0.f, sg1 = 0.f, sp1 = 0.f;
#pragma unroll
    for (int nt = 0; nt < 16; nt++) {
        const int c0 = nt * 8 + q * 2;
        const float w0 = Wls[c0], w1 = Wls[c0 + 1];
        float2 g0 = *(const float2*)(grow0 + c0);
        float2 p0 = *(const float2*)(prow0 + c0);
        float2 g1 = *(const float2*)(grow1 + c0);
        float2 p1 = *(const float2*)(prow1 + c0);
        float d00 = acc[nt][0] + w0, d01 = acc[nt][1] + w1;
        float d10 = acc[nt][2] + w0, d11 = acc[nt][3] + w1;
        sg0 += d00 * g0.x + d01 * g0.y;  sp0 += d00 * p0.x + d01 * p0.y;
        sg1 += d10 * g1.x + d11 * g1.y;  sp1 += d10 * p1.x + d11 * p1.y;
    }
#pragma unroll
    for (int o = 1; o <= 2; o <<= 1) {
        sg0 += __shfl_xor_sync(0xffffffffu, sg0, o);
        sp0 += __shfl_xor_sync(0xffffffffu, sp0, o);
        sg1 += __shfl_xor_sync(0xffffffffu, sg1, o);
        sp1 += __shfl_xor_sync(0xffffffffu, sp1, o);
    }
    if (q == 0) {
        if (va) { g_sg[(size_t)n * NT + ta] = sg0; g_sp[(size_t)n * NT + ta] = sp0; }
        if (vb) { g_sg[(size_t)n * NT + tb] = sg1; g_sp[(size_t)n * NT + tb] = sp1; }
    }
}

/* ===== K5b: lin[n,t] = elm[t] . Wr[n] + lbl_b[n] ===== */
__global__ __launch_bounds__(256) void k_lin(
    const float* __restrict__ Wr, const float* __restrict__ lb)
{
    __shared__ float As[16][64];
    __shared__ float Bs[16][64];
    const int tid = threadIdx.x;
    const int t0 = blockIdx.x * 64, n0 = blockIdx.y * 64;
    const int ar = tid >> 2, ac = (tid & 3) * 4;
    const float* arow = g_enc + (size_t)(t0 + ar) * ENCW + 640;
    const float* brow = Wr + (size_t)(n0 + ar) * NEL;
    const int ty = tid >> 4, tx = tid & 15;
    float acc[4][4] = {};
    for (int k0 = 0; k0 < NEL; k0 += 16) {
        float4 av = *(const float4*)(arow + k0 + ac);
        float4 bv = *(const float4*)(brow + k0 + ac);
        As[ac + 0][ar] = av.x; As[ac + 1][ar] = av.y;
        As[ac + 2][ar] = av.z; As[ac + 3][ar] = av.w;
        Bs[ac + 0][ar] = bv.x; Bs[ac + 1][ar] = bv.y;
        Bs[ac + 2][ar] = bv.z; Bs[ac + 3][ar] = bv.w;
        __syncthreads();
#pragma unroll
        for (int k = 0; k < 16; k++) {
            float a[4], bb[4];
#pragma unroll
            for (int i = 0; i < 4; i++) a[i]  = As[k][ty * 4 + i];
#pragma unroll
            for (int j = 0; j < 4; j++) bb[j] = Bs[k][tx * 4 + j];
#pragma unroll
            for (int i = 0; i < 4; i++)
#pragma unroll
                for (int j = 0; j < 4; j++) acc[i][j] += a[i] * bb[j];
        }
        __syncthreads();
    }
#pragma unroll
    for (int i = 0; i < 4; i++) {
        int t = t0 + ty * 4 + i;
#pragma unroll
        for (int j = 0; j < 4; j++) {
            int nn = n0 + tx * 4 + j;
            g_lin[(size_t)nn * NT + t] = acc[i][j] + lb[nn];
        }
    }
}

/* ===== K6: label log-softmax over n (gold pick) + max over n (pred) ===== */
__global__ __launch_bounds__(256) void k_lbl_reduce(
    const int* __restrict__ elabels, float* __restrict__ out)
{
    __shared__ float red[256];
    const int t = blockIdx.x * 256 + threadIdx.x;
    float contrib = 0.f;
    if (t < NT) {
        int b = t / L1, l = t % L1;
        int lab = (l == 0) ? 0 : elabels[b * NL + l - 1];
        float mg = -1e30f, sg = 0.f, mp = -1e30f, xlab = 0.f;
        for (int n = 0; n < NLB; n++) {
            float lin = g_lin[(size_t)n * NT + t];
            float xg = g_sg[(size_t)n * NT + t] + lin;
            float xp = g_sp[(size_t)n * NT + t] + lin;
            if (n == lab) xlab = xg;
            if (xg > mg) { sg = sg * expf(mg - xg) + 1.f; mg = xg; }
            else           sg += expf(xg - mg);
            mp = fmaxf(mp, xp);
        }
        float ll = xlab - (mg + logf(sg));
        if (l >= 1) {
            contrib = -ll;
            out[OUT_PL + (size_t)b * NL + l - 1] = mp;
        }
    }
    red[threadIdx.x] = contrib;
    __syncthreads();
    for (int s = 128; s; s >>= 1) {
        if (threadIdx.x < s) red[threadIdx.x] += red[threadIdx.x + s];
        __syncthreads();
    }
    if (!threadIdx.x) g_partB[blockIdx.x] = red[0];
}

/* ===== K7: labels1 output + deterministic NLL finalize ===== */
__global__ __launch_bounds__(256) void k_final(
    const int* __restrict__ elabels, float* __restrict__ out)
{
    const int i = blockIdx.x * 256 + threadIdx.x;
    if (i < NT) {
        int b = i / L1, l = i % L1;
        out[OUT_LB + i] = (l == 0) ? 0.f : (float)elabels[b * NL + l - 1];
    }
    if (i == 0) {
        float s = 0.f;
        for (int k = 0; k < 17 * 64; k++) s += g_partA[k];
        out[OUT_NN] = s;
        float s2 = 0.f;
        for (int k = 0; k < 129; k++) s2 += g_partB[k];
        out[OUT_LN] = s2;
    }
}

extern "C" void kernel_launch(void* const* d_in, const int* in_sizes, int n_in,
                              void* d_out, int out_size)
{
    const float* mem    = (const float*)d_in[0];
    const int*   eheads = (const int*)d_in[1];
    const int*   elabs  = (const int*)d_in[2];
    const int*   mask   = (const int*)d_in[4];
    const float* sent   = (const float*)d_in[5];
    const float* Wenh = (const float*)d_in[6];  const float* benh = (const float*)d_in[7];
    const float* Wenm = (const float*)d_in[8];  const float* benm = (const float*)d_in[9];
    const float* Welh = (const float*)d_in[10]; const float* belh = (const float*)d_in[11];
    const float* Welm = (const float*)d_in[12]; const float* belm = (const float*)d_in[13];
    const float* baU  = (const float*)d_in[14];
    const float* baWd = (const float*)d_in[15];
    const float* baWe = (const float*)d_in[16];
    const float* bab  = (const float*)d_in[17];
    const float* lU   = (const float*)d_in[18];
    const float* lWl  = (const float*)d_in[19];
    const float* lWr  = (const float*)d_in[20];
    const float* lb   = (const float*)d_in[21];
    float* out = (float*)d_out;

    static int attr_done = 0;
    if (!attr_done) {
        cudaFuncSetAttribute(k_bilin_mma, cudaFuncAttributeMaxDynamicSharedMemorySize, SMB_TOTAL);
        cudaFuncSetAttribute(k_enc_mma, cudaFuncAttributeMaxDynamicSharedMemorySize, SME_BYTES);
        cudaFuncSetAttribute(k_tmp_mma, cudaFuncAttributeMaxDynamicSharedMemorySize, SME_BYTES);
        cudaFuncSetAttribute(k_ns_mma,  cudaFuncAttributeMaxDynamicSharedMemorySize, SME_BYTES);
        attr_done = 1;
    }

    k_trans<<<1456, 256>>>(Wenh, Wenm, Welh, Welm, benh, benm, belh, belm, baU);
    k_enc_mma<<<dim3(257, 6), 256, SME_BYTES>>>(mem, sent);
    k_tmp_mma<<<dim3(257, 2), 256, SME_BYTES>>>();
    k_dotvec<<<4104, 256>>>(baWd, baWe);
    k_ns_mma<<<dim3(5, 5, 64), 256, SME_BYTES>>>(bab);
    k_node_reduce<<<dim3(17, 64), 256>>>(eheads, mask, out);
    k_lin<<<dim3(513, 2), 256>>>(lWr, lb);
    k_bilin_mma<<<dim3(NTILES, NLB), 256, SMB_TOTAL>>>(lU, lWl, eheads);
    k_lbl_reduce<<<129, 256>>>(elabs, out);
    k_final<<<129, 256>>>(elabs, out);
}

// round 6
// speedup vs baseline: 3.5815x; 1.3327x over previous
#include <cuda_runtime.h>
#include <cuda_fp16.h>

#define NB   64
#define NL   512
#define NH   400
#define NEN  256
#define NEL  128
#define NLB  128
#define L1   513
#define NT   (NB * L1)     /* 32832 */
#define ENCW 768
#define NTILES 257         /* ceil(32832/128) */

/* output layout (flattened tuple, float32) */
#define OUT_PH 0
#define OUT_PL 32768
#define OUT_LB 65536
#define OUT_NN 98368
#define OUT_LN 98369

/* -------- scratch (device globals; no allocation allowed) -------- */
__device__ float g_enc[(size_t)NT * ENCW];      /* enh|enm|elh|elm  */
__device__ float g_tmp[(size_t)NT * NEN];
__device__ float g_dh[NT];
__device__ float g_em[NT];
__device__ float g_S[(size_t)NB * L1 * L1];
__device__ int   g_pred[NT];
__device__ float g_sg[(size_t)NLB * NT];
__device__ float g_sp[(size_t)NLB * NT];
__device__ float g_lin[(size_t)NLB * NT];
__device__ float g_partA[17 * 64];
__device__ float g_partB[129];
__device__ float g_WT[768 * NH];
__device__ float g_biasC[768];
__device__ float g_baUT[NEN * NEN];
__device__ __half g_Uh[(size_t)NLB * NEL * NEL];   /* lbl_U fp16 [n][d][e] */
__device__ __half g_elhh[(size_t)NT * NEL];        /* elh fp16 */
__device__ __half g_elmh[(size_t)NT * NEL];        /* elm fp16 */

__device__ __forceinline__ float elu1(float x) { return x > 0.f ? x : expm1f(x); }
__device__ __forceinline__ float logmask(int s) {
    return s == 0 ? -103.27893f : (s == 1 ? 0.f : 0.69314718f);
}
__device__ __forceinline__ unsigned f2tf32(float v) {
    unsigned t;
    asm("cvt.rna.tf32.f32 %0, %1;" : "=r"(t) : "f"(v));
    return t;
}
__device__ __forceinline__ void mma_tf32(float* c, unsigned a0, unsigned a1,
                                         unsigned a2, unsigned a3,
                                         unsigned b0, unsigned b1) {
    asm volatile(
        "mma.sync.aligned.m16n8k8.row.col.f32.tf32.tf32.f32 "
        "{%0,%1,%2,%3}, {%4,%5,%6,%7}, {%8,%9}, {%0,%1,%2,%3};\n"
        : "+f"(c[0]), "+f"(c[1]), "+f"(c[2]), "+f"(c[3])
        : "r"(a0), "r"(a1), "r"(a2), "r"(a3), "r"(b0), "r"(b1));
}
__device__ __forceinline__ void mma_f16(float* c, unsigned a0, unsigned a1,
                                        unsigned a2, unsigned a3,
                                        unsigned b0, unsigned b1) {
    asm volatile(
        "mma.sync.aligned.m16n8k16.row.col.f32.f16.f16.f32 "
        "{%0,%1,%2,%3}, {%4,%5,%6,%7}, {%8,%9}, {%0,%1,%2,%3};\n"
        : "+f"(c[0]), "+f"(c[1]), "+f"(c[2]), "+f"(c[3])
        : "r"(a0), "r"(a1), "r"(a2), "r"(a3), "r"(b0), "r"(b1));
}
__device__ __forceinline__ void split2(float4 v, uint4& h, uint4& l) {
    h.x = f2tf32(v.x); l.x = f2tf32(v.x - __uint_as_float(h.x));
    h.y = f2tf32(v.y); l.y = f2tf32(v.y - __uint_as_float(h.y));
    h.z = f2tf32(v.z); l.z = f2tf32(v.z - __uint_as_float(h.z));
    h.w = f2tf32(v.w); l.w = f2tf32(v.w - __uint_as_float(h.w));
}

/* ===== K0a: weight transposes ===== */
__global__ __launch_bounds__(256) void k_trans(
    const float* __restrict__ Wenh, const float* __restrict__ Wenm,
    const float* __restrict__ Welh, const float* __restrict__ Welm,
    const float* __restrict__ benh, const float* __restrict__ benm,
    const float* __restrict__ belh, const float* __restrict__ belm,
    const float* __restrict__ baU)
{
    const int i = blockIdx.x * 256 + threadIdx.x;
    if (i < 768 * NH) {
        const int k = i / 768, j = i % 768;
        float v;
        if (j < 256)      v = Wenh[k * NEN + j];
        else if (j < 512) v = Wenm[k * NEN + j - 256];
        else if (j < 640) v = Welh[k * NEL + j - 512];
        else              v = Welm[k * NEL + j - 640];
        g_WT[(size_t)j * NH + k] = v;
        if (k == 0)
            g_biasC[j] = (j < 256) ? benh[j] : (j < 512) ? benm[j - 256]
                       : (j < 640) ? belh[j - 512] : belm[j - 640];
    } else {
        const int i2 = i - 768 * NH;
        if (i2 < NEN * NEN) {
            const int k = i2 / NEN, n = i2 % NEN;
            g_baUT[(size_t)n * NEN + k] = baU[k * NEN + n];
        }
    }
}

/* ===== K0b: lbl_U -> fp16 ===== */
__global__ __launch_bounds__(256) void k_uh(const float* __restrict__ U)
{
    const size_t base = ((size_t)blockIdx.x * 256 + threadIdx.x) * 4;
    float4 v = *(const float4*)(U + base);
    __half2 h0 = __floats2half2_rn(v.x, v.y);
    __half2 h1 = __floats2half2_rn(v.z, v.w);
    uint2 wv; wv.x = *(unsigned*)&h0; wv.y = *(unsigned*)&h1;
    *(uint2*)&g_Uh[base] = wv;
}

/* ===== K0c: elh/elm -> fp16 (after k_enc) ===== */
__global__ __launch_bounds__(256) void k_half()
{
    const size_t idx = (size_t)blockIdx.x * 256 + threadIdx.x;
    const size_t base = idx * 4;
    const int t = (int)(base >> 8);
    const int r = (int)(base & 255);
    float4 v = *(const float4*)(g_enc + (size_t)t * ENCW + 512 + r);
    __half2 h0 = __floats2half2_rn(v.x, v.y);
    __half2 h1 = __floats2half2_rn(v.z, v.w);
    uint2 wv; wv.x = *(unsigned*)&h0; wv.y = *(unsigned*)&h1;
    if (r < 128) *(uint2*)&g_elhh[(size_t)t * NEL + r] = wv;
    else         *(uint2*)&g_elmh[(size_t)t * NEL + r - 128] = wv;
}

/* ===== 3xTF32 GEMM skeleton constants ===== */
#define ESTR 36
#define SME_BYTES (4 * 128 * ESTR * 4)

/* ===== K1: encoder GEMM + ELU, 3xtf32 ===== */
__global__ __launch_bounds__(256) void k_enc_mma(
    const float* __restrict__ mem, const float* __restrict__ sent)
{
    extern __shared__ unsigned smu[];
    unsigned* Ah = smu;
    unsigned* Al = smu + 128 * ESTR;
    unsigned* Bh = smu + 2 * 128 * ESTR;
    unsigned* Bl = smu + 3 * 128 * ESTR;
    const int tid = threadIdx.x, lane = tid & 31, w = tid >> 5;
    const int q = lane & 3, oct = lane >> 2;
    const int t0 = blockIdx.x * 128;
    const int nb = blockIdx.y * 128;

    const int srow = tid >> 1, skg = (tid & 1) * 16;
    const int ta = t0 + srow;
    const bool aval = ta < NT;
    const int bA = aval ? ta / L1 : 0, lA = aval ? ta % L1 : 0;
    const float* aptr = (lA == 0) ? sent : (mem + ((size_t)bA * NL + (lA - 1)) * NH);
    const float* bptr = g_WT + (size_t)(nb + srow) * NH;

    float acc[16][4] = {};
    for (int k0 = 0; k0 < NH; k0 += 32) {
#pragma unroll
        for (int g = 0; g < 4; g++) {
            const int k = skg + g * 4, gk = k0 + k;
            const bool kok = gk < NH;
            float4 va = (aval && kok) ? *(const float4*)(aptr + gk) : make_float4(0, 0, 0, 0);
            float4 vb = kok ? *(const float4*)(bptr + gk) : make_float4(0, 0, 0, 0);
            uint4 ha, la, hb, lb;
            split2(va, ha, la); split2(vb, hb, lb);
            *(uint4*)&Ah[srow * ESTR + k] = ha;
            *(uint4*)&Al[srow * ESTR + k] = la;
            *(uint4*)&Bh[srow * ESTR + k] = hb;
            *(uint4*)&Bl[srow * ESTR + k] = lb;
        }
        __syncthreads();
        const int r0 = w * 16 + oct;
#pragma unroll
        for (int kb = 0; kb < 32; kb += 8) {
            const unsigned ah0 = Ah[r0 * ESTR + kb + q],     ah1 = Ah[(r0 + 8) * ESTR + kb + q];
            const unsigned ah2 = Ah[r0 * ESTR + kb + q + 4], ah3 = Ah[(r0 + 8) * ESTR + kb + q + 4];
            const unsigned al0 = Al[r0 * ESTR + kb + q],     al1 = Al[(r0 + 8) * ESTR + kb + q];
            const unsigned al2 = Al[r0 * ESTR + kb + q + 4], al3 = Al[(r0 + 8) * ESTR + kb + q + 4];
#pragma unroll
            for (int nt = 0; nt < 16; nt++) {
                const int cb = (nt * 8 + oct) * ESTR + kb;
                const unsigned bh0 = Bh[cb + q], bh1 = Bh[cb + q + 4];
                const unsigned bl0 = Bl[cb + q], bl1 = Bl[cb + q + 4];
                mma_tf32(acc[nt], ah0, ah1, ah2, ah3, bh0, bh1);
                mma_tf32(acc[nt], ah0, ah1, ah2, ah3, bl0, bl1);
                mma_tf32(acc[nt], al0, al1, al2, al3, bh0, bh1);
            }
        }
        __syncthreads();
    }
    const int r0 = w * 16 + oct;
    const int tA = t0 + r0, tB = tA + 8;
#pragma unroll
    for (int nt = 0; nt < 16; nt++) {
        const int c = nt * 8 + q * 2;
        const float b0 = g_biasC[nb + c], b1 = g_biasC[nb + c + 1];
        if (tA < NT) {
            float2 v; v.x = elu1(acc[nt][0] + b0); v.y = elu1(acc[nt][1] + b1);
            *(float2*)&g_enc[(size_t)tA * ENCW + nb + c] = v;
        }
        if (tB < NT) {
            float2 v; v.x = elu1(acc[nt][2] + b0); v.y = elu1(acc[nt][3] + b1);
            *(float2*)&g_enc[(size_t)tB * ENCW + nb + c] = v;
        }
    }
}

/* ===== K2: tmp = enh @ ba_U, 3xtf32 ===== */
__global__ __launch_bounds__(256) void k_tmp_mma()
{
    extern __shared__ unsigned smu[];
    unsigned* Ah = smu;
    unsigned* Al = smu + 128 * ESTR;
    unsigned* Bh = smu + 2 * 128 * ESTR;
    unsigned* Bl = smu + 3 * 128 * ESTR;
    const int tid = threadIdx.x, lane = tid & 31, w = tid >> 5;
    const int q = lane & 3, oct = lane >> 2;
    const int t0 = blockIdx.x * 128;
    const int nb = blockIdx.y * 128;

    const int srow = tid >> 1, skg = (tid & 1) * 16;
    const int ta = t0 + srow;
    const float* aptr = g_enc + (size_t)(ta < NT ? ta : 0) * ENCW;
    const float* bptr = g_baUT + (size_t)(nb + srow) * NEN;

    float acc[16][4] = {};
    for (int k0 = 0; k0 < NEN; k0 += 32) {
#pragma unroll
        for (int g = 0; g < 4; g++) {
            const int k = skg + g * 4;
            float4 va = *(const float4*)(aptr + k0 + k);
            float4 vb = *(const float4*)(bptr + k0 + k);
            uint4 ha, la, hb, lb;
            split2(va, ha, la); split2(vb, hb, lb);
            *(uint4*)&Ah[srow * ESTR + k] = ha;
            *(uint4*)&Al[srow * ESTR + k] = la;
            *(uint4*)&Bh[srow * ESTR + k] = hb;
            *(uint4*)&Bl[srow * ESTR + k] = lb;
        }
        __syncthreads();
        const int r0 = w * 16 + oct;
#pragma unroll
        for (int kb = 0; kb < 32; kb += 8) {
            const unsigned ah0 = Ah[r0 * ESTR + kb + q],     ah1 = Ah[(r0 + 8) * ESTR + kb + q];
            const unsigned ah2 = Ah[r0 * ESTR + kb + q + 4], ah3 = Ah[(r0 + 8) * ESTR + kb + q + 4];
            const unsigned al0 = Al[r0 * ESTR + kb + q],     al1 = Al[(r0 + 8) * ESTR + kb + q];
            const unsigned al2 = Al[r0 * ESTR + kb + q + 4], al3 = Al[(r0 + 8) * ESTR + kb + q + 4];
#pragma unroll
            for (int nt = 0; nt < 16; nt++) {
                const int cb = (nt * 8 + oct) * ESTR + kb;
                const unsigned bh0 = Bh[cb + q], bh1 = Bh[cb + q + 4];
                const unsigned bl0 = Bl[cb + q], bl1 = Bl[cb + q + 4];
                mma_tf32(acc[nt], ah0, ah1, ah2, ah3, bh0, bh1);
                mma_tf32(acc[nt], ah0, ah1, ah2, ah3, bl0, bl1);
                mma_tf32(acc[nt], al0, al1, al2, al3, bh0, bh1);
            }
        }
        __syncthreads();
    }
    const int r0 = w * 16 + oct;
    const int tA = t0 + r0, tB = tA + 8;
#pragma unroll
    for (int nt = 0; nt < 16; nt++) {
        const int c = nt * 8 + q * 2;
        if (tA < NT)
            *(float2*)&g_tmp[(size_t)tA * NEN + nb + c] = make_float2(acc[nt][0], acc[nt][1]);
        if (tB < NT)
            *(float2*)&g_tmp[(size_t)tB * NEN + nb + c] = make_float2(acc[nt][2], acc[nt][3]);
    }
}

/* ===== K3: node scores, 3xtf32 ===== */
__global__ __launch_bounds__(256) void k_ns_mma(const float* __restrict__ bab)
{
    extern __shared__ unsigned smu[];
    unsigned* Ah = smu;
    unsigned* Al = smu + 128 * ESTR;
    unsigned* Bh = smu + 2 * 128 * ESTR;
    unsigned* Bl = smu + 3 * 128 * ESTR;
    const int tid = threadIdx.x, lane = tid & 31, w = tid >> 5;
    const int q = lane & 3, oct = lane >> 2;
    const int b = blockIdx.z;
    const int h0 = blockIdx.x * 128, m0 = blockIdx.y * 128;

    const int srow = tid >> 1, skg = (tid & 1) * 16;
    int hr = h0 + srow; if (hr > 512) hr = 512;
    int mr = m0 + srow; if (mr > 512) mr = 512;
    const float* aptr = g_tmp + (size_t)(b * L1 + hr) * NEN;
    const float* bptr = g_enc + (size_t)(b * L1 + mr) * ENCW + 256;

    float acc[16][4] = {};
    for (int k0 = 0; k0 < NEN; k0 += 32) {
#pragma unroll
        for (int g = 0; g < 4; g++) {
            const int k = skg + g * 4;
            float4 va = *(const float4*)(aptr + k0 + k);
            float4 vb = *(const float4*)(bptr + k0 + k);
            uint4 ha, la, hb, lb;
            split2(va, ha, la); split2(vb, hb, lb);
            *(uint4*)&Ah[srow * ESTR + k] = ha;
            *(uint4*)&Al[srow * ESTR + k] = la;
            *(uint4*)&Bh[srow * ESTR + k] = hb;
            *(uint4*)&Bl[srow * ESTR + k] = lb;
        }
        __syncthreads();
        const int r0 = w * 16 + oct;
#pragma unroll
        for (int kb = 0; kb < 32; kb += 8) {
            const unsigned ah0 = Ah[r0 * ESTR + kb + q],     ah1 = Ah[(r0 + 8) * ESTR + kb + q];
            const unsigned ah2 = Ah[r0 * ESTR + kb + q + 4], ah3 = Ah[(r0 + 8) * ESTR + kb + q + 4];
            const unsigned al0 = Al[r0 * ESTR + kb + q],     al1 = Al[(r0 + 8) * ESTR + kb + q];
            const unsigned al2 = Al[r0 * ESTR + kb + q + 4], al3 = Al[(r0 + 8) * ESTR + kb + q + 4];
#pragma unroll
            for (int nt = 0; nt < 16; nt++) {
                const int cb = (nt * 8 + oct) * ESTR + kb;
                const unsigned bh0 = Bh[cb + q], bh1 = Bh[cb + q + 4];
                const unsigned bl0 = Bl[cb + q], bl1 = Bl[cb + q + 4];
                mma_tf32(acc[nt], ah0, ah1, ah2, ah3, bh0, bh1);
                mma_tf32(acc[nt], ah0, ah1, ah2, ah3, bl0, bl1);
                mma_tf32(acc[nt], al0, al1, al2, al3, bh0, bh1);
            }
        }
        __syncthreads();
    }
    const int r0 = w * 16 + oct;
    const int hA = h0 + r0, hB = hA + 8;
    const float bb0 = __ldg(bab);
    const float dhA = (hA <= 512) ? g_dh[b * L1 + hA] : 0.f;
    const float dhB = (hB <= 512) ? g_dh[b * L1 + hB] : 0.f;
    float* Sb = g_S + (size_t)b * L1 * L1;
#pragma unroll
    for (int nt = 0; nt < 16; nt++) {
        const int m = m0 + nt * 8 + q * 2;
        if (m <= 512) {
            const float em0 = g_em[b * L1 + m];
            if (hA <= 512) Sb[(size_t)hA * L1 + m] = acc[nt][0] + dhA + em0 + bb0;
            if (hB <= 512) Sb[(size_t)hB * L1 + m] = acc[nt][2] + dhB + em0 + bb0;
        }
        if (m + 1 <= 512) {
            const float em1 = g_em[b * L1 + m + 1];
            if (hA <= 512) Sb[(size_t)hA * L1 + m + 1] = acc[nt][1] + dhA + em1 + bb0;
            if (hB <= 512) Sb[(size_t)hB * L1 + m + 1] = acc[nt][3] + dhB + em1 + bb0;
        }
    }
}

/* ============ K2b: dh = enh . ba_Wd, em = enm . ba_We ============ */
__global__ __launch_bounds__(256) void k_dotvec(
    const float* __restrict__ Wd, const float* __restrict__ We)
{
    const int gw = (blockIdx.x * blockDim.x + threadIdx.x) >> 5;
    const int lane = threadIdx.x & 31;
    if (gw >= NT) return;
    const float* r = g_enc + (size_t)gw * ENCW;
    float s1 = 0.f, s2 = 0.f;
#pragma unroll
    for (int k = lane; k < NEN; k += 32) {
        s1 += r[k] * Wd[k];
        s2 += r[256 + k] * We[k];
    }
#pragma unroll
    for (int o = 16; o; o >>= 1) {
        s1 += __shfl_xor_sync(0xffffffffu, s1, o);
        s2 += __shfl_xor_sync(0xffffffffu, s2, o);
    }
    if (!lane) { g_dh[gw] = s1; g_em[gw] = s2; }
}

/* ==== K4: per-column logsumexp + gold pick + decode argmax ==== */
__global__ __launch_bounds__(256) void k_node_reduce(
    const int* __restrict__ eheads, const int* __restrict__ mask,
    float* __restrict__ out)
{
    const int b = blockIdx.y;
    const int m0 = blockIdx.x * 32;
    const int tid = threadIdx.x, lane = tid & 31, w = tid >> 5;
    __shared__ int mk[L1];
    __shared__ float s_max[8][32], s_sum[8][32], s_bv[8][32];
    __shared__ int s_bi[8][32];
    for (int i = tid; i < L1; i += 256) mk[i] = (i == 0) ? 0 : mask[b * NL + i - 1];
    __syncthreads();

    const int m = m0 + lane;
    const bool mv = m < L1;
    const int msafe = mv ? m : (L1 - 1);
    const int mm_ = mk[msafe];
    const float* Sb = g_S + (size_t)b * L1 * L1;

    float rmax = -1e30f, rsum = 0.f, bv = -1e30f;
    int bi = 0x7fffffff;
    for (int h = w; h < L1; h += 8) {
        float s = Sb[(size_t)h * L1 + msafe];
        int mh = mk[h];
        float x = s + logmask(mh + mm_);
        if (x > rmax) { rsum = rsum * expf(rmax - x) + 1.f; rmax = x; }
        else            rsum += expf(x - rmax);
        float dv = s + (1.f - (float)mh) * (-1e8f);
        if (h != msafe && dv > bv) { bv = dv; bi = h; }
    }
    s_max[w][lane] = rmax; s_sum[w][lane] = rsum;
    s_bv[w][lane] = bv;    s_bi[w][lane] = bi;
    __syncthreads();

    if (w == 0) {
        float tm = -1e30f;
#pragma unroll
        for (int i = 0; i < 8; i++) tm = fmaxf(tm, s_max[i][lane]);
        float ts = 0.f;
#pragma unroll
        for (int i = 0; i < 8; i++) ts += s_sum[i][lane] * expf(s_max[i][lane] - tm);
        float lse = tm + logf(ts);
        int gh = (msafe == 0) ? 0 : eheads[b * NL + msafe - 1];
        float xg = Sb[(size_t)gh * L1 + msafe] + logmask(mk[gh] + mm_);
        float bbv = -1e30f; int bbi = 0x7fffffff;
#pragma unroll
        for (int i = 0; i < 8; i++) {
            float v = s_bv[i][lane]; int ix = s_bi[i][lane];
            if (v > bbv || (v == bbv && ix < bbi)) { bbv = v; bbi = ix; }
        }
        float contrib = 0.f;
        if (mv) {
            g_pred[b * L1 + m] = bbi;
            if (m >= 1) {
                out[OUT_PH + (size_t)b * NL + m - 1] = (float)bbi;
                contrib = -(xg - lse);
            }
        }
#pragma unroll
        for (int o = 16; o; o >>= 1) contrib += __shfl_xor_sync(0xffffffffu, contrib, o);
        if (lane == 0) g_partA[blockIdx.y * 17 + blockIdx.x] = contrib;
    }
}

/* ===== K5: label bilinear, fp16 m16n8k16, NBL labels per CTA ===== */
#define NBL  16
#define SW   68
#define W_AS 0
#define W_GS 8704
#define W_PS 17408
#define W_B0 26112
#define W_B1 34816
#define W_WL 43520
#define W_WB 45568
#define SMB2_BYTES ((45568 + 256) * 4)

__global__ __launch_bounds__(256) void k_bilin_mma(
    const float* __restrict__ Wl, const int* __restrict__ eheads)
{
    extern __shared__ unsigned smu[];
    float* Wls = (float*)(smu + W_WL);
    float* wb  = (float*)(smu + W_WB);
    const int tid = threadIdx.x, lane = tid & 31, w = tid >> 5;
    const int q = lane & 3, oct = lane >> 2;
    const int nb0 = blockIdx.y * NBL;
    const int t0 = blockIdx.x * 128;

    const int row = tid >> 1, h = tid & 1;
    const int ts = t0 + row;
    const bool tv = ts < NT;
    const int tc = tv ? ts : 0;

    /* As: elm fp16, thread (row, h) stages its 64-half chunk */
    {
        unsigned* dst = smu + W_AS + row * SW + h * 32;
        if (tv) {
            const uint4* src = (const uint4*)(g_elmh + (size_t)tc * NEL + h * 64);
#pragma unroll
            for (int j = 0; j < 8; j++) *(uint4*)(dst + 4 * j) = src[j];
        } else {
            uint4 z = make_uint4(0, 0, 0, 0);
#pragma unroll
            for (int j = 0; j < 8; j++) *(uint4*)(dst + 4 * j) = z;
        }
    }
    /* Gs/Ps: h selects matrix (G vs P); each thread stages the FULL
       128-half row (16 uint4) — this was the round-5 bug (only 8). */
    {
        const int bb = tc / L1, ll = tc - bb * L1;
        const int hr = h ? g_pred[tc] : ((ll == 0) ? 0 : eheads[bb * NL + ll - 1]);
        const uint4* src = (const uint4*)(g_elhh + (size_t)(bb * L1 + hr) * NEL);
        unsigned* dst = smu + (h ? W_PS : W_GS) + row * SW;
#pragma unroll
        for (int j = 0; j < 16; j++) *(uint4*)(dst + 4 * j) = src[j];
    }
    for (int idx = tid; idx < NBL * 128; idx += 256)
        Wls[idx] = Wl[nb0 * 128 + idx];
    {
        const uint4* src = (const uint4*)(g_Uh + ((size_t)nb0 * NEL + row) * NEL + h * 64);
        unsigned* dst = smu + W_B0 + row * SW + h * 32;
#pragma unroll
        for (int j = 0; j < 8; j++) *(uint4*)(dst + 4 * j) = src[j];
    }
    __syncthreads();

    const int r0 = w * 16 + oct;
    const unsigned* As = smu + W_AS;
    const unsigned* Gs = smu + W_GS;
    const unsigned* Ps = smu + W_PS;

    for (int i = 0; i < NBL; i++) {
        uint4 pf[8];
        if (i + 1 < NBL) {
            const uint4* src = (const uint4*)(g_Uh + ((size_t)(nb0 + i + 1) * NEL + row) * NEL + h * 64);
#pragma unroll
            for (int j = 0; j < 8; j++) pf[j] = src[j];
        }
        const unsigned* Bs = smu + W_B0 + (i & 1) * 8704;

        float acc[16][4] = {};
#pragma unroll
        for (int ks = 0; ks < 8; ks++) {
            const int kw = ks * 8 + q;
            const unsigned a0 = As[r0 * SW + kw],     a1 = As[(r0 + 8) * SW + kw];
            const unsigned a2 = As[r0 * SW + kw + 4], a3 = As[(r0 + 8) * SW + kw + 4];
#pragma unroll
            for (int nt = 0; nt < 16; nt++) {
                const int cb = (nt * 8 + oct) * SW + kw;
                mma_f16(acc[nt], a0, a1, a2, a3, Bs[cb], Bs[cb + 4]);
            }
        }

        const float* Wln = Wls + i * 128;
        float sg0 = 0.f, sp0 = 0.f, sg1 = 0.f, sp1 = 0.f;
#pragma unroll
        for (int nt = 0; nt < 16; nt++) {
            const int ch = nt * 8 + 2 * q;
            const int cw = nt * 4 + q;
            const float w0 = Wln[ch], w1 = Wln[ch + 1];
            const float d00 = acc[nt][0] + w0, d01 = acc[nt][1] + w1;
            const float d10 = acc[nt][2] + w0, d11 = acc[nt][3] + w1;
            unsigned ug0 = Gs[r0 * SW + cw], ug1 = Gs[(r0 + 8) * SW + cw];
            unsigned up0 = Ps[r0 * SW + cw], up1 = Ps[(r0 + 8) * SW + cw];
            float2 g0 = __half22float2(*(__half2*)&ug0);
            float2 g1 = __half22float2(*(__half2*)&ug1);
            float2 p0 = __half22float2(*(__half2*)&up0);
            float2 p1 = __half22float2(*(__half2*)&up1);
            sg0 += d00 * g0.x + d01 * g0.y;  sp0 += d00 * p0.x + d01 * p0.y;
            sg1 += d10 * g1.x + d11 * g1.y;  sp1 += d10 * p1.x + d11 * p1.y;
        }
#pragma unroll
        for (int o = 1; o <= 2; o <<= 1) {
            sg0 += __shfl_xor_sync(0xffffffffu, sg0, o);
            sp0 += __shfl_xor_sync(0xffffffffu, sp0, o);
            sg1 += __shfl_xor_sync(0xffffffffu, sg1, o);
            sp1 += __shfl_xor_sync(0xffffffffu, sp1, o);
        }
        if (q == 0) {
            wb[w * 32 + oct * 2 + 0] = sg0;
            wb[w * 32 + oct * 2 + 1] = sp0;
            wb[w * 32 + (oct + 8) * 2 + 0] = sg1;
            wb[w * 32 + (oct + 8) * 2 + 1] = sp1;
        }
        __syncwarp();
        {
            const int rr = lane & 15;
            const int t = t0 + w * 16 + rr;
            const size_t n = (size_t)(nb0 + i);
            if (t < NT) {
                if (lane < 16) g_sg[n * NT + t] = wb[w * 32 + rr * 2];
                else           g_sp[n * NT + t] = wb[w * 32 + rr * 2 + 1];
            }
        }
        __syncwarp();

        if (i + 1 < NBL) {
            unsigned* dst = smu + W_B0 + ((i + 1) & 1) * 8704 + row * SW + h * 32;
#pragma unroll
            for (int j = 0; j < 8; j++) *(uint4*)(dst + 4 * j) = pf[j];
        }
        __syncthreads();
    }
}

/* ===== K5b: lin[n,t] = elm[t] . Wr[n] + lbl_b[n] ===== */
__global__ __launch_bounds__(256) void k_lin(
    const float* __restrict__ Wr, const float* __restrict__ lb)
{
    __shared__ float As[16][64];
    __shared__ float Bs[16][64];
    const int tid = threadIdx.x;
    const int t0 = blockIdx.x * 64, n0 = blockIdx.y * 64;
    const int ar = tid >> 2, ac = (tid & 3) * 4;
    const float* arow = g_enc + (size_t)(t0 + ar) * ENCW + 640;
    const float* brow = Wr + (size_t)(n0 + ar) * NEL;
    const int ty = tid >> 4, tx = tid & 15;
    float acc[4][4] = {};
    for (int k0 = 0; k0 < NEL; k0 += 16) {
        float4 av = *(const float4*)(arow + k0 + ac);
        float4 bv = *(const float4*)(brow + k0 + ac);
        As[ac + 0][ar] = av.x; As[ac + 1][ar] = av.y;
        As[ac + 2][ar] = av.z; As[ac + 3][ar] = av.w;
        Bs[ac + 0][ar] = bv.x; Bs[ac + 1][ar] = bv.y;
        Bs[ac + 2][ar] = bv.z; Bs[ac + 3][ar] = bv.w;
        __syncthreads();
#pragma unroll
        for (int k = 0; k < 16; k++) {
            float a[4], bb[4];
#pragma unroll
            for (int i = 0; i < 4; i++) a[i]  = As[k][ty * 4 + i];
#pragma unroll
            for (int j = 0; j < 4; j++) bb[j] = Bs[k][tx * 4 + j];
#pragma unroll
            for (int i = 0; i < 4; i++)
#pragma unroll
                for (int j = 0; j < 4; j++) acc[i][j] += a[i] * bb[j];
        }
        __syncthreads();
    }
#pragma unroll
    for (int i = 0; i < 4; i++) {
        int t = t0 + ty * 4 + i;
#pragma unroll
        for (int j = 0; j < 4; j++) {
            int nn = n0 + tx * 4 + j;
            g_lin[(size_t)nn * NT + t] = acc[i][j] + lb[nn];
        }
    }
}

/* ===== K6: label log-softmax over n + max over n ===== */
__global__ __launch_bounds__(256) void k_lbl_reduce(
    const int* __restrict__ elabels, float* __restrict__ out)
{
    __shared__ float red[256];
    const int t = blockIdx.x * 256 + threadIdx.x;
    float contrib = 0.f;
    if (t < NT) {
        int b = t / L1, l = t % L1;
        int lab = (l == 0) ? 0 : elabels[b * NL + l - 1];
        float mg = -1e30f, sg = 0.f, mp = -1e30f, xlab = 0.f;
        for (int n = 0; n < NLB; n++) {
            float lin = g_lin[(size_t)n * NT + t];
            float xg = g_sg[(size_t)n * NT + t] + lin;
            float xp = g_sp[(size_t)n * NT + t] + lin;
            if (n == lab) xlab = xg;
            if (xg > mg) { sg = sg * expf(mg - xg) + 1.f; mg = xg; }
            else           sg += expf(xg - mg);
            mp = fmaxf(mp, xp);
        }
        float ll = xlab - (mg + logf(sg));
        if (l >= 1) {
            contrib = -ll;
            out[OUT_PL + (size_t)b * NL + l - 1] = mp;
        }
    }
    red[threadIdx.x] = contrib;
    __syncthreads();
    for (int s = 128; s; s >>= 1) {
        if (threadIdx.x < s) red[threadIdx.x] += red[threadIdx.x + s];
        __syncthreads();
    }
    if (!threadIdx.x) g_partB[blockIdx.x] = red[0];
}

/* ===== K7: labels1 output + deterministic NLL finalize ===== */
__global__ __launch_bounds__(256) void k_final(
    const int* __restrict__ elabels, float* __restrict__ out)
{
    const int i = blockIdx.x * 256 + threadIdx.x;
    if (i < NT) {
        int b = i / L1, l = i % L1;
        out[OUT_LB + i] = (l == 0) ? 0.f : (float)elabels[b * NL + l - 1];
    }
    if (i == 0) {
        float s = 0.f;
        for (int k = 0; k < 17 * 64; k++) s += g_partA[k];
        out[OUT_NN] = s;
        float s2 = 0.f;
        for (int k = 0; k < 129; k++) s2 += g_partB[k];
        out[OUT_LN] = s2;
    }
}

extern "C" void kernel_launch(void* const* d_in, const int* in_sizes, int n_in,
                              void* d_out, int out_size)
{
    const float* mem    = (const float*)d_in[0];
    const int*   eheads = (const int*)d_in[1];
    const int*   elabs  = (const int*)d_in[2];
    const int*   mask   = (const int*)d_in[4];
    const float* sent   = (const float*)d_in[5];
    const float* Wenh = (const float*)d_in[6];  const float* benh = (const float*)d_in[7];
    const float* Wenm = (const float*)d_in[8];  const float* benm = (const float*)d_in[9];
    const float* Welh = (const float*)d_in[10]; const float* belh = (const float*)d_in[11];
    const float* Welm = (const float*)d_in[12]; const float* belm = (const float*)d_in[13];
    const float* baU  = (const float*)d_in[14];
    const float* baWd = (const float*)d_in[15];
    const float* baWe = (const float*)d_in[16];
    const float* bab  = (const float*)d_in[17];
    const float* lU   = (const float*)d_in[18];
    const float* lWl  = (const float*)d_in[19];
    const float* lWr  = (const float*)d_in[20];
    const float* lb   = (const float*)d_in[21];
    float* out = (float*)d_out;

    cudaFuncSetAttribute(k_bilin_mma, cudaFuncAttributeMaxDynamicSharedMemorySize, SMB2_BYTES);
    cudaFuncSetAttribute(k_enc_mma, cudaFuncAttributeMaxDynamicSharedMemorySize, SME_BYTES);
    cudaFuncSetAttribute(k_tmp_mma, cudaFuncAttributeMaxDynamicSharedMemorySize, SME_BYTES);
    cudaFuncSetAttribute(k_ns_mma,  cudaFuncAttributeMaxDynamicSharedMemorySize, SME_BYTES);

    k_trans<<<1456, 256>>>(Wenh, Wenm, Welh, Welm, benh, benm, belh, belm, baU);
    k_uh<<<2048, 256>>>(lU);
    k_enc_mma<<<dim3(257, 6), 256, SME_BYTES>>>(mem, sent);
    k_half<<<8208, 256>>>();
    k_tmp_mma<<<dim3(257, 2), 256, SME_BYTES>>>();
    k_dotvec<<<4104, 256>>>(baWd, baWe);
    k_ns_mma<<<dim3(5, 5, 64), 256, SME_BYTES>>>(bab);
    k_node_reduce<<<dim3(17, 64), 256>>>(eheads, mask, out);
    k_lin<<<dim3(513, 2), 256>>>(lWr, lb);
    k_bilin_mma<<<dim3(NTILES, 8), 256, SMB2_BYTES>>>(lWl, eheads);
    k_lbl_reduce<<<129, 256>>>(elabs, out);
    k_final<<<129, 256>>>(elabs, out);
}

// round 7
// speedup vs baseline: 4.0214x; 1.1228x over previous
#include <cuda_runtime.h>
#include <cuda_fp16.h>

#define NB   64
#define NL   512
#define NH   400
#define NHP  448            /* NH padded to 64 multiple */
#define NEN  256
#define NEL  128
#define NLB  128
#define L1   513
#define NT   (NB * L1)      /* 32832 */
#define ENCW 768
#define NTILES 257

/* output layout (flattened tuple, float32) */
#define OUT_PH 0
#define OUT_PL 32768
#define OUT_LB 65536
#define OUT_NN 98368
#define OUT_LN 98369

/* -------- scratch (device globals) -------- */
__device__ float  g_enc[(size_t)NT * ENCW];      /* enh|enm|elh|elm fp32 */
__device__ float  g_dh[NT];
__device__ float  g_em[NT];
__device__ float  g_S[(size_t)NB * L1 * L1];
__device__ int    g_pred[NT];
__device__ float  g_sg[(size_t)NLB * NT];
__device__ float  g_sp[(size_t)NLB * NT];
__device__ float  g_lin[(size_t)NLB * NT];
__device__ float  g_partA[17 * 64];
__device__ float  g_partB[129];
__device__ float  g_biasC[768];
__device__ __half g_memh[(size_t)NT * NHP];      /* input hi/lo fp16 */
__device__ __half g_meml[(size_t)NT * NHP];
__device__ __half g_WTh[768 * NHP];              /* W concat^T hi/lo */
__device__ __half g_WTl[768 * NHP];
__device__ __half g_baUTh[NEN * NEN];
__device__ __half g_baUTl[NEN * NEN];
__device__ __half g_enhh[(size_t)NT * NEN];      /* enh hi/lo */
__device__ __half g_enhl[(size_t)NT * NEN];
__device__ __half g_enmh[(size_t)NT * NEN];      /* enm hi/lo */
__device__ __half g_enml[(size_t)NT * NEN];
__device__ __half g_tmph[(size_t)NT * NEN];      /* enh@baU hi/lo */
__device__ __half g_tmpl[(size_t)NT * NEN];
__device__ __half g_Uh[(size_t)NLB * NEL * NEL]; /* lbl_U fp16 */
__device__ __half g_elhh[(size_t)NT * NEL];      /* elh fp16 (hi only) */
__device__ __half g_elmh[(size_t)NT * NEL];      /* elm fp16 (hi only) */

__device__ __forceinline__ float elu1(float x) { return x > 0.f ? x : expm1f(x); }
__device__ __forceinline__ float logmask(int s) {
    return s == 0 ? -103.27893f : (s == 1 ? 0.f : 0.69314718f);
}
__device__ __forceinline__ void fsplit(float v, __half& h, __half& l) {
    h = __float2half_rn(v);
    l = __float2half_rn(v - __half2float(h));
}
__device__ __forceinline__ void mma_f16(float* c, unsigned a0, unsigned a1,
                                        unsigned a2, unsigned a3,
                                        unsigned b0, unsigned b1) {
    asm volatile(
        "mma.sync.aligned.m16n8k16.row.col.f32.f16.f16.f32 "
        "{%0,%1,%2,%3}, {%4,%5,%6,%7}, {%8,%9}, {%0,%1,%2,%3};\n"
        : "+f"(c[0]), "+f"(c[1]), "+f"(c[2]), "+f"(c[3])
        : "r"(a0), "r"(a1), "r"(a2), "r"(a3), "r"(b0), "r"(b1));
}

/* ===== K0a: weight transposes + fp16 hi/lo split (one-shot) ===== */
__global__ __launch_bounds__(256) void k_trans(
    const float* __restrict__ Wenh, const float* __restrict__ Wenm,
    const float* __restrict__ Welh, const float* __restrict__ Welm,
    const float* __restrict__ benh, const float* __restrict__ benm,
    const float* __restrict__ belh, const float* __restrict__ belm,
    const float* __restrict__ baU)
{
    const int i = blockIdx.x * 256 + threadIdx.x;
    if (i < 768 * NHP) {
        const int k = i / 768, j = i % 768;
        float v = 0.f;
        if (k < NH) {
            if (j < 256)      v = Wenh[k * NEN + j];
            else if (j < 512) v = Wenm[k * NEN + j - 256];
            else if (j < 640) v = Welh[k * NEL + j - 512];
            else              v = Welm[k * NEL + j - 640];
        }
        __half h, l; fsplit(v, h, l);
        g_WTh[(size_t)j * NHP + k] = h;
        g_WTl[(size_t)j * NHP + k] = l;
        if (k == 0)
            g_biasC[j] = (j < 256) ? benh[j] : (j < 512) ? benm[j - 256]
                       : (j < 640) ? belh[j - 512] : belm[j - 640];
    } else {
        const int i2 = i - 768 * NHP;
        if (i2 < NEN * NEN) {
            const int k = i2 / NEN, n = i2 % NEN;
            __half h, l; fsplit(baU[k * NEN + n], h, l);
            g_baUTh[n * NEN + k] = h;
            g_baUTl[n * NEN + k] = l;
        }
    }
}

/* ===== K0b: lbl_U -> fp16 ===== */
__global__ __launch_bounds__(256) void k_uh(const float* __restrict__ U)
{
    const size_t base = ((size_t)blockIdx.x * 256 + threadIdx.x) * 4;
    float4 v = *(const float4*)(U + base);
    __half2 h0 = __floats2half2_rn(v.x, v.y);
    __half2 h1 = __floats2half2_rn(v.z, v.w);
    uint2 wv; wv.x = *(unsigned*)&h0; wv.y = *(unsigned*)&h1;
    *(uint2*)&g_Uh[base] = wv;
}

/* ===== K0c: [sentinel;mem] -> fp16 hi/lo, K padded to 448 ===== */
__global__ __launch_bounds__(256) void k_msplit(
    const float* __restrict__ mem, const float* __restrict__ sent)
{
    const size_t idx = (size_t)blockIdx.x * 256 + threadIdx.x;   /* NT*448 exact */
    const int t = (int)(idx / NHP), k = (int)(idx % NHP);
    const int b = t / L1, l = t - b * L1;
    float v = 0.f;
    if (k < NH) v = (l == 0) ? sent[k] : mem[((size_t)b * NL + (l - 1)) * NH + k];
    __half h, lo; fsplit(v, h, lo);
    g_memh[idx] = h; g_meml[idx] = lo;
}

/* ===== shared 3xfp16 GEMM pieces: 128x128 tile, K-chunk 64 ===== */
#define HSTR 36                                   /* word stride, 36%32=4 */
#define SME2_BYTES (4 * 128 * HSTR * 4)           /* Ah|Al|Bh|Bl = 73728 */

__device__ __forceinline__ void stage64(unsigned* dstRow, const __half* src, int h) {
    const uint4* s = (const uint4*)(src + h * 32);
    uint4* d = (uint4*)(dstRow + h * 16);
    d[0] = s[0]; d[1] = s[1]; d[2] = s[2]; d[3] = s[3];
}
__device__ __forceinline__ void stage64z(unsigned* dstRow, int h) {
    uint4 z = make_uint4(0, 0, 0, 0);
    uint4* d = (uint4*)(dstRow + h * 16);
    d[0] = z; d[1] = z; d[2] = z; d[3] = z;
}
__device__ __forceinline__ void gemm3h_chunk(
    const unsigned* Ah, const unsigned* Al,
    const unsigned* Bh, const unsigned* Bl,
    int r0, int q, int oct, float acc[16][4])
{
#pragma unroll
    for (int ks = 0; ks < 4; ks++) {
        const int kw = ks * 8 + q;
        const unsigned ah0 = Ah[r0 * HSTR + kw],     ah1 = Ah[(r0 + 8) * HSTR + kw];
        const unsigned ah2 = Ah[r0 * HSTR + kw + 4], ah3 = Ah[(r0 + 8) * HSTR + kw + 4];
        const unsigned al0 = Al[r0 * HSTR + kw],     al1 = Al[(r0 + 8) * HSTR + kw];
        const unsigned al2 = Al[r0 * HSTR + kw + 4], al3 = Al[(r0 + 8) * HSTR + kw + 4];
#pragma unroll
        for (int nt = 0; nt < 16; nt++) {
            const int cb = (nt * 8 + oct) * HSTR + kw;
            const unsigned bh0 = Bh[cb], bh1 = Bh[cb + 4];
            const unsigned bl0 = Bl[cb], bl1 = Bl[cb + 4];
            mma_f16(acc[nt], ah0, ah1, ah2, ah3, bh0, bh1);
            mma_f16(acc[nt], ah0, ah1, ah2, ah3, bl0, bl1);
            mma_f16(acc[nt], al0, al1, al2, al3, bh0, bh1);
        }
    }
}

/* ===== K1: encoder GEMM + ELU, 3xfp16; epilogue emits all fp16 views ===== */
__global__ __launch_bounds__(256) void k_enc_mma()
{
    extern __shared__ unsigned smu[];
    unsigned* Ah = smu;
    unsigned* Al = smu + 128 * HSTR;
    unsigned* Bh = smu + 2 * 128 * HSTR;
    unsigned* Bl = smu + 3 * 128 * HSTR;
    const int tid = threadIdx.x, lane = tid & 31, w = tid >> 5;
    const int q = lane & 3, oct = lane >> 2;
    const int t0 = blockIdx.x * 128;
    const int nb = blockIdx.y * 128;

    const int row = tid >> 1, h = tid & 1;
    const int ta = t0 + row;
    const bool aval = ta < NT;
    const __half* aH = g_memh + (size_t)(aval ? ta : 0) * NHP;
    const __half* aL = g_meml + (size_t)(aval ? ta : 0) * NHP;
    const __half* bH = g_WTh + (size_t)(nb + row) * NHP;
    const __half* bL = g_WTl + (size_t)(nb + row) * NHP;

    float acc[16][4] = {};
    for (int c = 0; c < 7; c++) {
        const int k0 = c * 64;
        if (aval) { stage64(Ah + row * HSTR, aH + k0, h); stage64(Al + row * HSTR, aL + k0, h); }
        else      { stage64z(Ah + row * HSTR, h);         stage64z(Al + row * HSTR, h); }
        stage64(Bh + row * HSTR, bH + k0, h);
        stage64(Bl + row * HSTR, bL + k0, h);
        __syncthreads();
        gemm3h_chunk(Ah, Al, Bh, Bl, w * 16 + oct, q, oct, acc);
        __syncthreads();
    }

    const int r0 = w * 16 + oct;
#pragma unroll
    for (int rr = 0; rr < 2; rr++) {
        const int t = t0 + r0 + rr * 8;
        if (t >= NT) continue;
#pragma unroll
        for (int nt = 0; nt < 16; nt++) {
            const int c = nt * 8 + q * 2;
            const float v0 = elu1(acc[nt][rr * 2 + 0] + g_biasC[nb + c]);
            const float v1 = elu1(acc[nt][rr * 2 + 1] + g_biasC[nb + c + 1]);
            *(float2*)&g_enc[(size_t)t * ENCW + nb + c] = make_float2(v0, v1);
            __half h0, l0, h1, l1;
            fsplit(v0, h0, l0); fsplit(v1, h1, l1);
            if (nb < 256) {
                const int col = nb + c;
                *(__half2*)&g_enhh[(size_t)t * NEN + col] = __halves2half2(h0, h1);
                *(__half2*)&g_enhl[(size_t)t * NEN + col] = __halves2half2(l0, l1);
            } else if (nb < 512) {
                const int col = nb - 256 + c;
                *(__half2*)&g_enmh[(size_t)t * NEN + col] = __halves2half2(h0, h1);
                *(__half2*)&g_enml[(size_t)t * NEN + col] = __halves2half2(l0, l1);
            } else {
                const int col = nb - 512 + c;
                if (col < 128)
                    *(__half2*)&g_elhh[(size_t)t * NEL + col] = __halves2half2(h0, h1);
                else
                    *(__half2*)&g_elmh[(size_t)t * NEL + col - 128] = __halves2half2(h0, h1);
            }
        }
    }
}

/* ===== K2: tmp = enh @ ba_U, 3xfp16; output stored as hi/lo fp16 ===== */
__global__ __launch_bounds__(256) void k_tmp_mma()
{
    extern __shared__ unsigned smu[];
    unsigned* Ah = smu;
    unsigned* Al = smu + 128 * HSTR;
    unsigned* Bh = smu + 2 * 128 * HSTR;
    unsigned* Bl = smu + 3 * 128 * HSTR;
    const int tid = threadIdx.x, lane = tid & 31, w = tid >> 5;
    const int q = lane & 3, oct = lane >> 2;
    const int t0 = blockIdx.x * 128;
    const int nb = blockIdx.y * 128;

    const int row = tid >> 1, h = tid & 1;
    const int ta = t0 + row;
    const bool aval = ta < NT;
    const __half* aH = g_enhh + (size_t)(aval ? ta : 0) * NEN;
    const __half* aL = g_enhl + (size_t)(aval ? ta : 0) * NEN;
    const __half* bH = g_baUTh + (size_t)(nb + row) * NEN;
    const __half* bL = g_baUTl + (size_t)(nb + row) * NEN;

    float acc[16][4] = {};
    for (int c = 0; c < 4; c++) {
        const int k0 = c * 64;
        if (aval) { stage64(Ah + row * HSTR, aH + k0, h); stage64(Al + row * HSTR, aL + k0, h); }
        else      { stage64z(Ah + row * HSTR, h);         stage64z(Al + row * HSTR, h); }
        stage64(Bh + row * HSTR, bH + k0, h);
        stage64(Bl + row * HSTR, bL + k0, h);
        __syncthreads();
        gemm3h_chunk(Ah, Al, Bh, Bl, w * 16 + oct, q, oct, acc);
        __syncthreads();
    }

    const int r0 = w * 16 + oct;
#pragma unroll
    for (int rr = 0; rr < 2; rr++) {
        const int t = t0 + r0 + rr * 8;
        if (t >= NT) continue;
#pragma unroll
        for (int nt = 0; nt < 16; nt++) {
            const int c = nt * 8 + q * 2;
            __half h0, l0, h1, l1;
            fsplit(acc[nt][rr * 2 + 0], h0, l0);
            fsplit(acc[nt][rr * 2 + 1], h1, l1);
            *(__half2*)&g_tmph[(size_t)t * NEN + nb + c] = __halves2half2(h0, h1);
            *(__half2*)&g_tmpl[(size_t)t * NEN + nb + c] = __halves2half2(l0, l1);
        }
    }
}

/* ===== K3: node scores S[b,h,m], 3xfp16 ===== */
__global__ __launch_bounds__(256) void k_ns_mma(const float* __restrict__ bab)
{
    extern __shared__ unsigned smu[];
    unsigned* Ah = smu;
    unsigned* Al = smu + 128 * HSTR;
    unsigned* Bh = smu + 2 * 128 * HSTR;
    unsigned* Bl = smu + 3 * 128 * HSTR;
    const int tid = threadIdx.x, lane = tid & 31, w = tid >> 5;
    const int q = lane & 3, oct = lane >> 2;
    const int b = blockIdx.z;
    const int h0 = blockIdx.x * 128, m0 = blockIdx.y * 128;

    const int row = tid >> 1, h = tid & 1;
    int hr = h0 + row; if (hr > 512) hr = 512;
    int mr = m0 + row; if (mr > 512) mr = 512;
    const __half* aH = g_tmph + (size_t)(b * L1 + hr) * NEN;
    const __half* aL = g_tmpl + (size_t)(b * L1 + hr) * NEN;
    const __half* bH = g_enmh + (size_t)(b * L1 + mr) * NEN;
    const __half* bL = g_enml + (size_t)(b * L1 + mr) * NEN;

    float acc[16][4] = {};
    for (int c = 0; c < 4; c++) {
        const int k0 = c * 64;
        stage64(Ah + row * HSTR, aH + k0, h);
        stage64(Al + row * HSTR, aL + k0, h);
        stage64(Bh + row * HSTR, bH + k0, h);
        stage64(Bl + row * HSTR, bL + k0, h);
        __syncthreads();
        gemm3h_chunk(Ah, Al, Bh, Bl, w * 16 + oct, q, oct, acc);
        __syncthreads();
    }

    const int r0 = w * 16 + oct;
    const int hA = h0 + r0, hB = hA + 8;
    const float bb0 = __ldg(bab);
    const float dhA = (hA <= 512) ? g_dh[b * L1 + hA] : 0.f;
    const float dhB = (hB <= 512) ? g_dh[b * L1 + hB] : 0.f;
    float* Sb = g_S + (size_t)b * L1 * L1;
#pragma unroll
    for (int nt = 0; nt < 16; nt++) {
        const int m = m0 + nt * 8 + q * 2;
        if (m <= 512) {
            const float em0 = g_em[b * L1 + m];
            if (hA <= 512) Sb[(size_t)hA * L1 + m] = acc[nt][0] + dhA + em0 + bb0;
            if (hB <= 512) Sb[(size_t)hB * L1 + m] = acc[nt][2] + dhB + em0 + bb0;
        }
        if (m + 1 <= 512) {
            const float em1 = g_em[b * L1 + m + 1];
            if (hA <= 512) Sb[(size_t)hA * L1 + m + 1] = acc[nt][1] + dhA + em1 + bb0;
            if (hB <= 512) Sb[(size_t)hB * L1 + m + 1] = acc[nt][3] + dhB + em1 + bb0;
        }
    }
}

/* ============ K2b: dh = enh . ba_Wd, em = enm . ba_We ============ */
__global__ __launch_bounds__(256) void k_dotvec(
    const float* __restrict__ Wd, const float* __restrict__ We)
{
    const int gw = (blockIdx.x * blockDim.x + threadIdx.x) >> 5;
    const int lane = threadIdx.x & 31;
    if (gw >= NT) return;
    const float* r = g_enc + (size_t)gw * ENCW;
    float s1 = 0.f, s2 = 0.f;
#pragma unroll
    for (int k = lane; k < NEN; k += 32) {
        s1 += r[k] * Wd[k];
        s2 += r[256 + k] * We[k];
    }
#pragma unroll
    for (int o = 16; o; o >>= 1) {
        s1 += __shfl_xor_sync(0xffffffffu, s1, o);
        s2 += __shfl_xor_sync(0xffffffffu, s2, o);
    }
    if (!lane) { g_dh[gw] = s1; g_em[gw] = s2; }
}

/* ==== K4: per-column logsumexp + gold pick + decode argmax ==== */
__global__ __launch_bounds__(256) void k_node_reduce(
    const int* __restrict__ eheads, const int* __restrict__ mask,
    float* __restrict__ out)
{
    const int b = blockIdx.y;
    const int m0 = blockIdx.x * 32;
    const int tid = threadIdx.x, lane = tid & 31, w = tid >> 5;
    __shared__ int mk[L1];
    __shared__ float s_max[8][32], s_sum[8][32], s_bv[8][32];
    __shared__ int s_bi[8][32];
    for (int i = tid; i < L1; i += 256) mk[i] = (i == 0) ? 0 : mask[b * NL + i - 1];
    __syncthreads();

    const int m = m0 + lane;
    const bool mv = m < L1;
    const int msafe = mv ? m : (L1 - 1);
    const int mm_ = mk[msafe];
    const float* Sb = g_S + (size_t)b * L1 * L1;

    float rmax = -1e30f, rsum = 0.f, bv = -1e30f;
    int bi = 0x7fffffff;
    for (int h = w; h < L1; h += 8) {
        float s = Sb[(size_t)h * L1 + msafe];
        int mh = mk[h];
        float x = s + logmask(mh + mm_);
        if (x > rmax) { rsum = rsum * expf(rmax - x) + 1.f; rmax = x; }
        else            rsum += expf(x - rmax);
        float dv = s + (1.f - (float)mh) * (-1e8f);
        if (h != msafe && dv > bv) { bv = dv; bi = h; }
    }
    s_max[w][lane] = rmax; s_sum[w][lane] = rsum;
    s_bv[w][lane] = bv;    s_bi[w][lane] = bi;
    __syncthreads();

    if (w == 0) {
        float tm = -1e30f;
#pragma unroll
        for (int i = 0; i < 8; i++) tm = fmaxf(tm, s_max[i][lane]);
        float ts = 0.f;
#pragma unroll
        for (int i = 0; i < 8; i++) ts += s_sum[i][lane] * expf(s_max[i][lane] - tm);
        float lse = tm + logf(ts);
        int gh = (msafe == 0) ? 0 : eheads[b * NL + msafe - 1];
        float xg = Sb[(size_t)gh * L1 + msafe] + logmask(mk[gh] + mm_);
        float bbv = -1e30f; int bbi = 0x7fffffff;
#pragma unroll
        for (int i = 0; i < 8; i++) {
            float v = s_bv[i][lane]; int ix = s_bi[i][lane];
            if (v > bbv || (v == bbv && ix < bbi)) { bbv = v; bbi = ix; }
        }
        float contrib = 0.f;
        if (mv) {
            g_pred[b * L1 + m] = bbi;
            if (m >= 1) {
                out[OUT_PH + (size_t)b * NL + m - 1] = (float)bbi;
                contrib = -(xg - lse);
            }
        }
#pragma unroll
        for (int o = 16; o; o >>= 1) contrib += __shfl_xor_sync(0xffffffffu, contrib, o);
        if (lane == 0) g_partA[blockIdx.y * 17 + blockIdx.x] = contrib;
    }
}

/* ===== K5: label bilinear, fp16 m16n8k16, 16 labels per CTA ===== */
#define NBL  16
#define SW   68
#define W_AS 0
#define W_GS 8704
#define W_PS 17408
#define W_B0 26112
#define W_WL 43520
#define W_WB 45568
#define SMB2_BYTES ((45568 + 256) * 4)

__global__ __launch_bounds__(256) void k_bilin_mma(
    const float* __restrict__ Wl, const int* __restrict__ eheads)
{
    extern __shared__ unsigned smu[];
    float* Wls = (float*)(smu + W_WL);
    float* wb  = (float*)(smu + W_WB);
    const int tid = threadIdx.x, lane = tid & 31, w = tid >> 5;
    const int q = lane & 3, oct = lane >> 2;
    const int nb0 = blockIdx.y * NBL;
    const int t0 = blockIdx.x * 128;

    const int row = tid >> 1, h = tid & 1;
    const int ts = t0 + row;
    const bool tv = ts < NT;
    const int tc = tv ? ts : 0;

    {
        unsigned* dst = smu + W_AS + row * SW + h * 32;
        if (tv) {
            const uint4* src = (const uint4*)(g_elmh + (size_t)tc * NEL + h * 64);
#pragma unroll
            for (int j = 0; j < 8; j++) *(uint4*)(dst + 4 * j) = src[j];
        } else {
            uint4 z = make_uint4(0, 0, 0, 0);
#pragma unroll
            for (int j = 0; j < 8; j++) *(uint4*)(dst + 4 * j) = z;
        }
    }
    {
        const int bb = tc / L1, ll = tc - bb * L1;
        const int hr = h ? g_pred[tc] : ((ll == 0) ? 0 : eheads[bb * NL + ll - 1]);
        const uint4* src = (const uint4*)(g_elhh + (size_t)(bb * L1 + hr) * NEL);
        unsigned* dst = smu + (h ? W_PS : W_GS) + row * SW;
#pragma unroll
        for (int j = 0; j < 16; j++) *(uint4*)(dst + 4 * j) = src[j];
    }
    for (int idx = tid; idx < NBL * 128; idx += 256)
        Wls[idx] = Wl[nb0 * 128 + idx];
    {
        const uint4* src = (const uint4*)(g_Uh + ((size_t)nb0 * NEL + row) * NEL + h * 64);
        unsigned* dst = smu + W_B0 + row * SW + h * 32;
#pragma unroll
        for (int j = 0; j < 8; j++) *(uint4*)(dst + 4 * j) = src[j];
    }
    __syncthreads();

    const int r0 = w * 16 + oct;
    const unsigned* As = smu + W_AS;
    const unsigned* Gs = smu + W_GS;
    const unsigned* Ps = smu + W_PS;

    for (int i = 0; i < NBL; i++) {
        uint4 pf[8];
        if (i + 1 < NBL) {
            const uint4* src = (const uint4*)(g_Uh + ((size_t)(nb0 + i + 1) * NEL + row) * NEL + h * 64);
#pragma unroll
            for (int j = 0; j < 8; j++) pf[j] = src[j];
        }
        const unsigned* Bs = smu + W_B0 + (i & 1) * 8704;

        float acc[16][4] = {};
#pragma unroll
        for (int ks = 0; ks < 8; ks++) {
            const int kw = ks * 8 + q;
            const unsigned a0 = As[r0 * SW + kw],     a1 = As[(r0 + 8) * SW + kw];
            const unsigned a2 = As[r0 * SW + kw + 4], a3 = As[(r0 + 8) * SW + kw + 4];
#pragma unroll
            for (int nt = 0; nt < 16; nt++) {
                const int cb = (nt * 8 + oct) * SW + kw;
                mma_f16(acc[nt], a0, a1, a2, a3, Bs[cb], Bs[cb + 4]);
            }
        }

        const float* Wln = Wls + i * 128;
        float sg0 = 0.f, sp0 = 0.f, sg1 = 0.f, sp1 = 0.f;
#pragma unroll
        for (int nt = 0; nt < 16; nt++) {
            const int ch = nt * 8 + 2 * q;
            const int cw = nt * 4 + q;
            const float w0 = Wln[ch], w1 = Wln[ch + 1];
            const float d00 = acc[nt][0] + w0, d01 = acc[nt][1] + w1;
            const float d10 = acc[nt][2] + w0, d11 = acc[nt][3] + w1;
            unsigned ug0 = Gs[r0 * SW + cw], ug1 = Gs[(r0 + 8) * SW + cw];
            unsigned up0 = Ps[r0 * SW + cw], up1 = Ps[(r0 + 8) * SW + cw];
            float2 g0 = __half22float2(*(__half2*)&ug0);
            float2 g1 = __half22float2(*(__half2*)&ug1);
            float2 p0 = __half22float2(*(__half2*)&up0);
            float2 p1 = __half22float2(*(__half2*)&up1);
            sg0 += d00 * g0.x + d01 * g0.y;  sp0 += d00 * p0.x + d01 * p0.y;
            sg1 += d10 * g1.x + d11 * g1.y;  sp1 += d10 * p1.x + d11 * p1.y;
        }
#pragma unroll
        for (int o = 1; o <= 2; o <<= 1) {
            sg0 += __shfl_xor_sync(0xffffffffu, sg0, o);
            sp0 += __shfl_xor_sync(0xffffffffu, sp0, o);
            sg1 += __shfl_xor_sync(0xffffffffu, sg1, o);
            sp1 += __shfl_xor_sync(0xffffffffu, sp1, o);
        }
        if (q == 0) {
            wb[w * 32 + oct * 2 + 0] = sg0;
            wb[w * 32 + oct * 2 + 1] = sp0;
            wb[w * 32 + (oct + 8) * 2 + 0] = sg1;
            wb[w * 32 + (oct + 8) * 2 + 1] = sp1;
        }
        __syncwarp();
        {
            const int rr = lane & 15;
            const int t = t0 + w * 16 + rr;
            const size_t n = (size_t)(nb0 + i);
            if (t < NT) {
                if (lane < 16) g_sg[n * NT + t] = wb[w * 32 + rr * 2];
                else           g_sp[n * NT + t] = wb[w * 32 + rr * 2 + 1];
            }
        }
        __syncwarp();

        if (i + 1 < NBL) {
            unsigned* dst = smu + W_B0 + ((i + 1) & 1) * 8704 + row * SW + h * 32;
#pragma unroll
            for (int j = 0; j < 8; j++) *(uint4*)(dst + 4 * j) = pf[j];
        }
        __syncthreads();
    }
}

/* ===== K5b: lin[n,t] = elm[t] . Wr[n] + lbl_b[n] ===== */
__global__ __launch_bounds__(256) void k_lin(
    const float* __restrict__ Wr, const float* __restrict__ lb)
{
    __shared__ float As[16][64];
    __shared__ float Bs[16][64];
    const int tid = threadIdx.x;
    const int t0 = blockIdx.x * 64, n0 = blockIdx.y * 64;
    const int ar = tid >> 2, ac = (tid & 3) * 4;
    const float* arow = g_enc + (size_t)(t0 + ar) * ENCW + 640;
    const float* brow = Wr + (size_t)(n0 + ar) * NEL;
    const int ty = tid >> 4, tx = tid & 15;
    float acc[4][4] = {};
    for (int k0 = 0; k0 < NEL; k0 += 16) {
        float4 av = *(const float4*)(arow + k0 + ac);
        float4 bv = *(const float4*)(brow + k0 + ac);
        As[ac + 0][ar] = av.x; As[ac + 1][ar] = av.y;
        As[ac + 2][ar] = av.z; As[ac + 3][ar] = av.w;
        Bs[ac + 0][ar] = bv.x; Bs[ac + 1][ar] = bv.y;
        Bs[ac + 2][ar] = bv.z; Bs[ac + 3][ar] = bv.w;
        __syncthreads();
#pragma unroll
        for (int k = 0; k < 16; k++) {
            float a[4], bb[4];
#pragma unroll
            for (int i = 0; i < 4; i++) a[i]  = As[k][ty * 4 + i];
#pragma unroll
            for (int j = 0; j < 4; j++) bb[j] = Bs[k][tx * 4 + j];
#pragma unroll
            for (int i = 0; i < 4; i++)
#pragma unroll
                for (int j = 0; j < 4; j++) acc[i][j] += a[i] * bb[j];
        }
        __syncthreads();
    }
#pragma unroll
    for (int i = 0; i < 4; i++) {
        int t = t0 + ty * 4 + i;
#pragma unroll
        for (int j = 0; j < 4; j++) {
            int nn = n0 + tx * 4 + j;
            g_lin[(size_t)nn * NT + t] = acc[i][j] + lb[nn];
        }
    }
}

/* ===== K6: label log-softmax over n + max over n ===== */
__global__ __launch_bounds__(256) void k_lbl_reduce(
    const int* __restrict__ elabels, float* __restrict__ out)
{
    __shared__ float red[256];
    const int t = blockIdx.x * 256 + threadIdx.x;
    float contrib = 0.f;
    if (t < NT) {
        int b = t / L1, l = t % L1;
        int lab = (l == 0) ? 0 : elabels[b * NL + l - 1];
        float mg = -1e30f, sg = 0.f, mp = -1e30f, xlab = 0.f;
        for (int n = 0; n < NLB; n++) {
            float lin = g_lin[(size_t)n * NT + t];
            float xg = g_sg[(size_t)n * NT + t] + lin;
            float xp = g_sp[(size_t)n * NT + t] + lin;
            if (n == lab) xlab = xg;
            if (xg > mg) { sg = sg * expf(mg - xg) + 1.f; mg = xg; }
            else           sg += expf(xg - mg);
            mp = fmaxf(mp, xp);
        }
        float ll = xlab - (mg + logf(sg));
        if (l >= 1) {
            contrib = -ll;
            out[OUT_PL + (size_t)b * NL + l - 1] = mp;
        }
    }
    red[threadIdx.x] = contrib;
    __syncthreads();
    for (int s = 128; s; s >>= 1) {
        if (threadIdx.x < s) red[threadIdx.x] += red[threadIdx.x + s];
        __syncthreads();
    }
    if (!threadIdx.x) g_partB[blockIdx.x] = red[0];
}

/* ===== K7: labels1 output + deterministic NLL finalize ===== */
__global__ __launch_bounds__(256) void k_final(
    const int* __restrict__ elabels, float* __restrict__ out)
{
    const int i = blockIdx.x * 256 + threadIdx.x;
    if (i < NT) {
        int b = i / L1, l = i % L1;
        out[OUT_LB + i] = (l == 0) ? 0.f : (float)elabels[b * NL + l - 1];
    }
    if (i == 0) {
        float s = 0.f;
        for (int k = 0; k < 17 * 64; k++) s += g_partA[k];
        out[OUT_NN] = s;
        float s2 = 0.f;
        for (int k = 0; k < 129; k++) s2 += g_partB[k];
        out[OUT_LN] = s2;
    }
}

extern "C" void kernel_launch(void* const* d_in, const int* in_sizes, int n_in,
                              void* d_out, int out_size)
{
    const float* mem    = (const float*)d_in[0];
    const int*   eheads = (const int*)d_in[1];
    const int*   elabs  = (const int*)d_in[2];
    const int*   mask   = (const int*)d_in[4];
    const float* sent   = (const float*)d_in[5];
    const float* Wenh = (const float*)d_in[6];  const float* benh = (const float*)d_in[7];
    const float* Wenm = (const float*)d_in[8];  const float* benm = (const float*)d_in[9];
    const float* Welh = (const float*)d_in[10]; const float* belh = (const float*)d_in[11];
    const float* Welm = (const float*)d_in[12]; const float* belm = (const float*)d_in[13];
    const float* baU  = (const float*)d_in[14];
    const float* baWd = (const float*)d_in[15];
    const float* baWe = (const float*)d_in[16];
    const float* bab  = (const float*)d_in[17];
    const float* lU   = (const float*)d_in[18];
    const float* lWl  = (const float*)d_in[19];
    const float* lWr  = (const float*)d_in[20];
    const float* lb   = (const float*)d_in[21];
    float* out = (float*)d_out;

    cudaFuncSetAttribute(k_bilin_mma, cudaFuncAttributeMaxDynamicSharedMemorySize, SMB2_BYTES);
    cudaFuncSetAttribute(k_enc_mma, cudaFuncAttributeMaxDynamicSharedMemorySize, SME2_BYTES);
    cudaFuncSetAttribute(k_tmp_mma, cudaFuncAttributeMaxDynamicSharedMemorySize, SME2_BYTES);
    cudaFuncSetAttribute(k_ns_mma,  cudaFuncAttributeMaxDynamicSharedMemorySize, SME2_BYTES);

    k_trans<<<1600, 256>>>(Wenh, Wenm, Welh, Welm, benh, benm, belh, belm, baU);
    k_uh<<<2048, 256>>>(lU);
    k_msplit<<<57456, 256>>>(mem, sent);
    k_enc_mma<<<dim3(257, 6), 256, SME2_BYTES>>>();
    k_tmp_mma<<<dim3(257, 2), 256, SME2_BYTES>>>();
    k_dotvec<<<4104, 256>>>(baWd, baWe);
    k_ns_mma<<<dim3(5, 5, 64), 256, SME2_BYTES>>>(bab);
    k_node_reduce<<<dim3(17, 64), 256>>>(eheads, mask, out);
    k_lin<<<dim3(513, 2), 256>>>(lWr, lb);
    k_bilin_mma<<<dim3(NTILES, 8), 256, SMB2_BYTES>>>(lWl, eheads);
    k_lbl_reduce<<<129, 256>>>(elabs, out);
    k_final<<<129, 256>>>(elabs, out);
}

// round 8
// speedup vs baseline: 4.1629x; 1.0352x over previous
#include <cuda_runtime.h>
#include <cuda_fp16.h>

#define NB   64
#define NL   512
#define NH   400
#define NHP  448            /* NH padded to 64 multiple */
#define NEN  256
#define NEL  128
#define NLB  128
#define L1   513
#define NT   (NB * L1)      /* 32832 */
#define ENCW 768
#define NTILES 257

/* output layout (flattened tuple, float32) */
#define OUT_PH 0
#define OUT_PL 32768
#define OUT_LB 65536
#define OUT_NN 98368
#define OUT_LN 98369

/* -------- scratch (device globals) -------- */
__device__ float  g_enc[(size_t)NT * ENCW];
__device__ float  g_dh[NT];
__device__ float  g_em[NT];
__device__ float  g_S[(size_t)NB * L1 * L1];
__device__ int    g_pred[NT];
__device__ float  g_sg[(size_t)NLB * NT];
__device__ float  g_sp[(size_t)NLB * NT];
__device__ float  g_lin[(size_t)NLB * NT];
__device__ float  g_partA[17 * 64];
__device__ float  g_partB[129];
__device__ float  g_biasC[768];
__device__ __half g_memh[(size_t)NT * NHP];
__device__ __half g_meml[(size_t)NT * NHP];
__device__ __half g_WTh[768 * NHP];
__device__ __half g_WTl[768 * NHP];
__device__ __half g_baUTh[NEN * NEN];
__device__ __half g_baUTl[NEN * NEN];
__device__ __half g_enhh[(size_t)NT * NEN];
__device__ __half g_enhl[(size_t)NT * NEN];
__device__ __half g_enmh[(size_t)NT * NEN];
__device__ __half g_enml[(size_t)NT * NEN];
__device__ __half g_tmph[(size_t)NT * NEN];
__device__ __half g_tmpl[(size_t)NT * NEN];
__device__ __half g_Uh[(size_t)NLB * NEL * NEL];
__device__ __half g_elhh[(size_t)NT * NEL];
__device__ __half g_elmh[(size_t)NT * NEL];

__device__ __forceinline__ float elu1(float x) { return x > 0.f ? x : expm1f(x); }
__device__ __forceinline__ float logmask(int s) {
    return s == 0 ? -103.27893f : (s == 1 ? 0.f : 0.69314718f);
}
__device__ __forceinline__ void fsplit(float v, __half& h, __half& l) {
    h = __float2half_rn(v);
    l = __float2half_rn(v - __half2float(h));
}
__device__ __forceinline__ void mma_f16(float* c, unsigned a0, unsigned a1,
                                        unsigned a2, unsigned a3,
                                        unsigned b0, unsigned b1) {
    asm volatile(
        "mma.sync.aligned.m16n8k16.row.col.f32.f16.f16.f32 "
        "{%0,%1,%2,%3}, {%4,%5,%6,%7}, {%8,%9}, {%0,%1,%2,%3};\n"
        : "+f"(c[0]), "+f"(c[1]), "+f"(c[2]), "+f"(c[3])
        : "r"(a0), "r"(a1), "r"(a2), "r"(a3), "r"(b0), "r"(b1));
}
__device__ __forceinline__ unsigned smem_u32(const void* p) {
    unsigned a;
    asm("{ .reg .u64 t; cvta.to.shared.u64 t, %1; cvt.u32.u64 %0, t; }" : "=r"(a) : "l"(p));
    return a;
}
__device__ __forceinline__ void cpa16(unsigned dst, const void* src) {
    asm volatile("cp.async.cg.shared.global [%0], [%1], 16;" :: "r"(dst), "l"(src));
}
#define CP_COMMIT() asm volatile("cp.async.commit_group;" ::: "memory")
#define CP_WAIT1()  asm volatile("cp.async.wait_group 1;"  ::: "memory")
#define CP_WAIT0()  asm volatile("cp.async.wait_group 0;"  ::: "memory")

/* ===== K0a: weight transposes + fp16 hi/lo split ===== */
__global__ __launch_bounds__(256) void k_trans(
    const float* __restrict__ Wenh, const float* __restrict__ Wenm,
    const float* __restrict__ Welh, const float* __restrict__ Welm,
    const float* __restrict__ benh, const float* __restrict__ benm,
    const float* __restrict__ belh, const float* __restrict__ belm,
    const float* __restrict__ baU)
{
    const int i = blockIdx.x * 256 + threadIdx.x;
    if (i < 768 * NHP) {
        const int k = i / 768, j = i % 768;
        float v = 0.f;
        if (k < NH) {
            if (j < 256)      v = Wenh[k * NEN + j];
            else if (j < 512) v = Wenm[k * NEN + j - 256];
            else if (j < 640) v = Welh[k * NEL + j - 512];
            else              v = Welm[k * NEL + j - 640];
        }
        __half h, l; fsplit(v, h, l);
        g_WTh[(size_t)j * NHP + k] = h;
        g_WTl[(size_t)j * NHP + k] = l;
        if (k == 0)
            g_biasC[j] = (j < 256) ? benh[j] : (j < 512) ? benm[j - 256]
                       : (j < 640) ? belh[j - 512] : belm[j - 640];
    } else {
        const int i2 = i - 768 * NHP;
        if (i2 < NEN * NEN) {
            const int k = i2 / NEN, n = i2 % NEN;
            __half h, l; fsplit(baU[k * NEN + n], h, l);
            g_baUTh[n * NEN + k] = h;
            g_baUTl[n * NEN + k] = l;
        }
    }
}

/* ===== K0b: lbl_U -> fp16 ===== */
__global__ __launch_bounds__(256) void k_uh(const float* __restrict__ U)
{
    const size_t base = ((size_t)blockIdx.x * 256 + threadIdx.x) * 4;
    float4 v = *(const float4*)(U + base);
    __half2 h0 = __floats2half2_rn(v.x, v.y);
    __half2 h1 = __floats2half2_rn(v.z, v.w);
    uint2 wv; wv.x = *(unsigned*)&h0; wv.y = *(unsigned*)&h1;
    *(uint2*)&g_Uh[base] = wv;
}

/* ===== K0c: [sentinel;mem] -> fp16 hi/lo ===== */
__global__ __launch_bounds__(256) void k_msplit(
    const float* __restrict__ mem, const float* __restrict__ sent)
{
    const size_t idx = (size_t)blockIdx.x * 256 + threadIdx.x;
    const int t = (int)(idx / NHP), k = (int)(idx % NHP);
    const int b = t / L1, l = t - b * L1;
    float v = 0.f;
    if (k < NH) v = (l == 0) ? sent[k] : mem[((size_t)b * NL + (l - 1)) * NH + k];
    __half h, lo; fsplit(v, h, lo);
    g_memh[idx] = h; g_meml[idx] = lo;
}

/* ===== pipelined 3xfp16 GEMM pieces: 128x128 tile, K-chunk 32, 2 bufs =====
   buffer: 4 arrays (Ah|Al|Bh|Bl), each 128 rows x 20 words (16 data + 4 pad)
   buffer bytes = 4*128*80 = 40960; two buffers = 81920                    */
#define HSTR2 20
#define ABYTES 10240
#define BUFBYTES 40960
#define SME3_BYTES (2 * BUFBYTES)

__device__ __forceinline__ void stage_async(
    unsigned sb, int buf, int row, int h,
    const __half* aH, const __half* aL,
    const __half* bH, const __half* bL, int k0)
{
    const unsigned d = sb + buf * BUFBYTES + row * 80 + h * 32;
    const __half* s;
    s = aH + k0 + h * 16;
    cpa16(d, s); cpa16(d + 16, s + 8);
    s = aL + k0 + h * 16;
    cpa16(d + ABYTES, s); cpa16(d + ABYTES + 16, s + 8);
    s = bH + k0 + h * 16;
    cpa16(d + 2 * ABYTES, s); cpa16(d + 2 * ABYTES + 16, s + 8);
    s = bL + k0 + h * 16;
    cpa16(d + 3 * ABYTES, s); cpa16(d + 3 * ABYTES + 16, s + 8);
}

__device__ __forceinline__ void gemm3h_chunk32(
    const unsigned* base, int r0, int q, int oct, float acc[16][4])
{
    const unsigned* Ah = base;
    const unsigned* Al = base + ABYTES / 4;
    const unsigned* Bh = base + 2 * (ABYTES / 4);
    const unsigned* Bl = base + 3 * (ABYTES / 4);
#pragma unroll
    for (int ks = 0; ks < 2; ks++) {
        const int kw = ks * 8 + q;
        const unsigned ah0 = Ah[r0 * HSTR2 + kw],     ah1 = Ah[(r0 + 8) * HSTR2 + kw];
        const unsigned ah2 = Ah[r0 * HSTR2 + kw + 4], ah3 = Ah[(r0 + 8) * HSTR2 + kw + 4];
        const unsigned al0 = Al[r0 * HSTR2 + kw],     al1 = Al[(r0 + 8) * HSTR2 + kw];
        const unsigned al2 = Al[r0 * HSTR2 + kw + 4], al3 = Al[(r0 + 8) * HSTR2 + kw + 4];
#pragma unroll
        for (int nt = 0; nt < 16; nt++) {
            const int cb = (nt * 8 + oct) * HSTR2 + kw;
            const unsigned bh0 = Bh[cb], bh1 = Bh[cb + 4];
            const unsigned bl0 = Bl[cb], bl1 = Bl[cb + 4];
            mma_f16(acc[nt], ah0, ah1, ah2, ah3, bh0, bh1);
            mma_f16(acc[nt], ah0, ah1, ah2, ah3, bl0, bl1);
            mma_f16(acc[nt], al0, al1, al2, al3, bh0, bh1);
        }
    }
}

/* ===== K1: encoder GEMM + ELU, pipelined 3xfp16 ===== */
__global__ __launch_bounds__(256) void k_enc_mma()
{
    extern __shared__ unsigned smu[];
    const unsigned sb = smem_u32(smu);
    const int tid = threadIdx.x, lane = tid & 31, w = tid >> 5;
    const int q = lane & 3, oct = lane >> 2;
    const int t0 = blockIdx.x * 128;
    const int nb = blockIdx.y * 128;
    const int row = tid >> 1, h = tid & 1;
    const int ta = t0 + row;
    const bool aval = ta < NT;
    const __half* aH = g_memh + (size_t)(aval ? ta : 0) * NHP;
    const __half* aL = g_meml + (size_t)(aval ? ta : 0) * NHP;
    const __half* bH = g_WTh + (size_t)(nb + row) * NHP;
    const __half* bL = g_WTl + (size_t)(nb + row) * NHP;

    float acc[16][4] = {};
    stage_async(sb, 0, row, h, aH, aL, bH, bL, 0);
    CP_COMMIT();
    for (int c = 0; c < 14; c++) {
        if (c + 1 < 14) {
            stage_async(sb, (c + 1) & 1, row, h, aH, aL, bH, bL, (c + 1) * 32);
            CP_COMMIT();
            CP_WAIT1();
        } else CP_WAIT0();
        __syncthreads();
        gemm3h_chunk32(smu + (c & 1) * (BUFBYTES / 4), w * 16 + oct, q, oct, acc);
        __syncthreads();
    }

    const int r0 = w * 16 + oct;
#pragma unroll
    for (int rr = 0; rr < 2; rr++) {
        const int t = t0 + r0 + rr * 8;
        if (t >= NT) continue;
#pragma unroll
        for (int nt = 0; nt < 16; nt++) {
            const int c = nt * 8 + q * 2;
            const float v0 = elu1(acc[nt][rr * 2 + 0] + g_biasC[nb + c]);
            const float v1 = elu1(acc[nt][rr * 2 + 1] + g_biasC[nb + c + 1]);
            if (nb != 512)                              /* elh fp32 unused */
                *(float2*)&g_enc[(size_t)t * ENCW + nb + c] = make_float2(v0, v1);
            __half h0, l0, h1, l1;
            fsplit(v0, h0, l0); fsplit(v1, h1, l1);
            if (nb < 256) {
                const int col = nb + c;
                *(__half2*)&g_enhh[(size_t)t * NEN + col] = __halves2half2(h0, h1);
                *(__half2*)&g_enhl[(size_t)t * NEN + col] = __halves2half2(l0, l1);
            } else if (nb < 512) {
                const int col = nb - 256 + c;
                *(__half2*)&g_enmh[(size_t)t * NEN + col] = __halves2half2(h0, h1);
                *(__half2*)&g_enml[(size_t)t * NEN + col] = __halves2half2(l0, l1);
            } else {
                const int col = nb - 512 + c;
                if (col < 128)
                    *(__half2*)&g_elhh[(size_t)t * NEL + col] = __halves2half2(h0, h1);
                else
                    *(__half2*)&g_elmh[(size_t)t * NEL + col - 128] = __halves2half2(h0, h1);
            }
        }
    }
}

/* ===== K2: tmp = enh @ ba_U, pipelined 3xfp16 ===== */
__global__ __launch_bounds__(256) void k_tmp_mma()
{
    extern __shared__ unsigned smu[];
    const unsigned sb = smem_u32(smu);
    const int tid = threadIdx.x, lane = tid & 31, w = tid >> 5;
    const int q = lane & 3, oct = lane >> 2;
    const int t0 = blockIdx.x * 128;
    const int nb = blockIdx.y * 128;
    const int row = tid >> 1, h = tid & 1;
    const int ta = t0 + row;
    const bool aval = ta < NT;
    const __half* aH = g_enhh + (size_t)(aval ? ta : 0) * NEN;
    const __half* aL = g_enhl + (size_t)(aval ? ta : 0) * NEN;
    const __half* bH = g_baUTh + (size_t)(nb + row) * NEN;
    const __half* bL = g_baUTl + (size_t)(nb + row) * NEN;

    float acc[16][4] = {};
    stage_async(sb, 0, row, h, aH, aL, bH, bL, 0);
    CP_COMMIT();
    for (int c = 0; c < 8; c++) {
        if (c + 1 < 8) {
            stage_async(sb, (c + 1) & 1, row, h, aH, aL, bH, bL, (c + 1) * 32);
            CP_COMMIT();
            CP_WAIT1();
        } else CP_WAIT0();
        __syncthreads();
        gemm3h_chunk32(smu + (c & 1) * (BUFBYTES / 4), w * 16 + oct, q, oct, acc);
        __syncthreads();
    }

    const int r0 = w * 16 + oct;
#pragma unroll
    for (int rr = 0; rr < 2; rr++) {
        const int t = t0 + r0 + rr * 8;
        if (t >= NT) continue;
#pragma unroll
        for (int nt = 0; nt < 16; nt++) {
            const int c = nt * 8 + q * 2;
            __half h0, l0, h1, l1;
            fsplit(acc[nt][rr * 2 + 0], h0, l0);
            fsplit(acc[nt][rr * 2 + 1], h1, l1);
            *(__half2*)&g_tmph[(size_t)t * NEN + nb + c] = __halves2half2(h0, h1);
            *(__half2*)&g_tmpl[(size_t)t * NEN + nb + c] = __halves2half2(l0, l1);
        }
    }
}

/* ===== K3: node scores S[b,h,m] for h,m < 512, pipelined 3xfp16 ===== */
__global__ __launch_bounds__(256) void k_ns_mma(const float* __restrict__ bab)
{
    extern __shared__ unsigned smu[];
    const unsigned sb = smem_u32(smu);
    const int tid = threadIdx.x, lane = tid & 31, w = tid >> 5;
    const int q = lane & 3, oct = lane >> 2;
    const int b = blockIdx.z;
    const int h0 = blockIdx.x * 128, m0 = blockIdx.y * 128;
    const int row = tid >> 1, h = tid & 1;
    const __half* aH = g_tmph + (size_t)(b * L1 + h0 + row) * NEN;
    const __half* aL = g_tmpl + (size_t)(b * L1 + h0 + row) * NEN;
    const __half* bH = g_enmh + (size_t)(b * L1 + m0 + row) * NEN;
    const __half* bL = g_enml + (size_t)(b * L1 + m0 + row) * NEN;

    float acc[16][4] = {};
    stage_async(sb, 0, row, h, aH, aL, bH, bL, 0);
    CP_COMMIT();
    for (int c = 0; c < 8; c++) {
        if (c + 1 < 8) {
            stage_async(sb, (c + 1) & 1, row, h, aH, aL, bH, bL, (c + 1) * 32);
            CP_COMMIT();
            CP_WAIT1();
        } else CP_WAIT0();
        __syncthreads();
        gemm3h_chunk32(smu + (c & 1) * (BUFBYTES / 4), w * 16 + oct, q, oct, acc);
        __syncthreads();
    }

    const int r0 = w * 16 + oct;
    const int hA = h0 + r0, hB = hA + 8;
    const float bb0 = __ldg(bab);
    const float dhA = g_dh[b * L1 + hA];
    const float dhB = g_dh[b * L1 + hB];
    float* Sb = g_S + (size_t)b * L1 * L1;
#pragma unroll
    for (int nt = 0; nt < 16; nt++) {
        const int m = m0 + nt * 8 + q * 2;
        const float em0 = g_em[b * L1 + m];
        const float em1 = g_em[b * L1 + m + 1];
        Sb[(size_t)hA * L1 + m]     = acc[nt][0] + dhA + em0 + bb0;
        Sb[(size_t)hA * L1 + m + 1] = acc[nt][1] + dhA + em1 + bb0;
        Sb[(size_t)hB * L1 + m]     = acc[nt][2] + dhB + em0 + bb0;
        Sb[(size_t)hB * L1 + m + 1] = acc[nt][3] + dhB + em1 + bb0;
    }
}

/* ===== K3b: boundary strips S[b,512,:] and S[b,:,512] ===== */
__global__ __launch_bounds__(256) void k_strip(const float* __restrict__ bab)
{
    const int gw = (blockIdx.x * 256 + threadIdx.x) >> 5;
    const int lane = threadIdx.x & 31;
    if (gw >= NB * 1025) return;
    const int b = gw / 1025, idx = gw % 1025;
    const int h = (idx < 513) ? 512 : idx - 513;
    const int m = (idx < 513) ? idx : 512;
    const __half* th = g_tmph + (size_t)(b * L1 + h) * NEN;
    const __half* tl = g_tmpl + (size_t)(b * L1 + h) * NEN;
    const __half* eh = g_enmh + (size_t)(b * L1 + m) * NEN;
    const __half* el = g_enml + (size_t)(b * L1 + m) * NEN;
    float s = 0.f;
#pragma unroll
    for (int k = lane; k < NEN; k += 32) {
        float a = __half2float(th[k]) + __half2float(tl[k]);
        float c = __half2float(eh[k]) + __half2float(el[k]);
        s += a * c;
    }
#pragma unroll
    for (int o = 16; o; o >>= 1) s += __shfl_xor_sync(0xffffffffu, s, o);
    if (!lane)
        g_S[((size_t)b * L1 + h) * L1 + m] =
            s + g_dh[b * L1 + h] + g_em[b * L1 + m] + __ldg(bab);
}

/* ============ K2b: dh = enh . ba_Wd, em = enm . ba_We ============ */
__global__ __launch_bounds__(256) void k_dotvec(
    const float* __restrict__ Wd, const float* __restrict__ We)
{
    const int gw = (blockIdx.x * blockDim.x + threadIdx.x) >> 5;
    const int lane = threadIdx.x & 31;
    if (gw >= NT) return;
    const float* r = g_enc + (size_t)gw * ENCW;
    float s1 = 0.f, s2 = 0.f;
#pragma unroll
    for (int k = lane; k < NEN; k += 32) {
        s1 += r[k] * Wd[k];
        s2 += r[256 + k] * We[k];
    }
#pragma unroll
    for (int o = 16; o; o >>= 1) {
        s1 += __shfl_xor_sync(0xffffffffu, s1, o);
        s2 += __shfl_xor_sync(0xffffffffu, s2, o);
    }
    if (!lane) { g_dh[gw] = s1; g_em[gw] = s2; }
}

/* ==== K4: per-column logsumexp + gold pick + decode argmax ==== */
__global__ __launch_bounds__(256) void k_node_reduce(
    const int* __restrict__ eheads, const int* __restrict__ mask,
    float* __restrict__ out)
{
    const int b = blockIdx.y;
    const int m0 = blockIdx.x * 32;
    const int tid = threadIdx.x, lane = tid & 31, w = tid >> 5;
    __shared__ int mk[L1];
    __shared__ float s_max[8][32], s_sum[8][32], s_bv[8][32];
    __shared__ int s_bi[8][32];
    for (int i = tid; i < L1; i += 256) mk[i] = (i == 0) ? 0 : mask[b * NL + i - 1];
    __syncthreads();

    const int m = m0 + lane;
    const bool mv = m < L1;
    const int msafe = mv ? m : (L1 - 1);
    const int mm_ = mk[msafe];
    const float* Sb = g_S + (size_t)b * L1 * L1;

    float rmax = -1e30f, rsum = 0.f, bv = -1e30f;
    int bi = 0x7fffffff;
    for (int h = w; h < L1; h += 8) {
        float s = Sb[(size_t)h * L1 + msafe];
        int mh = mk[h];
        float x = s + logmask(mh + mm_);
        if (x > rmax) { rsum = rsum * expf(rmax - x) + 1.f; rmax = x; }
        else            rsum += expf(x - rmax);
        float dv = s + (1.f - (float)mh) * (-1e8f);
        if (h != msafe && dv > bv) { bv = dv; bi = h; }
    }
    s_max[w][lane] = rmax; s_sum[w][lane] = rsum;
    s_bv[w][lane] = bv;    s_bi[w][lane] = bi;
    __syncthreads();

    if (w == 0) {
        float tm = -1e30f;
#pragma unroll
        for (int i = 0; i < 8; i++) tm = fmaxf(tm, s_max[i][lane]);
        float ts = 0.f;
#pragma unroll
        for (int i = 0; i < 8; i++) ts += s_sum[i][lane] * expf(s_max[i][lane] - tm);
        float lse = tm + logf(ts);
        int gh = (msafe == 0) ? 0 : eheads[b * NL + msafe - 1];
        float xg = Sb[(size_t)gh * L1 + msafe] + logmask(mk[gh] + mm_);
        float bbv = -1e30f; int bbi = 0x7fffffff;
#pragma unroll
        for (int i = 0; i < 8; i++) {
            float v = s_bv[i][lane]; int ix = s_bi[i][lane];
            if (v > bbv || (v == bbv && ix < bbi)) { bbv = v; bbi = ix; }
        }
        float contrib = 0.f;
        if (mv) {
            g_pred[b * L1 + m] = bbi;
            if (m >= 1) {
                out[OUT_PH + (size_t)b * NL + m - 1] = (float)bbi;
                contrib = -(xg - lse);
            }
        }
#pragma unroll
        for (int o = 16; o; o >>= 1) contrib += __shfl_xor_sync(0xffffffffu, contrib, o);
        if (lane == 0) g_partA[blockIdx.y * 17 + blockIdx.x] = contrib;
    }
}

/* ===== K5: label bilinear, fp16 m16n8k16, 16 labels per CTA ===== */
#define NBL  16
#define SW   68
#define W_AS 0
#define W_GS 8704
#define W_PS 17408
#define W_B0 26112
#define W_WL 43520
#define W_WB 45568
#define SMB2_BYTES ((45568 + 256) * 4)

__global__ __launch_bounds__(256) void k_bilin_mma(
    const float* __restrict__ Wl, const int* __restrict__ eheads)
{
    extern __shared__ unsigned smu[];
    float* Wls = (float*)(smu + W_WL);
    float* wb  = (float*)(smu + W_WB);
    const int tid = threadIdx.x, lane = tid & 31, w = tid >> 5;
    const int q = lane & 3, oct = lane >> 2;
    const int nb0 = blockIdx.y * NBL;
    const int t0 = blockIdx.x * 128;

    const int row = tid >> 1, h = tid & 1;
    const int ts = t0 + row;
    const bool tv = ts < NT;
    const int tc = tv ? ts : 0;

    {
        unsigned* dst = smu + W_AS + row * SW + h * 32;
        if (tv) {
            const uint4* src = (const uint4*)(g_elmh + (size_t)tc * NEL + h * 64);
#pragma unroll
            for (int j = 0; j < 8; j++) *(uint4*)(dst + 4 * j) = src[j];
        } else {
            uint4 z = make_uint4(0, 0, 0, 0);
#pragma unroll
            for (int j = 0; j < 8; j++) *(uint4*)(dst + 4 * j) = z;
        }
    }
    {
        const int bb = tc / L1, ll = tc - bb * L1;
        const int hr = h ? g_pred[tc] : ((ll == 0) ? 0 : eheads[bb * NL + ll - 1]);
        const uint4* src = (const uint4*)(g_elhh + (size_t)(bb * L1 + hr) * NEL);
        unsigned* dst = smu + (h ? W_PS : W_GS) + row * SW;
#pragma unroll
        for (int j = 0; j < 16; j++) *(uint4*)(dst + 4 * j) = src[j];
    }
    for (int idx = tid; idx < NBL * 128; idx += 256)
        Wls[idx] = Wl[nb0 * 128 + idx];
    {
        const uint4* src = (const uint4*)(g_Uh + ((size_t)nb0 * NEL + row) * NEL + h * 64);
        unsigned* dst = smu + W_B0 + row * SW + h * 32;
#pragma unroll
        for (int j = 0; j < 8; j++) *(uint4*)(dst + 4 * j) = src[j];
    }
    __syncthreads();

    const int r0 = w * 16 + oct;
    const unsigned* As = smu + W_AS;
    const unsigned* Gs = smu + W_GS;
    const unsigned* Ps = smu + W_PS;

    for (int i = 0; i < NBL; i++) {
        uint4 pf[8];
        if (i + 1 < NBL) {
            const uint4* src = (const uint4*)(g_Uh + ((size_t)(nb0 + i + 1) * NEL + row) * NEL + h * 64);
#pragma unroll
            for (int j = 0; j < 8; j++) pf[j] = src[j];
        }
        const unsigned* Bs = smu + W_B0 + (i & 1) * 8704;

        float acc[16][4] = {};
#pragma unroll
        for (int ks = 0; ks < 8; ks++) {
            const int kw = ks * 8 + q;
            const unsigned a0 = As[r0 * SW + kw],     a1 = As[(r0 + 8) * SW + kw];
            const unsigned a2 = As[r0 * SW + kw + 4], a3 = As[(r0 + 8) * SW + kw + 4];
#pragma unroll
            for (int nt = 0; nt < 16; nt++) {
                const int cb = (nt * 8 + oct) * SW + kw;
                mma_f16(acc[nt], a0, a1, a2, a3, Bs[cb], Bs[cb + 4]);
            }
        }

        const float* Wln = Wls + i * 128;
        float sg0 = 0.f, sp0 = 0.f, sg1 = 0.f, sp1 = 0.f;
#pragma unroll
        for (int nt = 0; nt < 16; nt++) {
            const int ch = nt * 8 + 2 * q;
            const int cw = nt * 4 + q;
            const float w0 = Wln[ch], w1 = Wln[ch + 1];
            const float d00 = acc[nt][0] + w0, d01 = acc[nt][1] + w1;
            const float d10 = acc[nt][2] + w0, d11 = acc[nt][3] + w1;
            unsigned ug0 = Gs[r0 * SW + cw], ug1 = Gs[(r0 + 8) * SW + cw];
            unsigned up0 = Ps[r0 * SW + cw], up1 = Ps[(r0 + 8) * SW + cw];
            float2 g0 = __half22float2(*(__half2*)&ug0);
            float2 g1 = __half22float2(*(__half2*)&ug1);
            float2 p0 = __half22float2(*(__half2*)&up0);
            float2 p1 = __half22float2(*(__half2*)&up1);
            sg0 += d00 * g0.x + d01 * g0.y;  sp0 += d00 * p0.x + d01 * p0.y;
            sg1 += d10 * g1.x + d11 * g1.y;  sp1 += d10 * p1.x + d11 * p1.y;
        }
#pragma unroll
        for (int o = 1; o <= 2; o <<= 1) {
            sg0 += __shfl_xor_sync(0xffffffffu, sg0, o);
            sp0 += __shfl_xor_sync(0xffffffffu, sp0, o);
            sg1 += __shfl_xor_sync(0xffffffffu, sg1, o);
            sp1 += __shfl_xor_sync(0xffffffffu, sp1, o);
        }
        if (q == 0) {
            wb[w * 32 + oct * 2 + 0] = sg0;
            wb[w * 32 + oct * 2 + 1] = sp0;
            wb[w * 32 + (oct + 8) * 2 + 0] = sg1;
            wb[w * 32 + (oct + 8) * 2 + 1] = sp1;
        }
        __syncwarp();
        {
            const int rr = lane & 15;
            const int t = t0 + w * 16 + rr;
            const size_t n = (size_t)(nb0 + i);
            if (t < NT) {
                if (lane < 16) g_sg[n * NT + t] = wb[w * 32 + rr * 2];
                else           g_sp[n * NT + t] = wb[w * 32 + rr * 2 + 1];
            }
        }
        __syncwarp();

        if (i + 1 < NBL) {
            unsigned* dst = smu + W_B0 + ((i + 1) & 1) * 8704 + row * SW + h * 32;
#pragma unroll
            for (int j = 0; j < 8; j++) *(uint4*)(dst + 4 * j) = pf[j];
        }
        __syncthreads();
    }
}

/* ===== K5b: lin[n,t] = elm[t] . Wr[n] + lbl_b[n] ===== */
__global__ __launch_bounds__(256) void k_lin(
    const float* __restrict__ Wr, const float* __restrict__ lb)
{
    __shared__ float As[16][64];
    __shared__ float Bs[16][64];
    const int tid = threadIdx.x;
    const int t0 = blockIdx.x * 64, n0 = blockIdx.y * 64;
    const int ar = tid >> 2, ac = (tid & 3) * 4;
    const float* arow = g_enc + (size_t)(t0 + ar) * ENCW + 640;
    const float* brow = Wr + (size_t)(n0 + ar) * NEL;
    const int ty = tid >> 4, tx = tid & 15;
    float acc[4][4] = {};
    for (int k0 = 0; k0 < NEL; k0 += 16) {
        float4 av = *(const float4*)(arow + k0 + ac);
        float4 bv = *(const float4*)(brow + k0 + ac);
        As[ac + 0][ar] = av.x; As[ac + 1][ar] = av.y;
        As[ac + 2][ar] = av.z; As[ac + 3][ar] = av.w;
        Bs[ac + 0][ar] = bv.x; Bs[ac + 1][ar] = bv.y;
        Bs[ac + 2][ar] = bv.z; Bs[ac + 3][ar] = bv.w;
        __syncthreads();
#pragma unroll
        for (int k = 0; k < 16; k++) {
            float a[4], bb[4];
#pragma unroll
            for (int i = 0; i < 4; i++) a[i]  = As[k][ty * 4 + i];
#pragma unroll
            for (int j = 0; j < 4; j++) bb[j] = Bs[k][tx * 4 + j];
#pragma unroll
            for (int i = 0; i < 4; i++)
#pragma unroll
                for (int j = 0; j < 4; j++) acc[i][j] += a[i] * bb[j];
        }
        __syncthreads();
    }
#pragma unroll
    for (int i = 0; i < 4; i++) {
        int t = t0 + ty * 4 + i;
#pragma unroll
        for (int j = 0; j < 4; j++) {
            int nn = n0 + tx * 4 + j;
            g_lin[(size_t)nn * NT + t] = acc[i][j] + lb[nn];
        }
    }
}

/* ===== K6: label log-softmax over n + max over n ===== */
__global__ __launch_bounds__(256) void k_lbl_reduce(
    const int* __restrict__ elabels, float* __restrict__ out)
{
    __shared__ float red[256];
    const int t = blockIdx.x * 256 + threadIdx.x;
    float contrib = 0.f;
    if (t < NT) {
        int b = t / L1, l = t % L1;
        int lab = (l == 0) ? 0 : elabels[b * NL + l - 1];
        float mg = -1e30f, sg = 0.f, mp = -1e30f, xlab = 0.f;
        for (int n = 0; n < NLB; n++) {
            float lin = g_lin[(size_t)n * NT + t];
            float xg = g_sg[(size_t)n * NT + t] + lin;
            float xp = g_sp[(size_t)n * NT + t] + lin;
            if (n == lab) xlab = xg;
            if (xg > mg) { sg = sg * expf(mg - xg) + 1.f; mg = xg; }
            else           sg += expf(xg - mg);
            mp = fmaxf(mp, xp);
        }
        float ll = xlab - (mg + logf(sg));
        if (l >= 1) {
            contrib = -ll;
            out[OUT_PL + (size_t)b * NL + l - 1] = mp;
        }
    }
    red[threadIdx.x] = contrib;
    __syncthreads();
    for (int s = 128; s; s >>= 1) {
        if (threadIdx.x < s) red[threadIdx.x] += red[threadIdx.x + s];
        __syncthreads();
    }
    if (!threadIdx.x) g_partB[blockIdx.x] = red[0];
}

/* ===== K7: labels1 output + deterministic NLL finalize ===== */
__global__ __launch_bounds__(256) void k_final(
    const int* __restrict__ elabels, float* __restrict__ out)
{
    const int i = blockIdx.x * 256 + threadIdx.x;
    if (i < NT) {
        int b = i / L1, l = i % L1;
        out[OUT_LB + i] = (l == 0) ? 0.f : (float)elabels[b * NL + l - 1];
    }
    if (i == 0) {
        float s = 0.f;
        for (int k = 0; k < 17 * 64; k++) s += g_partA[k];
        out[OUT_NN] = s;
        float s2 = 0.f;
        for (int k = 0; k < 129; k++) s2 += g_partB[k];
        out[OUT_LN] = s2;
    }
}

extern "C" void kernel_launch(void* const* d_in, const int* in_sizes, int n_in,
                              void* d_out, int out_size)
{
    const float* mem    = (const float*)d_in[0];
    const int*   eheads = (const int*)d_in[1];
    const int*   elabs  = (const int*)d_in[2];
    const int*   mask   = (const int*)d_in[4];
    const float* sent   = (const float*)d_in[5];
    const float* Wenh = (const float*)d_in[6];  const float* benh = (const float*)d_in[7];
    const float* Wenm = (const float*)d_in[8];  const float* benm = (const float*)d_in[9];
    const float* Welh = (const float*)d_in[10]; const float* belh = (const float*)d_in[11];
    const float* Welm = (const float*)d_in[12]; const float* belm = (const float*)d_in[13];
    const float* baU  = (const float*)d_in[14];
    const float* baWd = (const float*)d_in[15];
    const float* baWe = (const float*)d_in[16];
    const float* bab  = (const float*)d_in[17];
    const float* lU   = (const float*)d_in[18];
    const float* lWl  = (const float*)d_in[19];
    const float* lWr  = (const float*)d_in[20];
    const float* lb   = (const float*)d_in[21];
    float* out = (float*)d_out;

    cudaFuncSetAttribute(k_bilin_mma, cudaFuncAttributeMaxDynamicSharedMemorySize, SMB2_BYTES);
    cudaFuncSetAttribute(k_enc_mma, cudaFuncAttributeMaxDynamicSharedMemorySize, SME3_BYTES);
    cudaFuncSetAttribute(k_tmp_mma, cudaFuncAttributeMaxDynamicSharedMemorySize, SME3_BYTES);
    cudaFuncSetAttribute(k_ns_mma,  cudaFuncAttributeMaxDynamicSharedMemorySize, SME3_BYTES);

    k_trans<<<1600, 256>>>(Wenh, Wenm, Welh, Welm, benh, benm, belh, belm, baU);
    k_uh<<<2048, 256>>>(lU);
    k_msplit<<<57456, 256>>>(mem, sent);
    k_enc_mma<<<dim3(257, 6), 256, SME3_BYTES>>>();
    k_tmp_mma<<<dim3(257, 2), 256, SME3_BYTES>>>();
    k_dotvec<<<4104, 256>>>(baWd, baWe);
    k_ns_mma<<<dim3(4, 4, 64), 256, SME3_BYTES>>>(bab);
    k_strip<<<8200, 256>>>(bab);
    k_node_reduce<<<dim3(17, 64), 256>>>(eheads, mask, out);
    k_lin<<<dim3(513, 2), 256>>>(lWr, lb);
    k_bilin_mma<<<dim3(NTILES, 8), 256, SMB2_BYTES>>>(lWl, eheads);
    k_lbl_reduce<<<129, 256>>>(elabs, out);
    k_final<<<129, 256>>>(elabs, out);
}

// round 11
// speedup vs baseline: 4.2422x; 1.0191x over previous
#include <cuda_runtime.h>
#include <cuda_fp16.h>

#define NB   64
#define NL   512
#define NH   400
#define NHP  416            /* NH padded to 32 multiple (13 chunks of 32) */
#define NEN  256
#define NEL  128
#define NLB  128
#define L1   513
#define NT   (NB * L1)      /* 32832 */
#define ENCW 768
#define NTILES 257

/* output layout (flattened tuple, float32) */
#define OUT_PH 0
#define OUT_PL 32768
#define OUT_LB 65536
#define OUT_NN 98368
#define OUT_LN 98369

/* -------- scratch (device globals) -------- */
__device__ float  g_enc[(size_t)NT * ENCW];
__device__ float  g_dh[NT];
__device__ float  g_em[NT];
__device__ float  g_S[(size_t)NB * L1 * L1];
__device__ int    g_pred[NT];
__device__ float  g_sg[(size_t)NLB * NT];
__device__ float  g_sp[(size_t)NLB * NT];
__device__ float  g_lin[(size_t)NLB * NT];
__device__ float  g_partA[17 * 64];
__device__ float  g_partB[129];
__device__ float  g_biasC[768];
__device__ __half g_memh[(size_t)NT * NHP];
__device__ __half g_meml[(size_t)NT * NHP];
__device__ __half g_WTh[768 * NHP];
__device__ __half g_WTl[768 * NHP];
__device__ __half g_baUTh[NEN * NEN];
__device__ __half g_baUTl[NEN * NEN];
__device__ __half g_enhh[(size_t)NT * NEN];
__device__ __half g_enhl[(size_t)NT * NEN];
__device__ __half g_enmh[(size_t)NT * NEN];
__device__ __half g_enml[(size_t)NT * NEN];
__device__ __half g_tmph[(size_t)NT * NEN];
__device__ __half g_tmpl[(size_t)NT * NEN];
__device__ __half g_Uh[(size_t)NLB * NEL * NEL];
__device__ __half g_elhh[(size_t)NT * NEL];
__device__ __half g_elmh[(size_t)NT * NEL];

__device__ __forceinline__ float elu1(float x) { return x > 0.f ? x : expm1f(x); }
__device__ __forceinline__ float logmask(int s) {
    return s == 0 ? -103.27893f : (s == 1 ? 0.f : 0.69314718f);
}
/* FMA-pipe exp (arg <= 0 in all call sites): 2^(x*log2e), deg-6 poly, no MUFU */
__device__ __forceinline__ float fexp(float x) {
    x = fmaxf(x, -87.0f);
    float y = x * 1.4426950408889634f;
    float z = y + 12582912.0f;                    /* round to int via magic */
    int   n = __float_as_int(z) - 0x4B400000;
    float f = y - (z - 12582912.0f);              /* f in [-0.5, 0.5] */
    float p = 1.5403530e-4f;
    p = fmaf(p, f, 1.3333558e-3f);
    p = fmaf(p, f, 9.6181291e-3f);
    p = fmaf(p, f, 5.5504109e-2f);
    p = fmaf(p, f, 2.4022651e-1f);
    p = fmaf(p, f, 6.9314718e-1f);
    p = fmaf(p, f, 1.0f);
    return p * __int_as_float((n + 127) << 23);
}
__device__ __forceinline__ void fsplit(float v, __half& h, __half& l) {
    h = __float2half_rn(v);
    l = __float2half_rn(v - __half2float(h));
}
__device__ __forceinline__ void mma_f16(float* c, unsigned a0, unsigned a1,
                                        unsigned a2, unsigned a3,
                                        unsigned b0, unsigned b1) {
    asm volatile(
        "mma.sync.aligned.m16n8k16.row.col.f32.f16.f16.f32 "
        "{%0,%1,%2,%3}, {%4,%5,%6,%7}, {%8,%9}, {%0,%1,%2,%3};\n"
        : "+f"(c[0]), "+f"(c[1]), "+f"(c[2]), "+f"(c[3])
        : "r"(a0), "r"(a1), "r"(a2), "r"(a3), "r"(b0), "r"(b1));
}
__device__ __forceinline__ unsigned smem_u32(const void* p) {
    unsigned a;
    asm("{ .reg .u64 t; cvta.to.shared.u64 t, %1; cvt.u32.u64 %0, t; }" : "=r"(a) : "l"(p));
    return a;
}
__device__ __forceinline__ void cpa16(unsigned dst, const void* src) {
    asm volatile("cp.async.cg.shared.global [%0], [%1], 16;" :: "r"(dst), "l"(src));
}
#define CP_COMMIT() asm volatile("cp.async.commit_group;" ::: "memory")
#define CP_WAIT1()  asm volatile("cp.async.wait_group 1;"  ::: "memory")
#define CP_WAIT0()  asm volatile("cp.async.wait_group 0;"  ::: "memory")

/* ===== K0a: weight transposes + fp16 hi/lo split ===== */
__global__ __launch_bounds__(256) void k_trans(
    const float* __restrict__ Wenh, const float* __restrict__ Wenm,
    const float* __restrict__ Welh, const float* __restrict__ Welm,
    const float* __restrict__ benh, const float* __restrict__ benm,
    const float* __restrict__ belh, const float* __restrict__ belm,
    const float* __restrict__ baU)
{
    const int i = blockIdx.x * 256 + threadIdx.x;
    if (i < 768 * NHP) {
        const int k = i / 768, j = i % 768;
        float v = 0.f;
        if (k < NH) {
            if (j < 256)      v = Wenh[k * NEN + j];
            else if (j < 512) v = Wenm[k * NEN + j - 256];
            else if (j < 640) v = Welh[k * NEL + j - 512];
            else              v = Welm[k * NEL + j - 640];
        }
        __half h, l; fsplit(v, h, l);
        g_WTh[(size_t)j * NHP + k] = h;
        g_WTl[(size_t)j * NHP + k] = l;
        if (k == 0)
            g_biasC[j] = (j < 256) ? benh[j] : (j < 512) ? benm[j - 256]
                       : (j < 640) ? belh[j - 512] : belm[j - 640];
    } else {
        const int i2 = i - 768 * NHP;
        if (i2 < NEN * NEN) {
            const int k = i2 / NEN, n = i2 % NEN;
            __half h, l; fsplit(baU[k * NEN + n], h, l);
            g_baUTh[n * NEN + k] = h;
            g_baUTl[n * NEN + k] = l;
        }
    }
}

/* ===== K0b: lbl_U -> fp16 ===== */
__global__ __launch_bounds__(256) void k_uh(const float* __restrict__ U)
{
    const size_t base = ((size_t)blockIdx.x * 256 + threadIdx.x) * 4;
    float4 v = *(const float4*)(U + base);
    __half2 h0 = __floats2half2_rn(v.x, v.y);
    __half2 h1 = __floats2half2_rn(v.z, v.w);
    uint2 wv; wv.x = *(unsigned*)&h0; wv.y = *(unsigned*)&h1;
    *(uint2*)&g_Uh[base] = wv;
}

/* ===== K0c: [sentinel;mem] -> fp16 hi/lo ===== */
__global__ __launch_bounds__(256) void k_msplit(
    const float* __restrict__ mem, const float* __restrict__ sent)
{
    const size_t idx = (size_t)blockIdx.x * 256 + threadIdx.x;
    const int t = (int)(idx / NHP), k = (int)(idx % NHP);
    const int b = t / L1, l = t - b * L1;
    float v = 0.f;
    if (k < NH) v = (l == 0) ? sent[k] : mem[((size_t)b * NL + (l - 1)) * NH + k];
    __half h, lo; fsplit(v, h, lo);
    g_memh[idx] = h; g_meml[idx] = lo;
}

/* ===== pipelined fp16 GEMM pieces: 128x128 tile, K-chunk 32, 2 bufs ===== */
#define HSTR2 20
#define ABYTES 10240
#define BUFBYTES 40960
#define SME3_BYTES (2 * BUFBYTES)

__device__ __forceinline__ void stage_async(
    unsigned sb, int buf, int row, int h,
    const __half* aH, const __half* aL,
    const __half* bH, const __half* bL, int k0)
{
    const unsigned d = sb + buf * BUFBYTES + row * 80 + h * 32;
    const __half* s;
    s = aH + k0 + h * 16;
    cpa16(d, s); cpa16(d + 16, s + 8);
    s = aL + k0 + h * 16;
    cpa16(d + ABYTES, s); cpa16(d + ABYTES + 16, s + 8);
    s = bH + k0 + h * 16;
    cpa16(d + 2 * ABYTES, s); cpa16(d + 2 * ABYTES + 16, s + 8);
    s = bL + k0 + h * 16;
    cpa16(d + 3 * ABYTES, s); cpa16(d + 3 * ABYTES + 16, s + 8);
}
/* 2-term variant: skip A-lo staging */
__device__ __forceinline__ void stage_async2(
    unsigned sb, int buf, int row, int h,
    const __half* aH,
    const __half* bH, const __half* bL, int k0)
{
    const unsigned d = sb + buf * BUFBYTES + row * 80 + h * 32;
    const __half* s;
    s = aH + k0 + h * 16;
    cpa16(d, s); cpa16(d + 16, s + 8);
    s = bH + k0 + h * 16;
    cpa16(d + 2 * ABYTES, s); cpa16(d + 2 * ABYTES + 16, s + 8);
    s = bL + k0 + h * 16;
    cpa16(d + 3 * ABYTES, s); cpa16(d + 3 * ABYTES + 16, s + 8);
}

__device__ __forceinline__ void gemm3h_chunk32(
    const unsigned* base, int r0, int q, int oct, float acc[16][4])
{
    const unsigned* Ah = base;
    const unsigned* Al = base + ABYTES / 4;
    const unsigned* Bh = base + 2 * (ABYTES / 4);
    const unsigned* Bl = base + 3 * (ABYTES / 4);
#pragma unroll
    for (int ks = 0; ks < 2; ks++) {
        const int kw = ks * 8 + q;
        const unsigned ah0 = Ah[r0 * HSTR2 + kw],     ah1 = Ah[(r0 + 8) * HSTR2 + kw];
        const unsigned ah2 = Ah[r0 * HSTR2 + kw + 4], ah3 = Ah[(r0 + 8) * HSTR2 + kw + 4];
        const unsigned al0 = Al[r0 * HSTR2 + kw],     al1 = Al[(r0 + 8) * HSTR2 + kw];
        const unsigned al2 = Al[r0 * HSTR2 + kw + 4], al3 = Al[(r0 + 8) * HSTR2 + kw + 4];
#pragma unroll
        for (int nt = 0; nt < 16; nt++) {
            const int cb = (nt * 8 + oct) * HSTR2 + kw;
            const unsigned bh0 = Bh[cb], bh1 = Bh[cb + 4];
            const unsigned bl0 = Bl[cb], bl1 = Bl[cb + 4];
            mma_f16(acc[nt], ah0, ah1, ah2, ah3, bh0, bh1);
            mma_f16(acc[nt], ah0, ah1, ah2, ah3, bl0, bl1);
            mma_f16(acc[nt], al0, al1, al2, al3, bh0, bh1);
        }
    }
}
/* 2-term: ah*(bh+bl) — used for label-path encoder blocks */
__device__ __forceinline__ void gemm2h_chunk32(
    const unsigned* base, int r0, int q, int oct, float acc[16][4])
{
    const unsigned* Ah = base;
    const unsigned* Bh = base + 2 * (ABYTES / 4);
    const unsigned* Bl = base + 3 * (ABYTES / 4);
#pragma unroll
    for (int ks = 0; ks < 2; ks++) {
        const int kw = ks * 8 + q;
        const unsigned ah0 = Ah[r0 * HSTR2 + kw],     ah1 = Ah[(r0 + 8) * HSTR2 + kw];
        const unsigned ah2 = Ah[r0 * HSTR2 + kw + 4], ah3 = Ah[(r0 + 8) * HSTR2 + kw + 4];
#pragma unroll
        for (int nt = 0; nt < 16; nt++) {
            const int cb = (nt * 8 + oct) * HSTR2 + kw;
            mma_f16(acc[nt], ah0, ah1, ah2, ah3, Bh[cb], Bh[cb + 4]);
            mma_f16(acc[nt], ah0, ah1, ah2, ah3, Bl[cb], Bl[cb + 4]);
        }
    }
}

/* ===== K1: encoder GEMM + ELU, pipelined ===== */
__global__ __launch_bounds__(256) void k_enc_mma()
{
    extern __shared__ unsigned smu[];
    const unsigned sb = smem_u32(smu);
    const int tid = threadIdx.x, lane = tid & 31, w = tid >> 5;
    const int q = lane & 3, oct = lane >> 2;
    const int t0 = blockIdx.x * 128;
    const int nb = blockIdx.y * 128;
    const bool full = nb < 512;                 /* node path: 3-term */
    const int row = tid >> 1, h = tid & 1;
    const int ta = t0 + row;
    const bool aval = ta < NT;
    const __half* aH = g_memh + (size_t)(aval ? ta : 0) * NHP;
    const __half* aL = g_meml + (size_t)(aval ? ta : 0) * NHP;
    const __half* bH = g_WTh + (size_t)(nb + row) * NHP;
    const __half* bL = g_WTl + (size_t)(nb + row) * NHP;

    float acc[16][4] = {};
    if (full) stage_async(sb, 0, row, h, aH, aL, bH, bL, 0);
    else      stage_async2(sb, 0, row, h, aH, bH, bL, 0);
    CP_COMMIT();
    for (int c = 0; c < 13; c++) {
        if (c + 1 < 13) {
            if (full) stage_async(sb, (c + 1) & 1, row, h, aH, aL, bH, bL, (c + 1) * 32);
            else      stage_async2(sb, (c + 1) & 1, row, h, aH, bH, bL, (c + 1) * 32);
            CP_COMMIT();
            CP_WAIT1();
        } else CP_WAIT0();
        __syncthreads();
        if (full) gemm3h_chunk32(smu + (c & 1) * (BUFBYTES / 4), w * 16 + oct, q, oct, acc);
        else      gemm2h_chunk32(smu + (c & 1) * (BUFBYTES / 4), w * 16 + oct, q, oct, acc);
        __syncthreads();
    }

    const int r0 = w * 16 + oct;
#pragma unroll
    for (int rr = 0; rr < 2; rr++) {
        const int t = t0 + r0 + rr * 8;
        if (t >= NT) continue;
#pragma unroll
        for (int nt = 0; nt < 16; nt++) {
            const int c = nt * 8 + q * 2;
            const float v0 = elu1(acc[nt][rr * 2 + 0] + g_biasC[nb + c]);
            const float v1 = elu1(acc[nt][rr * 2 + 1] + g_biasC[nb + c + 1]);
            if (nb != 512)
                *(float2*)&g_enc[(size_t)t * ENCW + nb + c] = make_float2(v0, v1);
            __half h0, l0, h1, l1;
            fsplit(v0, h0, l0); fsplit(v1, h1, l1);
            if (nb < 256) {
                const int col = nb + c;
                *(__half2*)&g_enhh[(size_t)t * NEN + col] = __halves2half2(h0, h1);
                *(__half2*)&g_enhl[(size_t)t * NEN + col] = __halves2half2(l0, l1);
            } else if (nb < 512) {
                const int col = nb - 256 + c;
                *(__half2*)&g_enmh[(size_t)t * NEN + col] = __halves2half2(h0, h1);
                *(__half2*)&g_enml[(size_t)t * NEN + col] = __halves2half2(l0, l1);
            } else {
                const int col = nb - 512 + c;
                if (col < 128)
                    *(__half2*)&g_elhh[(size_t)t * NEL + col] = __halves2half2(h0, h1);
                else
                    *(__half2*)&g_elmh[(size_t)t * NEL + col - 128] = __halves2half2(h0, h1);
            }
        }
    }
}

/* ===== K2: tmp = enh @ ba_U, pipelined 3xfp16 ===== */
__global__ __launch_bounds__(256) void k_tmp_mma()
{
    extern __shared__ unsigned smu[];
    const unsigned sb = smem_u32(smu);
    const int tid = threadIdx.x, lane = tid & 31, w = tid >> 5;
    const int q = lane & 3, oct = lane >> 2;
    const int t0 = blockIdx.x * 128;
    const int nb = blockIdx.y * 128;
    const int row = tid >> 1, h = tid & 1;
    const int ta = t0 + row;
    const bool aval = ta < NT;
    const __half* aH = g_enhh + (size_t)(aval ? ta : 0) * NEN;
    const __half* aL = g_enhl + (size_t)(aval ? ta : 0) * NEN;
    const __half* bH = g_baUTh + (size_t)(nb + row) * NEN;
    const __half* bL = g_baUTl + (size_t)(nb + row) * NEN;

    float acc[16][4] = {};
    stage_async(sb, 0, row, h, aH, aL, bH, bL, 0);
    CP_COMMIT();
    for (int c = 0; c < 8; c++) {
        if (c + 1 < 8) {
            stage_async(sb, (c + 1) & 1, row, h, aH, aL, bH, bL, (c + 1) * 32);
            CP_COMMIT();
            CP_WAIT1();
        } else CP_WAIT0();
        __syncthreads();
        gemm3h_chunk32(smu + (c & 1) * (BUFBYTES / 4), w * 16 + oct, q, oct, acc);
        __syncthreads();
    }

    const int r0 = w * 16 + oct;
#pragma unroll
    for (int rr = 0; rr < 2; rr++) {
        const int t = t0 + r0 + rr * 8;
        if (t >= NT) continue;
#pragma unroll
        for (int nt = 0; nt < 16; nt++) {
            const int c = nt * 8 + q * 2;
            __half h0, l0, h1, l1;
            fsplit(acc[nt][rr * 2 + 0], h0, l0);
            fsplit(acc[nt][rr * 2 + 1], h1, l1);
            *(__half2*)&g_tmph[(size_t)t * NEN + nb + c] = __halves2half2(h0, h1);
            *(__half2*)&g_tmpl[(size_t)t * NEN + nb + c] = __halves2half2(l0, l1);
        }
    }
}

/* ===== K3: node scores S[b,h,m] for h,m < 512, pipelined 3xfp16 ===== */
__global__ __launch_bounds__(256) void k_ns_mma(const float* __restrict__ bab)
{
    extern __shared__ unsigned smu[];
    const unsigned sb = smem_u32(smu);
    const int tid = threadIdx.x, lane = tid & 31, w = tid >> 5;
    const int q = lane & 3, oct = lane >> 2;
    const int b = blockIdx.z;
    const int h0 = blockIdx.x * 128, m0 = blockIdx.y * 128;
    const int row = tid >> 1, h = tid & 1;
    const __half* aH = g_tmph + (size_t)(b * L1 + h0 + row) * NEN;
    const __half* aL = g_tmpl + (size_t)(b * L1 + h0 + row) * NEN;
    const __half* bH = g_enmh + (size_t)(b * L1 + m0 + row) * NEN;
    const __half* bL = g_enml + (size_t)(b * L1 + m0 + row) * NEN;

    float acc[16][4] = {};
    stage_async(sb, 0, row, h, aH, aL, bH, bL, 0);
    CP_COMMIT();
    for (int c = 0; c < 8; c++) {
        if (c + 1 < 8) {
            stage_async(sb, (c + 1) & 1, row, h, aH, aL, bH, bL, (c + 1) * 32);
            CP_COMMIT();
            CP_WAIT1();
        } else CP_WAIT0();
        __syncthreads();
        gemm3h_chunk32(smu + (c & 1) * (BUFBYTES / 4), w * 16 + oct, q, oct, acc);
        __syncthreads();
    }

    const int r0 = w * 16 + oct;
    const int hA = h0 + r0, hB = hA + 8;
    const float bb0 = __ldg(bab);
    const float dhA = g_dh[b * L1 + hA];
    const float dhB = g_dh[b * L1 + hB];
    float* Sb = g_S + (size_t)b * L1 * L1;
#pragma unroll
    for (int nt = 0; nt < 16; nt++) {
        const int m = m0 + nt * 8 + q * 2;
        const float em0 = g_em[b * L1 + m];
        const float em1 = g_em[b * L1 + m + 1];
        Sb[(size_t)hA * L1 + m]     = acc[nt][0] + dhA + em0 + bb0;
        Sb[(size_t)hA * L1 + m + 1] = acc[nt][1] + dhA + em1 + bb0;
        Sb[(size_t)hB * L1 + m]     = acc[nt][2] + dhB + em0 + bb0;
        Sb[(size_t)hB * L1 + m + 1] = acc[nt][3] + dhB + em1 + bb0;
    }
}

/* ===== K3b: boundary strips S[b,512,:] and S[b,:,512] ===== */
__global__ __launch_bounds__(256) void k_strip(const float* __restrict__ bab)
{
    const int gw = (blockIdx.x * 256 + threadIdx.x) >> 5;
    const int lane = threadIdx.x & 31;
    if (gw >= NB * 1025) return;
    const int b = gw / 1025, idx = gw % 1025;
    const int h = (idx < 513) ? 512 : idx - 513;
    const int m = (idx < 513) ? idx : 512;
    const __half* th = g_tmph + (size_t)(b * L1 + h) * NEN;
    const __half* tl = g_tmpl + (size_t)(b * L1 + h) * NEN;
    const __half* eh = g_enmh + (size_t)(b * L1 + m) * NEN;
    const __half* el = g_enml + (size_t)(b * L1 + m) * NEN;
    float s = 0.f;
#pragma unroll
    for (int k = lane; k < NEN; k += 32) {
        float a = __half2float(th[k]) + __half2float(tl[k]);
        float c = __half2float(eh[k]) + __half2float(el[k]);
        s += a * c;
    }
#pragma unroll
    for (int o = 16; o; o >>= 1) s += __shfl_xor_sync(0xffffffffu, s, o);
    if (!lane)
        g_S[((size_t)b * L1 + h) * L1 + m] =
            s + g_dh[b * L1 + h] + g_em[b * L1 + m] + __ldg(bab);
}

/* ============ K2b: dh = enh . ba_Wd, em = enm . ba_We ============ */
__global__ __launch_bounds__(256) void k_dotvec(
    const float* __restrict__ Wd, const float* __restrict__ We)
{
    const int gw = (blockIdx.x * blockDim.x + threadIdx.x) >> 5;
    const int lane = threadIdx.x & 31;
    if (gw >= NT) return;
    const float* r = g_enc + (size_t)gw * ENCW;
    float s1 = 0.f, s2 = 0.f;
#pragma unroll
    for (int k = lane; k < NEN; k += 32) {
        s1 += r[k] * Wd[k];
        s2 += r[256 + k] * We[k];
    }
#pragma unroll
    for (int o = 16; o; o >>= 1) {
        s1 += __shfl_xor_sync(0xffffffffu, s1, o);
        s2 += __shfl_xor_sync(0xffffffffu, s2, o);
    }
    if (!lane) { g_dh[gw] = s1; g_em[gw] = s2; }
}

/* ==== K4: per-column logsumexp + gold pick + decode argmax ==== */
__global__ __launch_bounds__(256) void k_node_reduce(
    const int* __restrict__ eheads, const int* __restrict__ mask,
    float* __restrict__ out)
{
    const int b = blockIdx.y;
    const int m0 = blockIdx.x * 32;
    const int tid = threadIdx.x, lane = tid & 31, w = tid >> 5;
    __shared__ int mk[L1];
    __shared__ float s_max[8][32], s_sum[8][32], s_bv[8][32];
    __shared__ int s_bi[8][32];
    for (int i = tid; i < L1; i += 256) mk[i] = (i == 0) ? 0 : mask[b * NL + i - 1];
    __syncthreads();

    const int m = m0 + lane;
    const bool mv = m < L1;
    const int msafe = mv ? m : (L1 - 1);
    const int mm_ = mk[msafe];
    const float* Sb = g_S + (size_t)b * L1 * L1;

    float rmax = -1e30f, rsum = 0.f, bv = -1e30f;
    int bi = 0x7fffffff;
    for (int h = w; h < L1; h += 8) {
        float s = Sb[(size_t)h * L1 + msafe];
        int mh = mk[h];
        float x = s + logmask(mh + mm_);
        if (x > rmax) { rsum = rsum * fexp(rmax - x) + 1.f; rmax = x; }
        else            rsum += fexp(x - rmax);
        float dv = s + (1.f - (float)mh) * (-1e8f);
        if (h != msafe && dv > bv) { bv = dv; bi = h; }
    }
    s_max[w][lane] = rmax; s_sum[w][lane] = rsum;
    s_bv[w][lane] = bv;    s_bi[w][lane] = bi;
    __syncthreads();

    if (w == 0) {
        float tm = -1e30f;
#pragma unroll
        for (int i = 0; i < 8; i++) tm = fmaxf(tm, s_max[i][lane]);
        float ts = 0.f;
#pragma unroll
        for (int i = 0; i < 8; i++) ts += s_sum[i][lane] * fexp(s_max[i][lane] - tm);
        float lse = tm + logf(ts);
        int gh = (msafe == 0) ? 0 : eheads[b * NL + msafe - 1];
        float xg = Sb[(size_t)gh * L1 + msafe] + logmask(mk[gh] + mm_);
        float bbv = -1e30f; int bbi = 0x7fffffff;
#pragma unroll
        for (int i = 0; i < 8; i++) {
            float v = s_bv[i][lane]; int ix = s_bi[i][lane];
            if (v > bbv || (v == bbv && ix < bbi)) { bbv = v; bbi = ix; }
        }
        float contrib = 0.f;
        if (mv) {
            g_pred[b * L1 + m] = bbi;
            if (m >= 1) {
                out[OUT_PH + (size_t)b * NL + m - 1] = (float)bbi;
                contrib = -(xg - lse);
            }
        }
#pragma unroll
        for (int o = 16; o; o >>= 1) contrib += __shfl_xor_sync(0xffffffffu, contrib, o);
        if (lane == 0) g_partA[blockIdx.y * 17 + blockIdx.x] = contrib;
    }
}

/* ===== K5: label bilinear, fp16 m16n8k16, 16 labels per CTA ===== */
#define NBL  16
#define SW   68
#define W_AS 0
#define W_GS 8704
#define W_PS 17408
#define W_B0 26112
#define W_WL 43520
#define W_WB 45568
#define SMB2_BYTES ((45568 + 256) * 4)

__global__ __launch_bounds__(256) void k_bilin_mma(
    const float* __restrict__ Wl, const int* __restrict__ eheads)
{
    extern __shared__ unsigned smu[];
    float* Wls = (float*)(smu + W_WL);
    float* wb  = (float*)(smu + W_WB);
    const int tid = threadIdx.x, lane = tid & 31, w = tid >> 5;
    const int q = lane & 3, oct = lane >> 2;
    const int nb0 = blockIdx.y * NBL;
    const int t0 = blockIdx.x * 128;

    const int row = tid >> 1, h = tid & 1;
    const int ts = t0 + row;
    const bool tv = ts < NT;
    const int tc = tv ? ts : 0;

    {
        unsigned* dst = smu + W_AS + row * SW + h * 32;
        if (tv) {
            const uint4* src = (const uint4*)(g_elmh + (size_t)tc * NEL + h * 64);
#pragma unroll
            for (int j = 0; j < 8; j++) *(uint4*)(dst + 4 * j) = src[j];
        } else {
            uint4 z = make_uint4(0, 0, 0, 0);
#pragma unroll
            for (int j = 0; j < 8; j++) *(uint4*)(dst + 4 * j) = z;
        }
    }
    {
        const int bb = tc / L1, ll = tc - bb * L1;
        const int hr = h ? g_pred[tc] : ((ll == 0) ? 0 : eheads[bb * NL + ll - 1]);
        const uint4* src = (const uint4*)(g_elhh + (size_t)(bb * L1 + hr) * NEL);
        unsigned* dst = smu + (h ? W_PS : W_GS) + row * SW;
#pragma unroll
        for (int j = 0; j < 16; j++) *(uint4*)(dst + 4 * j) = src[j];
    }
    for (int idx = tid; idx < NBL * 128; idx += 256)
        Wls[idx] = Wl[nb0 * 128 + idx];
    {
        const uint4* src = (const uint4*)(g_Uh + ((size_t)nb0 * NEL + row) * NEL + h * 64);
        unsigned* dst = smu + W_B0 + row * SW + h * 32;
#pragma unroll
        for (int j = 0; j < 8; j++) *(uint4*)(dst + 4 * j) = src[j];
    }
    __syncthreads();

    const int r0 = w * 16 + oct;
    const unsigned* As = smu + W_AS;
    const unsigned* Gs = smu + W_GS;
    const unsigned* Ps = smu + W_PS;

    for (int i = 0; i < NBL; i++) {
        uint4 pf[8];
        if (i + 1 < NBL) {
            const uint4* src = (const uint4*)(g_Uh + ((size_t)(nb0 + i + 1) * NEL + row) * NEL + h * 64);
#pragma unroll
            for (int j = 0; j < 8; j++) pf[j] = src[j];
        }
        const unsigned* Bs = smu + W_B0 + (i & 1) * 8704;

        float acc[16][4] = {};
#pragma unroll
        for (int ks = 0; ks < 8; ks++) {
            const int kw = ks * 8 + q;
            const unsigned a0 = As[r0 * SW + kw],     a1 = As[(r0 + 8) * SW + kw];
            const unsigned a2 = As[r0 * SW + kw + 4], a3 = As[(r0 + 8) * SW + kw + 4];
#pragma unroll
            for (int nt = 0; nt < 16; nt++) {
                const int cb = (nt * 8 + oct) * SW + kw;
                mma_f16(acc[nt], a0, a1, a2, a3, Bs[cb], Bs[cb + 4]);
            }
        }

        const float* Wln = Wls + i * 128;
        float sg0 = 0.f, sp0 = 0.f, sg1 = 0.f, sp1 = 0.f;
#pragma unroll
        for (int nt = 0; nt < 16; nt++) {
            const int ch = nt * 8 + 2 * q;
            const int cw = nt * 4 + q;
            const float w0 = Wln[ch], w1 = Wln[ch + 1];
            const float d00 = acc[nt][0] + w0, d01 = acc[nt][1] + w1;
            const float d10 = acc[nt][2] + w0, d11 = acc[nt][3] + w1;
            unsigned ug0 = Gs[r0 * SW + cw], ug1 = Gs[(r0 + 8) * SW + cw];
            unsigned up0 = Ps[r0 * SW + cw], up1 = Ps[(r0 + 8) * SW + cw];
            float2 g0 = __half22float2(*(__half2*)&ug0);
            float2 g1 = __half22float2(*(__half2*)&ug1);
            float2 p0 = __half22float2(*(__half2*)&up0);
            float2 p1 = __half22float2(*(__half2*)&up1);
            sg0 += d00 * g0.x + d01 * g0.y;  sp0 += d00 * p0.x + d01 * p0.y;
            sg1 += d10 * g1.x + d11 * g1.y;  sp1 += d10 * p1.x + d11 * p1.y;
        }
#pragma unroll
        for (int o = 1; o <= 2; o <<= 1) {
            sg0 += __shfl_xor_sync(0xffffffffu, sg0, o);
            sp0 += __shfl_xor_sync(0xffffffffu, sp0, o);
            sg1 += __shfl_xor_sync(0xffffffffu, sg1, o);
            sp1 += __shfl_xor_sync(0xffffffffu, sp1, o);
        }
        if (q == 0) {
            wb[w * 32 + oct * 2 + 0] = sg0;
            wb[w * 32 + oct * 2 + 1] = sp0;
            wb[w * 32 + (oct + 8) * 2 + 0] = sg1;
            wb[w * 32 + (oct + 8) * 2 + 1] = sp1;
        }
        __syncwarp();
        {
            const int rr = lane & 15;
            const int t = t0 + w * 16 + rr;
            const size_t n = (size_t)(nb0 + i);
            if (t < NT) {
                if (lane < 16) g_sg[n * NT + t] = wb[w * 32 + rr * 2];
                else           g_sp[n * NT + t] = wb[w * 32 + rr * 2 + 1];
            }
        }
        __syncwarp();

        if (i + 1 < NBL) {
            unsigned* dst = smu + W_B0 + ((i + 1) & 1) * 8704 + row * SW + h * 32;
#pragma unroll
            for (int j = 0; j < 8; j++) *(uint4*)(dst + 4 * j) = pf[j];
        }
        __syncthreads();
    }
}

/* ===== K5b: lin[n,t] = elm[t] . Wr[n] + lbl_b[n] ===== */
__global__ __launch_bounds__(256) void k_lin(
    const float* __restrict__ Wr, const float* __restrict__ lb)
{
    __shared__ float As[16][64];
    __shared__ float Bs[16][64];
    const int tid = threadIdx.x;
    const int t0 = blockIdx.x * 64, n0 = blockIdx.y * 64;
    const int ar = tid >> 2, ac = (tid & 3) * 4;
    const float* arow = g_enc + (size_t)(t0 + ar) * ENCW + 640;
    const float* brow = Wr + (size_t)(n0 + ar) * NEL;
    const int ty = tid >> 4, tx = tid & 15;
    float acc[4][4] = {};
    for (int k0 = 0; k0 < NEL; k0 += 16) {
        float4 av = *(const float4*)(arow + k0 + ac);
        float4 bv = *(const float4*)(brow + k0 + ac);
        As[ac + 0][ar] = av.x; As[ac + 1][ar] = av.y;
        As[ac + 2][ar] = av.z; As[ac + 3][ar] = av.w;
        Bs[ac + 0][ar] = bv.x; Bs[ac + 1][ar] = bv.y;
        Bs[ac + 2][ar] = bv.z; Bs[ac + 3][ar] = bv.w;
        __syncthreads();
#pragma unroll
        for (int k = 0; k < 16; k++) {
            float a[4], bb[4];
#pragma unroll
            for (int i = 0; i < 4; i++) a[i]  = As[k][ty * 4 + i];
#pragma unroll
            for (int j = 0; j < 4; j++) bb[j] = Bs[k][tx * 4 + j];
#pragma unroll
            for (int i = 0; i < 4; i++)
#pragma unroll
                for (int j = 0; j < 4; j++) acc[i][j] += a[i] * bb[j];
        }
        __syncthreads();
    }
#pragma unroll
    for (int i = 0; i < 4; i++) {
        int t = t0 + ty * 4 + i;
#pragma unroll
        for (int j = 0; j < 4; j++) {
            int nn = n0 + tx * 4 + j;
            g_lin[(size_t)nn * NT + t] = acc[i][j] + lb[nn];
        }
    }
}

/* ===== K6: label log-softmax over n + max over n ===== */
__global__ __launch_bounds__(256) void k_lbl_reduce(
    const int* __restrict__ elabels, float* __restrict__ out)
{
    __shared__ float red[256];
    const int t = blockIdx.x * 256 + threadIdx.x;
    float contrib = 0.f;
    if (t < NT) {
        int b = t / L1, l = t % L1;
        int lab = (l == 0) ? 0 : elabels[b * NL + l - 1];
        float mg = -1e30f, sg = 0.f, mp = -1e30f, xlab = 0.f;
        for (int n = 0; n < NLB; n++) {
            float lin = g_lin[(size_t)n * NT + t];
            float xg = g_sg[(size_t)n * NT + t] + lin;
            float xp = g_sp[(size_t)n * NT + t] + lin;
            if (n == lab) xlab = xg;
            if (xg > mg) { sg = sg * fexp(mg - xg) + 1.f; mg = xg; }
            else           sg += fexp(xg - mg);
            mp = fmaxf(mp, xp);
        }
        float ll = xlab - (mg + logf(sg));
        if (l >= 1) {
            contrib = -ll;
            out[OUT_PL + (size_t)b * NL + l - 1] = mp;
        }
    }
    red[threadIdx.x] = contrib;
    __syncthreads();
    for (int s = 128; s; s >>= 1) {
        if (threadIdx.x < s) red[threadIdx.x] += red[threadIdx.x + s];
        __syncthreads();
    }
    if (!threadIdx.x) g_partB[blockIdx.x] = red[0];
}

/* ===== K7: labels1 output + deterministic NLL finalize ===== */
__global__ __launch_bounds__(256) void k_final(
    const int* __restrict__ elabels, float* __restrict__ out)
{
    const int i = blockIdx.x * 256 + threadIdx.x;
    if (i < NT) {
        int b = i / L1, l = i % L1;
        out[OUT_LB + i] = (l == 0) ? 0.f : (float)elabels[b * NL + l - 1];
    }
    if (i == 0) {
        float s = 0.f;
        for (int k = 0; k < 17 * 64; k++) s += g_partA[k];
        out[OUT_NN] = s;
        float s2 = 0.f;
        for (int k = 0; k < 129; k++) s2 += g_partB[k];
        out[OUT_LN] = s2;
    }
}

extern "C" void kernel_launch(void* const* d_in, const int* in_sizes, int n_in,
                              void* d_out, int out_size)
{
    const float* mem    = (const float*)d_in[0];
    const int*   eheads = (const int*)d_in[1];
    const int*   elabs  = (const int*)d_in[2];
    const int*   mask   = (const int*)d_in[4];
    const float* sent   = (const float*)d_in[5];
    const float* Wenh = (const float*)d_in[6];  const float* benh = (const float*)d_in[7];
    const float* Wenm = (const float*)d_in[8];  const float* benm = (const float*)d_in[9];
    const float* Welh = (const float*)d_in[10]; const float* belh = (const float*)d_in[11];
    const float* Welm = (const float*)d_in[12]; const float* belm = (const float*)d_in[13];
    const float* baU  = (const float*)d_in[14];
    const float* baWd = (const float*)d_in[15];
    const float* baWe = (const float*)d_in[16];
    const float* bab  = (const float*)d_in[17];
    const float* lU   = (const float*)d_in[18];
    const float* lWl  = (const float*)d_in[19];
    const float* lWr  = (const float*)d_in[20];
    const float* lb   = (const float*)d_in[21];
    float* out = (float*)d_out;

    cudaFuncSetAttribute(k_bilin_mma, cudaFuncAttributeMaxDynamicSharedMemorySize, SMB2_BYTES);
    cudaFuncSetAttribute(k_enc_mma, cudaFuncAttributeMaxDynamicSharedMemorySize, SME3_BYTES);
    cudaFuncSetAttribute(k_tmp_mma, cudaFuncAttributeMaxDynamicSharedMemorySize, SME3_BYTES);
    cudaFuncSetAttribute(k_ns_mma,  cudaFuncAttributeMaxDynamicSharedMemorySize, SME3_BYTES);

    k_trans<<<1504, 256>>>(Wenh, Wenm, Welh, Welm, benh, benm, belh, belm, baU);
    k_uh<<<2048, 256>>>(lU);
    k_msplit<<<53352, 256>>>(mem, sent);
    k_enc_mma<<<dim3(257, 6), 256, SME3_BYTES>>>();
    k_tmp_mma<<<dim3(257, 2), 256, SME3_BYTES>>>();
    k_dotvec<<<4104, 256>>>(baWd, baWe);
    k_ns_mma<<<dim3(4, 4, 64), 256, SME3_BYTES>>>(bab);
    k_strip<<<8200, 256>>>(bab);
    k_node_reduce<<<dim3(17, 64), 256>>>(eheads, mask, out);
    k_lin<<<dim3(513, 2), 256>>>(lWr, lb);
    k_bilin_mma<<<dim3(NTILES, 8), 256, SMB2_BYTES>>>(lWl, eheads);
    k_lbl_reduce<<<129, 256>>>(elabs, out);
    k_final<<<129, 256>>>(elabs, out);
}

// round 12
// speedup vs baseline: 4.2546x; 1.0029x over previous
#include <cuda_runtime.h>
#include <cuda_fp16.h>

#define NB   64
#define NL   512
#define NH   400
#define NHP  416
#define NEN  256
#define NEL  128
#define NLB  128
#define L1   513
#define NT   (NB * L1)      /* 32832 */
#define ENCW 768
#define NTILES 257

#define OUT_PH 0
#define OUT_PL 32768
#define OUT_LB 65536
#define OUT_NN 98368
#define OUT_LN 98369

/* -------- scratch (device globals) -------- */
__device__ float  g_enc[(size_t)NT * ENCW];
__device__ float  g_dh[NT];
__device__ float  g_em[NT];
__device__ float  g_S[(size_t)NB * L1 * L1];
__device__ int    g_pred[NT];
__device__ float  g_sg[(size_t)NLB * NT];
__device__ float  g_sp[(size_t)NLB * NT];
__device__ float  g_lin[(size_t)NLB * NT];
__device__ float  g_partA[17 * 64];
__device__ float  g_partB[129];
__device__ float  g_biasC[768];
__device__ __half g_memh[(size_t)NT * NHP];
__device__ __half g_meml[(size_t)NT * NHP];
__device__ __half g_WTh[768 * NHP];
__device__ __half g_WTl[768 * NHP];
__device__ __half g_baUTh[NEN * NEN];
__device__ __half g_baUTl[NEN * NEN];
__device__ __half g_enhh[(size_t)NT * NEN];
__device__ __half g_enhl[(size_t)NT * NEN];
__device__ __half g_enmh[(size_t)NT * NEN];
__device__ __half g_enml[(size_t)NT * NEN];
__device__ __half g_tmph[(size_t)NT * NEN];
__device__ __half g_tmpl[(size_t)NT * NEN];
__device__ __half g_Uh[(size_t)NLB * NEL * NEL];
__device__ __half g_elhh[(size_t)NT * NEL];
__device__ __half g_elmh[(size_t)NT * NEL];

__device__ __forceinline__ float elu1(float x) { return x > 0.f ? x : expm1f(x); }
__device__ __forceinline__ float logmask(int s) {
    return s == 0 ? -103.27893f : (s == 1 ? 0.f : 0.69314718f);
}
/* FMA-pipe exp (arg <= 0 at call sites) */
__device__ __forceinline__ float fexp(float x) {
    x = fmaxf(x, -87.0f);
    float y = x * 1.4426950408889634f;
    float z = y + 12582912.0f;
    int   n = __float_as_int(z) - 0x4B400000;
    float f = y - (z - 12582912.0f);
    float p = 1.5403530e-4f;
    p = fmaf(p, f, 1.3333558e-3f);
    p = fmaf(p, f, 9.6181291e-3f);
    p = fmaf(p, f, 5.5504109e-2f);
    p = fmaf(p, f, 2.4022651e-1f);
    p = fmaf(p, f, 6.9314718e-1f);
    p = fmaf(p, f, 1.0f);
    return p * __int_as_float((n + 127) << 23);
}
__device__ __forceinline__ void fsplit(float v, __half& h, __half& l) {
    h = __float2half_rn(v);
    l = __float2half_rn(v - __half2float(h));
}
__device__ __forceinline__ void mma_f16(float* c, unsigned a0, unsigned a1,
                                        unsigned a2, unsigned a3,
                                        unsigned b0, unsigned b1) {
    asm volatile(
        "mma.sync.aligned.m16n8k16.row.col.f32.f16.f16.f32 "
        "{%0,%1,%2,%3}, {%4,%5,%6,%7}, {%8,%9}, {%0,%1,%2,%3};\n"
        : "+f"(c[0]), "+f"(c[1]), "+f"(c[2]), "+f"(c[3])
        : "r"(a0), "r"(a1), "r"(a2), "r"(a3), "r"(b0), "r"(b1));
}
__device__ __forceinline__ unsigned smem_u32(const void* p) {
    unsigned a;
    asm("{ .reg .u64 t; cvta.to.shared.u64 t, %1; cvt.u32.u64 %0, t; }" : "=r"(a) : "l"(p));
    return a;
}
__device__ __forceinline__ void cpa16(unsigned dst, const void* src) {
    asm volatile("cp.async.cg.shared.global [%0], [%1], 16;" :: "r"(dst), "l"(src));
}
#define CP_COMMIT() asm volatile("cp.async.commit_group;" ::: "memory")
#define CP_WAIT1()  asm volatile("cp.async.wait_group 1;"  ::: "memory")
#define CP_WAIT0()  asm volatile("cp.async.wait_group 0;"  ::: "memory")

/* ===== K0a: weight transposes + fp16 hi/lo split ===== */
__global__ __launch_bounds__(256) void k_trans(
    const float* __restrict__ Wenh, const float* __restrict__ Wenm,
    const float* __restrict__ Welh, const float* __restrict__ Welm,
    const float* __restrict__ benh, const float* __restrict__ benm,
    const float* __restrict__ belh, const float* __restrict__ belm,
    const float* __restrict__ baU)
{
    const int i = blockIdx.x * 256 + threadIdx.x;
    if (i < 768 * NHP) {
        const int k = i / 768, j = i % 768;
        float v = 0.f;
        if (k < NH) {
            if (j < 256)      v = Wenh[k * NEN + j];
            else if (j < 512) v = Wenm[k * NEN + j - 256];
            else if (j < 640) v = Welh[k * NEL + j - 512];
            else              v = Welm[k * NEL + j - 640];
        }
        __half h, l; fsplit(v, h, l);
        g_WTh[(size_t)j * NHP + k] = h;
        g_WTl[(size_t)j * NHP + k] = l;
        if (k == 0)
            g_biasC[j] = (j < 256) ? benh[j] : (j < 512) ? benm[j - 256]
                       : (j < 640) ? belh[j - 512] : belm[j - 640];
    } else {
        const int i2 = i - 768 * NHP;
        if (i2 < NEN * NEN) {
            const int k = i2 / NEN, n = i2 % NEN;
            __half h, l; fsplit(baU[k * NEN + n], h, l);
            g_baUTh[n * NEN + k] = h;
            g_baUTl[n * NEN + k] = l;
        }
    }
}

/* ===== K0b: lbl_U -> fp16 ===== */
__global__ __launch_bounds__(256) void k_uh(const float* __restrict__ U)
{
    const size_t base = ((size_t)blockIdx.x * 256 + threadIdx.x) * 4;
    float4 v = *(const float4*)(U + base);
    __half2 h0 = __floats2half2_rn(v.x, v.y);
    __half2 h1 = __floats2half2_rn(v.z, v.w);
    uint2 wv; wv.x = *(unsigned*)&h0; wv.y = *(unsigned*)&h1;
    *(uint2*)&g_Uh[base] = wv;
}

/* ===== K0c: [sentinel;mem] -> fp16 hi/lo ===== */
__global__ __launch_bounds__(256) void k_msplit(
    const float* __restrict__ mem, const float* __restrict__ sent)
{
    const size_t idx = (size_t)blockIdx.x * 256 + threadIdx.x;
    const int t = (int)(idx / NHP), k = (int)(idx % NHP);
    const int b = t / L1, l = t - b * L1;
    float v = 0.f;
    if (k < NH) v = (l == 0) ? sent[k] : mem[((size_t)b * NL + (l - 1)) * NH + k];
    __half h, lo; fsplit(v, h, lo);
    g_memh[idx] = h; g_meml[idx] = lo;
}

/* ===== pipelined fp16 GEMM pieces: 128x128 tile, K-chunk 32, 2 bufs.
   Warp tile 32 rows x 64 cols (w&3 -> row group, w>>2 -> col group). ===== */
#define HSTR2 20
#define ABYTES 10240
#define BUFBYTES 40960
#define SME3_BYTES (2 * BUFBYTES)

__device__ __forceinline__ void stage_async(
    unsigned sb, int buf, int row, int h,
    const __half* aH, const __half* aL,
    const __half* bH, const __half* bL, int k0)
{
    const unsigned d = sb + buf * BUFBYTES + row * 80 + h * 32;
    const __half* s;
    s = aH + k0 + h * 16;
    cpa16(d, s); cpa16(d + 16, s + 8);
    s = aL + k0 + h * 16;
    cpa16(d + ABYTES, s); cpa16(d + ABYTES + 16, s + 8);
    s = bH + k0 + h * 16;
    cpa16(d + 2 * ABYTES, s); cpa16(d + 2 * ABYTES + 16, s + 8);
    s = bL + k0 + h * 16;
    cpa16(d + 3 * ABYTES, s); cpa16(d + 3 * ABYTES + 16, s + 8);
}
__device__ __forceinline__ void stage_async2(
    unsigned sb, int buf, int row, int h,
    const __half* aH,
    const __half* bH, const __half* bL, int k0)
{
    const unsigned d = sb + buf * BUFBYTES + row * 80 + h * 32;
    const __half* s;
    s = aH + k0 + h * 16;
    cpa16(d, s); cpa16(d + 16, s + 8);
    s = bH + k0 + h * 16;
    cpa16(d + 2 * ABYTES, s); cpa16(d + 2 * ABYTES + 16, s + 8);
    s = bL + k0 + h * 16;
    cpa16(d + 3 * ABYTES, s); cpa16(d + 3 * ABYTES + 16, s + 8);
}

/* 3-term chunk: warp tile 32x64, acc0 = rows R..R+15, acc1 = rows R+16..R+31 */
__device__ __forceinline__ void gemm3h_chunk32(
    const unsigned* base, int R, int C, int q, int oct,
    float acc0[8][4], float acc1[8][4])
{
    const unsigned* Ah = base;
    const unsigned* Al = base + ABYTES / 4;
    const unsigned* Bh = base + 2 * (ABYTES / 4);
    const unsigned* Bl = base + 3 * (ABYTES / 4);
#pragma unroll
    for (int ks = 0; ks < 2; ks++) {
        const int kw = ks * 8 + q;
        const int ra = (R + oct) * HSTR2 + kw;
        const unsigned ah0 = Ah[ra],                  ah1 = Ah[ra + 8 * HSTR2];
        const unsigned ah2 = Ah[ra + 4],              ah3 = Ah[ra + 8 * HSTR2 + 4];
        const unsigned ah4 = Ah[ra + 16 * HSTR2],     ah5 = Ah[ra + 24 * HSTR2];
        const unsigned ah6 = Ah[ra + 16 * HSTR2 + 4], ah7 = Ah[ra + 24 * HSTR2 + 4];
        const unsigned al0 = Al[ra],                  al1 = Al[ra + 8 * HSTR2];
        const unsigned al2 = Al[ra + 4],              al3 = Al[ra + 8 * HSTR2 + 4];
        const unsigned al4 = Al[ra + 16 * HSTR2],     al5 = Al[ra + 24 * HSTR2];
        const unsigned al6 = Al[ra + 16 * HSTR2 + 4], al7 = Al[ra + 24 * HSTR2 + 4];
#pragma unroll
        for (int nt = 0; nt < 8; nt++) {
            const int cb = (C + nt * 8 + oct) * HSTR2 + kw;
            const unsigned bh0 = Bh[cb], bh1 = Bh[cb + 4];
            const unsigned bl0 = Bl[cb], bl1 = Bl[cb + 4];
            mma_f16(acc0[nt], ah0, ah1, ah2, ah3, bh0, bh1);
            mma_f16(acc0[nt], ah0, ah1, ah2, ah3, bl0, bl1);
            mma_f16(acc0[nt], al0, al1, al2, al3, bh0, bh1);
            mma_f16(acc1[nt], ah4, ah5, ah6, ah7, bh0, bh1);
            mma_f16(acc1[nt], ah4, ah5, ah6, ah7, bl0, bl1);
            mma_f16(acc1[nt], al4, al5, al6, al7, bh0, bh1);
        }
    }
}
/* 2-term chunk: ah*(bh+bl) */
__device__ __forceinline__ void gemm2h_chunk32(
    const unsigned* base, int R, int C, int q, int oct,
    float acc0[8][4], float acc1[8][4])
{
    const unsigned* Ah = base;
    const unsigned* Bh = base + 2 * (ABYTES / 4);
    const unsigned* Bl = base + 3 * (ABYTES / 4);
#pragma unroll
    for (int ks = 0; ks < 2; ks++) {
        const int kw = ks * 8 + q;
        const int ra = (R + oct) * HSTR2 + kw;
        const unsigned ah0 = Ah[ra],                  ah1 = Ah[ra + 8 * HSTR2];
        const unsigned ah2 = Ah[ra + 4],              ah3 = Ah[ra + 8 * HSTR2 + 4];
        const unsigned ah4 = Ah[ra + 16 * HSTR2],     ah5 = Ah[ra + 24 * HSTR2];
        const unsigned ah6 = Ah[ra + 16 * HSTR2 + 4], ah7 = Ah[ra + 24 * HSTR2 + 4];
#pragma unroll
        for (int nt = 0; nt < 8; nt++) {
            const int cb = (C + nt * 8 + oct) * HSTR2 + kw;
            const unsigned bh0 = Bh[cb], bh1 = Bh[cb + 4];
            const unsigned bl0 = Bl[cb], bl1 = Bl[cb + 4];
            mma_f16(acc0[nt], ah0, ah1, ah2, ah3, bh0, bh1);
            mma_f16(acc0[nt], ah0, ah1, ah2, ah3, bl0, bl1);
            mma_f16(acc1[nt], ah4, ah5, ah6, ah7, bh0, bh1);
            mma_f16(acc1[nt], ah4, ah5, ah6, ah7, bl0, bl1);
        }
    }
}

/* ===== K1: encoder GEMM + ELU, pipelined ===== */
__global__ __launch_bounds__(256) void k_enc_mma()
{
    extern __shared__ unsigned smu[];
    const unsigned sb = smem_u32(smu);
    const int tid = threadIdx.x, lane = tid & 31, w = tid >> 5;
    const int q = lane & 3, oct = lane >> 2;
    const int Rw = (w & 3) * 32, Cw = (w >> 2) * 64;
    const int t0 = blockIdx.x * 128;
    const int nb = blockIdx.y * 128;
    const bool full = nb < 512;
    const int row = tid >> 1, h = tid & 1;
    const int ta = t0 + row;
    const bool aval = ta < NT;
    const __half* aH = g_memh + (size_t)(aval ? ta : 0) * NHP;
    const __half* aL = g_meml + (size_t)(aval ? ta : 0) * NHP;
    const __half* bH = g_WTh + (size_t)(nb + row) * NHP;
    const __half* bL = g_WTl + (size_t)(nb + row) * NHP;

    float acc0[8][4] = {}, acc1[8][4] = {};
    if (full) stage_async(sb, 0, row, h, aH, aL, bH, bL, 0);
    else      stage_async2(sb, 0, row, h, aH, bH, bL, 0);
    CP_COMMIT();
    for (int c = 0; c < 13; c++) {
        if (c + 1 < 13) {
            if (full) stage_async(sb, (c + 1) & 1, row, h, aH, aL, bH, bL, (c + 1) * 32);
            else      stage_async2(sb, (c + 1) & 1, row, h, aH, bH, bL, (c + 1) * 32);
            CP_COMMIT();
            CP_WAIT1();
        } else CP_WAIT0();
        __syncthreads();
        if (full) gemm3h_chunk32(smu + (c & 1) * (BUFBYTES / 4), Rw, Cw, q, oct, acc0, acc1);
        else      gemm2h_chunk32(smu + (c & 1) * (BUFBYTES / 4), Rw, Cw, q, oct, acc0, acc1);
        __syncthreads();
    }

#pragma unroll
    for (int half = 0; half < 2; half++) {
        float (*A)[4] = half ? acc1 : acc0;
#pragma unroll
        for (int rr = 0; rr < 2; rr++) {
            const int t = t0 + Rw + oct + half * 16 + rr * 8;
            if (t >= NT) continue;
#pragma unroll
            for (int nt = 0; nt < 8; nt++) {
                const int c = Cw + nt * 8 + q * 2;
                const float v0 = elu1(A[nt][rr * 2 + 0] + g_biasC[nb + c]);
                const float v1 = elu1(A[nt][rr * 2 + 1] + g_biasC[nb + c + 1]);
                if (nb != 512)
                    *(float2*)&g_enc[(size_t)t * ENCW + nb + c] = make_float2(v0, v1);
                __half h0, l0, h1, l1;
                fsplit(v0, h0, l0); fsplit(v1, h1, l1);
                if (nb < 256) {
                    const int col = nb + c;
                    *(__half2*)&g_enhh[(size_t)t * NEN + col] = __halves2half2(h0, h1);
                    *(__half2*)&g_enhl[(size_t)t * NEN + col] = __halves2half2(l0, l1);
                } else if (nb < 512) {
                    const int col = nb - 256 + c;
                    *(__half2*)&g_enmh[(size_t)t * NEN + col] = __halves2half2(h0, h1);
                    *(__half2*)&g_enml[(size_t)t * NEN + col] = __halves2half2(l0, l1);
                } else {
                    const int col = nb - 512 + c;
                    if (col < 128)
                        *(__half2*)&g_elhh[(size_t)t * NEL + col] = __halves2half2(h0, h1);
                    else
                        *(__half2*)&g_elmh[(size_t)t * NEL + col - 128] = __halves2half2(h0, h1);
                }
            }
        }
    }
}

/* ===== K2: tmp = enh @ ba_U, pipelined 3xfp16 ===== */
__global__ __launch_bounds__(256) void k_tmp_mma()
{
    extern __shared__ unsigned smu[];
    const unsigned sb = smem_u32(smu);
    const int tid = threadIdx.x, lane = tid & 31, w = tid >> 5;
    const int q = lane & 3, oct = lane >> 2;
    const int Rw = (w & 3) * 32, Cw = (w >> 2) * 64;
    const int t0 = blockIdx.x * 128;
    const int nb = blockIdx.y * 128;
    const int row = tid >> 1, h = tid & 1;
    const int ta = t0 + row;
    const bool aval = ta < NT;
    const __half* aH = g_enhh + (size_t)(aval ? ta : 0) * NEN;
    const __half* aL = g_enhl + (size_t)(aval ? ta : 0) * NEN;
    const __half* bH = g_baUTh + (size_t)(nb + row) * NEN;
    const __half* bL = g_baUTl + (size_t)(nb + row) * NEN;

    float acc0[8][4] = {}, acc1[8][4] = {};
    stage_async(sb, 0, row, h, aH, aL, bH, bL, 0);
    CP_COMMIT();
    for (int c = 0; c < 8; c++) {
        if (c + 1 < 8) {
            stage_async(sb, (c + 1) & 1, row, h, aH, aL, bH, bL, (c + 1) * 32);
            CP_COMMIT();
            CP_WAIT1();
        } else CP_WAIT0();
        __syncthreads();
        gemm3h_chunk32(smu + (c & 1) * (BUFBYTES / 4), Rw, Cw, q, oct, acc0, acc1);
        __syncthreads();
    }

#pragma unroll
    for (int half = 0; half < 2; half++) {
        float (*A)[4] = half ? acc1 : acc0;
#pragma unroll
        for (int rr = 0; rr < 2; rr++) {
            const int t = t0 + Rw + oct + half * 16 + rr * 8;
            if (t >= NT) continue;
#pragma unroll
            for (int nt = 0; nt < 8; nt++) {
                const int c = Cw + nt * 8 + q * 2;
                __half h0, l0, h1, l1;
                fsplit(A[nt][rr * 2 + 0], h0, l0);
                fsplit(A[nt][rr * 2 + 1], h1, l1);
                *(__half2*)&g_tmph[(size_t)t * NEN + nb + c] = __halves2half2(h0, h1);
                *(__half2*)&g_tmpl[(size_t)t * NEN + nb + c] = __halves2half2(l0, l1);
            }
        }
    }
}

/* ===== K3: node scores S[b,h,m] for h,m < 512, pipelined 3xfp16 ===== */
__global__ __launch_bounds__(256) void k_ns_mma(const float* __restrict__ bab)
{
    extern __shared__ unsigned smu[];
    const unsigned sb = smem_u32(smu);
    const int tid = threadIdx.x, lane = tid & 31, w = tid >> 5;
    const int q = lane & 3, oct = lane >> 2;
    const int Rw = (w & 3) * 32, Cw = (w >> 2) * 64;
    const int b = blockIdx.z;
    const int h0 = blockIdx.x * 128, m0 = blockIdx.y * 128;
    const int row = tid >> 1, h = tid & 1;
    const __half* aH = g_tmph + (size_t)(b * L1 + h0 + row) * NEN;
    const __half* aL = g_tmpl + (size_t)(b * L1 + h0 + row) * NEN;
    const __half* bH = g_enmh + (size_t)(b * L1 + m0 + row) * NEN;
    const __half* bL = g_enml + (size_t)(b * L1 + m0 + row) * NEN;

    float acc0[8][4] = {}, acc1[8][4] = {};
    stage_async(sb, 0, row, h, aH, aL, bH, bL, 0);
    CP_COMMIT();
    for (int c = 0; c < 8; c++) {
        if (c + 1 < 8) {
            stage_async(sb, (c + 1) & 1, row, h, aH, aL, bH, bL, (c + 1) * 32);
            CP_COMMIT();
            CP_WAIT1();
        } else CP_WAIT0();
        __syncthreads();
        gemm3h_chunk32(smu + (c & 1) * (BUFBYTES / 4), Rw, Cw, q, oct, acc0, acc1);
        __syncthreads();
    }

    const float bb0 = __ldg(bab);
    float* Sb = g_S + (size_t)b * L1 * L1;
#pragma unroll
    for (int half = 0; half < 2; half++) {
        float (*A)[4] = half ? acc1 : acc0;
#pragma unroll
        for (int rr = 0; rr < 2; rr++) {
            const int hh = h0 + Rw + oct + half * 16 + rr * 8;
            const float dh = g_dh[b * L1 + hh];
#pragma unroll
            for (int nt = 0; nt < 8; nt++) {
                const int m = m0 + Cw + nt * 8 + q * 2;
                const float em0 = g_em[b * L1 + m];
                const float em1 = g_em[b * L1 + m + 1];
                Sb[(size_t)hh * L1 + m]     = A[nt][rr * 2 + 0] + dh + em0 + bb0;
                Sb[(size_t)hh * L1 + m + 1] = A[nt][rr * 2 + 1] + dh + em1 + bb0;
            }
        }
    }
}

/* ===== K3b: boundary strips S[b,512,:] and S[b,:,512] ===== */
__global__ __launch_bounds__(256) void k_strip(const float* __restrict__ bab)
{
    const int gw = (blockIdx.x * 256 + threadIdx.x) >> 5;
    const int lane = threadIdx.x & 31;
    if (gw >= NB * 1025) return;
    const int b = gw / 1025, idx = gw % 1025;
    const int h = (idx < 513) ? 512 : idx - 513;
    const int m = (idx < 513) ? idx : 512;
    const __half* th = g_tmph + (size_t)(b * L1 + h) * NEN;
    const __half* tl = g_tmpl + (size_t)(b * L1 + h) * NEN;
    const __half* eh = g_enmh + (size_t)(b * L1 + m) * NEN;
    const __half* el = g_enml + (size_t)(b * L1 + m) * NEN;
    float s = 0.f;
#pragma unroll
    for (int k = lane; k < NEN; k += 32) {
        float a = __half2float(th[k]) + __half2float(tl[k]);
        float c = __half2float(eh[k]) + __half2float(el[k]);
        s += a * c;
    }
#pragma unroll
    for (int o = 16; o; o >>= 1) s += __shfl_xor_sync(0xffffffffu, s, o);
    if (!lane)
        g_S[((size_t)b * L1 + h) * L1 + m] =
            s + g_dh[b * L1 + h] + g_em[b * L1 + m] + __ldg(bab);
}

/* ============ K2b: dh = enh . ba_Wd, em = enm . ba_We ============ */
__global__ __launch_bounds__(256) void k_dotvec(
    const float* __restrict__ Wd, const float* __restrict__ We)
{
    const int gw = (blockIdx.x * blockDim.x + threadIdx.x) >> 5;
    const int lane = threadIdx.x & 31;
    if (gw >= NT) return;
    const float* r = g_enc + (size_t)gw * ENCW;
    float s1 = 0.f, s2 = 0.f;
#pragma unroll
    for (int k = lane; k < NEN; k += 32) {
        s1 += r[k] * Wd[k];
        s2 += r[256 + k] * We[k];
    }
#pragma unroll
    for (int o = 16; o; o >>= 1) {
        s1 += __shfl_xor_sync(0xffffffffu, s1, o);
        s2 += __shfl_xor_sync(0xffffffffu, s2, o);
    }
    if (!lane) { g_dh[gw] = s1; g_em[gw] = s2; }
}

/* ==== K4: per-column logsumexp + gold pick + decode argmax ==== */
__global__ __launch_bounds__(256) void k_node_reduce(
    const int* __restrict__ eheads, const int* __restrict__ mask,
    float* __restrict__ out)
{
    const int b = blockIdx.y;
    const int m0 = blockIdx.x * 32;
    const int tid = threadIdx.x, lane = tid & 31, w = tid >> 5;
    __shared__ int mk[L1];
    __shared__ float s_max[8][32], s_sum[8][32], s_bv[8][32];
    __shared__ int s_bi[8][32];
    for (int i = tid; i < L1; i += 256) mk[i] = (i == 0) ? 0 : mask[b * NL + i - 1];
    __syncthreads();

    const int m = m0 + lane;
    const bool mv = m < L1;
    const int msafe = mv ? m : (L1 - 1);
    const int mm_ = mk[msafe];
    const float* Sb = g_S + (size_t)b * L1 * L1;

    float rmax = -1e30f, rsum = 0.f, bv = -1e30f;
    int bi = 0x7fffffff;
    for (int h = w; h < L1; h += 8) {
        float s = Sb[(size_t)h * L1 + msafe];
        int mh = mk[h];
        float x = s + logmask(mh + mm_);
        if (x > rmax) { rsum = rsum * fexp(rmax - x) + 1.f; rmax = x; }
        else            rsum += fexp(x - rmax);
        float dv = s + (1.f - (float)mh) * (-1e8f);
        if (h != msafe && dv > bv) { bv = dv; bi = h; }
    }
    s_max[w][lane] = rmax; s_sum[w][lane] = rsum;
    s_bv[w][lane] = bv;    s_bi[w][lane] = bi;
    __syncthreads();

    if (w == 0) {
        float tm = -1e30f;
#pragma unroll
        for (int i = 0; i < 8; i++) tm = fmaxf(tm, s_max[i][lane]);
        float ts = 0.f;
#pragma unroll
        for (int i = 0; i < 8; i++) ts += s_sum[i][lane] * fexp(s_max[i][lane] - tm);
        float lse = tm + logf(ts);
        int gh = (msafe == 0) ? 0 : eheads[b * NL + msafe - 1];
        float xg = Sb[(size_t)gh * L1 + msafe] + logmask(mk[gh] + mm_);
        float bbv = -1e30f; int bbi = 0x7fffffff;
#pragma unroll
        for (int i = 0; i < 8; i++) {
            float v = s_bv[i][lane]; int ix = s_bi[i][lane];
            if (v > bbv || (v == bbv && ix < bbi)) { bbv = v; bbi = ix; }
        }
        float contrib = 0.f;
        if (mv) {
            g_pred[b * L1 + m] = bbi;
            if (m >= 1) {
                out[OUT_PH + (size_t)b * NL + m - 1] = (float)bbi;
                contrib = -(xg - lse);
            }
        }
#pragma unroll
        for (int o = 16; o; o >>= 1) contrib += __shfl_xor_sync(0xffffffffu, contrib, o);
        if (lane == 0) g_partA[blockIdx.y * 17 + blockIdx.x] = contrib;
    }
}

/* ===== K5: label bilinear, fp16 m16n8k16, 16 labels per CTA.
   Writeback folds the g_lin term (sg/sp stored complete). ===== */
#define NBL  16
#define SW   68
#define W_AS 0
#define W_GS 8704
#define W_PS 17408
#define W_B0 26112
#define W_WL 43520
#define W_WB 45568
#define SMB2_BYTES ((45568 + 256) * 4)

__global__ __launch_bounds__(256) void k_bilin_mma(
    const float* __restrict__ Wl, const int* __restrict__ eheads)
{
    extern __shared__ unsigned smu[];
    float* Wls = (float*)(smu + W_WL);
    float* wb  = (float*)(smu + W_WB);
    const int tid = threadIdx.x, lane = tid & 31, w = tid >> 5;
    const int q = lane & 3, oct = lane >> 2;
    const int nb0 = blockIdx.y * NBL;
    const int t0 = blockIdx.x * 128;

    const int row = tid >> 1, h = tid & 1;
    const int ts = t0 + row;
    const bool tv = ts < NT;
    const int tc = tv ? ts : 0;

    {
        unsigned* dst = smu + W_AS + row * SW + h * 32;
        if (tv) {
            const uint4* src = (const uint4*)(g_elmh + (size_t)tc * NEL + h * 64);
#pragma unroll
            for (int j = 0; j < 8; j++) *(uint4*)(dst + 4 * j) = src[j];
        } else {
            uint4 z = make_uint4(0, 0, 0, 0);
#pragma unroll
            for (int j = 0; j < 8; j++) *(uint4*)(dst + 4 * j) = z;
        }
    }
    {
        const int bb = tc / L1, ll = tc - bb * L1;
        const int hr = h ? g_pred[tc] : ((ll == 0) ? 0 : eheads[bb * NL + ll - 1]);
        const uint4* src = (const uint4*)(g_elhh + (size_t)(bb * L1 + hr) * NEL);
        unsigned* dst = smu + (h ? W_PS : W_GS) + row * SW;
#pragma unroll
        for (int j = 0; j < 16; j++) *(uint4*)(dst + 4 * j) = src[j];
    }
    for (int idx = tid; idx < NBL * 128; idx += 256)
        Wls[idx] = Wl[nb0 * 128 + idx];
    {
        const uint4* src = (const uint4*)(g_Uh + ((size_t)nb0 * NEL + row) * NEL + h * 64);
        unsigned* dst = smu + W_B0 + row * SW + h * 32;
#pragma unroll
        for (int j = 0; j < 8; j++) *(uint4*)(dst + 4 * j) = src[j];
    }
    __syncthreads();

    const int r0 = w * 16 + oct;
    const unsigned* As = smu + W_AS;
    const unsigned* Gs = smu + W_GS;
    const unsigned* Ps = smu + W_PS;

    for (int i = 0; i < NBL; i++) {
        uint4 pf[8];
        if (i + 1 < NBL) {
            const uint4* src = (const uint4*)(g_Uh + ((size_t)(nb0 + i + 1) * NEL + row) * NEL + h * 64);
#pragma unroll
            for (int j = 0; j < 8; j++) pf[j] = src[j];
        }
        const unsigned* Bs = smu + W_B0 + (i & 1) * 8704;

        float acc[16][4] = {};
#pragma unroll
        for (int ks = 0; ks < 8; ks++) {
            const int kw = ks * 8 + q;
            const unsigned a0 = As[r0 * SW + kw],     a1 = As[(r0 + 8) * SW + kw];
            const unsigned a2 = As[r0 * SW + kw + 4], a3 = As[(r0 + 8) * SW + kw + 4];
#pragma unroll
            for (int nt = 0; nt < 16; nt++) {
                const int cb = (nt * 8 + oct) * SW + kw;
                mma_f16(acc[nt], a0, a1, a2, a3, Bs[cb], Bs[cb + 4]);
            }
        }

        const float* Wln = Wls + i * 128;
        float sg0 = 0.f, sp0 = 0.f, sg1 = 0.f, sp1 = 0.f;
#pragma unroll
        for (int nt = 0; nt < 16; nt++) {
            const int ch = nt * 8 + 2 * q;
            const int cw = nt * 4 + q;
            const float w0 = Wln[ch], w1 = Wln[ch + 1];
            const float d00 = acc[nt][0] + w0, d01 = acc[nt][1] + w1;
            const float d10 = acc[nt][2] + w0, d11 = acc[nt][3] + w1;
            unsigned ug0 = Gs[r0 * SW + cw], ug1 = Gs[(r0 + 8) * SW + cw];
            unsigned up0 = Ps[r0 * SW + cw], up1 = Ps[(r0 + 8) * SW + cw];
            float2 g0 = __half22float2(*(__half2*)&ug0);
            float2 g1 = __half22float2(*(__half2*)&ug1);
            float2 p0 = __half22float2(*(__half2*)&up0);
            float2 p1 = __half22float2(*(__half2*)&up1);
            sg0 += d00 * g0.x + d01 * g0.y;  sp0 += d00 * p0.x + d01 * p0.y;
            sg1 += d10 * g1.x + d11 * g1.y;  sp1 += d10 * p1.x + d11 * p1.y;
        }
#pragma unroll
        for (int o = 1; o <= 2; o <<= 1) {
            sg0 += __shfl_xor_sync(0xffffffffu, sg0, o);
            sp0 += __shfl_xor_sync(0xffffffffu, sp0, o);
            sg1 += __shfl_xor_sync(0xffffffffu, sg1, o);
            sp1 += __shfl_xor_sync(0xffffffffu, sp1, o);
        }
        if (q == 0) {
            wb[w * 32 + oct * 2 + 0] = sg0;
            wb[w * 32 + oct * 2 + 1] = sp0;
            wb[w * 32 + (oct + 8) * 2 + 0] = sg1;
            wb[w * 32 + (oct + 8) * 2 + 1] = sp1;
        }
        __syncwarp();
        {
            const int rr = lane & 15;
            const int t = t0 + w * 16 + rr;
            const size_t n = (size_t)(nb0 + i);
            if (t < NT) {
                const float lin = g_lin[n * NT + t];
                if (lane < 16) g_sg[n * NT + t] = wb[w * 32 + rr * 2] + lin;
                else           g_sp[n * NT + t] = wb[w * 32 + rr * 2 + 1] + lin;
            }
        }
        __syncwarp();

        if (i + 1 < NBL) {
            unsigned* dst = smu + W_B0 + ((i + 1) & 1) * 8704 + row * SW + h * 32;
#pragma unroll
            for (int j = 0; j < 8; j++) *(uint4*)(dst + 4 * j) = pf[j];
        }
        __syncthreads();
    }
}

/* ===== K5b: lin[n,t] = elm[t] . Wr[n] + lbl_b[n] ===== */
__global__ __launch_bounds__(256) void k_lin(
    const float* __restrict__ Wr, const float* __restrict__ lb)
{
    __shared__ float As[16][64];
    __shared__ float Bs[16][64];
    const int tid = threadIdx.x;
    const int t0 = blockIdx.x * 64, n0 = blockIdx.y * 64;
    const int ar = tid >> 2, ac = (tid & 3) * 4;
    const float* arow = g_enc + (size_t)(t0 + ar) * ENCW + 640;
    const float* brow = Wr + (size_t)(n0 + ar) * NEL;
    const int ty = tid >> 4, tx = tid & 15;
    float acc[4][4] = {};
    for (int k0 = 0; k0 < NEL; k0 += 16) {
        float4 av = *(const float4*)(arow + k0 + ac);
        float4 bv = *(const float4*)(brow + k0 + ac);
        As[ac + 0][ar] = av.x; As[ac + 1][ar] = av.y;
        As[ac + 2][ar] = av.z; As[ac + 3][ar] = av.w;
        Bs[ac + 0][ar] = bv.x; Bs[ac + 1][ar] = bv.y;
        Bs[ac + 2][ar] = bv.z; Bs[ac + 3][ar] = bv.w;
        __syncthreads();
#pragma unroll
        for (int k = 0; k < 16; k++) {
            float a[4], bb[4];
#pragma unroll
            for (int i = 0; i < 4; i++) a[i]  = As[k][ty * 4 + i];
#pragma unroll
            for (int j = 0; j < 4; j++) bb[j] = Bs[k][tx * 4 + j];
#pragma unroll
            for (int i = 0; i < 4; i++)
#pragma unroll
                for (int j = 0; j < 4; j++) acc[i][j] += a[i] * bb[j];
        }
        __syncthreads();
    }
#pragma unroll
    for (int i = 0; i < 4; i++) {
        int t = t0 + ty * 4 + i;
#pragma unroll
        for (int j = 0; j < 4; j++) {
            int nn = n0 + tx * 4 + j;
            g_lin[(size_t)nn * NT + t] = acc[i][j] + lb[nn];
        }
    }
}

/* ===== K6: label log-softmax over n + max over n (lin pre-folded) ===== */
__global__ __launch_bounds__(256) void k_lbl_reduce(
    const int* __restrict__ elabels, float* __restrict__ out)
{
    __shared__ float red[256];
    const int t = blockIdx.x * 256 + threadIdx.x;
    float contrib = 0.f;
    if (t < NT) {
        int b = t / L1, l = t % L1;
        int lab = (l == 0) ? 0 : elabels[b * NL + l - 1];
        float mg = -1e30f, sg = 0.f, mp = -1e30f, xlab = 0.f;
        for (int n = 0; n < NLB; n++) {
            float xg = g_sg[(size_t)n * NT + t];
            float xp = g_sp[(size_t)n * NT + t];
            if (n == lab) xlab = xg;
            if (xg > mg) { sg = sg * fexp(mg - xg) + 1.f; mg = xg; }
            else           sg += fexp(xg - mg);
            mp = fmaxf(mp, xp);
        }
        float ll = xlab - (mg + logf(sg));
        if (l >= 1) {
            contrib = -ll;
            out[OUT_PL + (size_t)b * NL + l - 1] = mp;
        }
    }
    red[threadIdx.x] = contrib;
    __syncthreads();
    for (int s = 128; s; s >>= 1) {
        if (threadIdx.x < s) red[threadIdx.x] += red[threadIdx.x + s];
        __syncthreads();
    }
    if (!threadIdx.x) g_partB[blockIdx.x] = red[0];
}

/* ===== K7: labels1 output + deterministic NLL finalize ===== */
__global__ __launch_bounds__(256) void k_final(
    const int* __restrict__ elabels, float* __restrict__ out)
{
    const int i = blockIdx.x * 256 + threadIdx.x;
    if (i < NT) {
        int b = i / L1, l = i % L1;
        out[OUT_LB + i] = (l == 0) ? 0.f : (float)elabels[b * NL + l - 1];
    }
    if (i == 0) {
        float s = 0.f;
        for (int k = 0; k < 17 * 64; k++) s += g_partA[k];
        out[OUT_NN] = s;
        float s2 = 0.f;
        for (int k = 0; k < 129; k++) s2 += g_partB[k];
        out[OUT_LN] = s2;
    }
}

extern "C" void kernel_launch(void* const* d_in, const int* in_sizes, int n_in,
                              void* d_out, int out_size)
{
    const float* mem    = (const float*)d_in[0];
    const int*   eheads = (const int*)d_in[1];
    const int*   elabs  = (const int*)d_in[2];
    const int*   mask   = (const int*)d_in[4];
    const float* sent   = (const float*)d_in[5];
    const float* Wenh = (const float*)d_in[6];  const float* benh = (const float*)d_in[7];
    const float* Wenm = (const float*)d_in[8];  const float* benm = (const float*)d_in[9];
    const float* Welh = (const float*)d_in[10]; const float* belh = (const float*)d_in[11];
    const float* Welm = (const float*)d_in[12]; const float* belm = (const float*)d_in[13];
    const float* baU  = (const float*)d_in[14];
    const float* baWd = (const float*)d_in[15];
    const float* baWe = (const float*)d_in[16];
    const float* bab  = (const float*)d_in[17];
    const float* lU   = (const float*)d_in[18];
    const float* lWl  = (const float*)d_in[19];
    const float* lWr  = (const float*)d_in[20];
    const float* lb   = (const float*)d_in[21];
    float* out = (float*)d_out;

    cudaFuncSetAttribute(k_bilin_mma, cudaFuncAttributeMaxDynamicSharedMemorySize, SMB2_BYTES);
    cudaFuncSetAttribute(k_enc_mma, cudaFuncAttributeMaxDynamicSharedMemorySize, SME3_BYTES);
    cudaFuncSetAttribute(k_tmp_mma, cudaFuncAttributeMaxDynamicSharedMemorySize, SME3_BYTES);
    cudaFuncSetAttribute(k_ns_mma,  cudaFuncAttributeMaxDynamicSharedMemorySize, SME3_BYTES);

    k_trans<<<1504, 256>>>(Wenh, Wenm, Welh, Welm, benh, benm, belh, belm, baU);
    k_uh<<<2048, 256>>>(lU);
    k_msplit<<<53352, 256>>>(mem, sent);
    k_enc_mma<<<dim3(257, 6), 256, SME3_BYTES>>>();
    k_tmp_mma<<<dim3(257, 2), 256, SME3_BYTES>>>();
    k_dotvec<<<4104, 256>>>(baWd, baWe);
    k_ns_mma<<<dim3(4, 4, 64), 256, SME3_BYTES>>>(bab);
    k_strip<<<8200, 256>>>(bab);
    k_node_reduce<<<dim3(17, 64), 256>>>(eheads, mask, out);
    k_lin<<<dim3(513, 2), 256>>>(lWr, lb);
    k_bilin_mma<<<dim3(NTILES, 8), 256, SMB2_BYTES>>>(lWl, eheads);
    k_lbl_reduce<<<129, 256>>>(elabs, out);
    k_final<<<129, 256>>>(elabs, out);
}

// round 16
// speedup vs baseline: 4.4215x; 1.0392x over previous
#include <cuda_runtime.h>
#include <cuda_fp16.h>

#define NB   64
#define NL   512
#define NH   400
#define NHP  416
#define NEN  256
#define NEL  128
#define NLB  128
#define L1   513
#define NT   (NB * L1)      /* 32832 */
#define NTILES 257

#define OUT_PH 0
#define OUT_PL 32768
#define OUT_LB 65536
#define OUT_NN 98368
#define OUT_LN 98369

/* -------- scratch (device globals) -------- */
__device__ float  g_dh[NT];
__device__ float  g_em[NT];
__device__ float  g_S[(size_t)NB * L1 * L1];
__device__ int    g_pred[NT];
__device__ float  g_sg[(size_t)NLB * NT];
__device__ float  g_sp[(size_t)NLB * NT];
__device__ float  g_lin[(size_t)NLB * NT];
__device__ float  g_partA[17 * 64];
__device__ float  g_partB[129];
__device__ float  g_biasC[768];
__device__ __half g_memh[(size_t)NT * NHP];
__device__ __half g_meml[(size_t)NT * NHP];
__device__ __half g_WTh[768 * NHP];
__device__ __half g_WTl[768 * NHP];
__device__ __half g_baUTh[NEN * NEN];
__device__ __half g_baUTl[NEN * NEN];
__device__ __half g_enhh[(size_t)NT * NEN];
__device__ __half g_enhl[(size_t)NT * NEN];
__device__ __half g_enmh[(size_t)NT * NEN];
__device__ __half g_enml[(size_t)NT * NEN];
__device__ __half g_tmph[(size_t)NT * NEN];
__device__ __half g_tmpl[(size_t)NT * NEN];
__device__ __half g_Uh[(size_t)NLB * NEL * NEL];
__device__ __half g_elhh[(size_t)NT * NEL];
__device__ __half g_elmh[(size_t)NT * NEL];

__device__ __forceinline__ float elu1(float x) { return x > 0.f ? x : expm1f(x); }
__device__ __forceinline__ float logmask(int s) {
    return s == 0 ? -103.27893f : (s == 1 ? 0.f : 0.69314718f);
}
/* FMA-pipe exp (arg <= 0 at call sites) */
__device__ __forceinline__ float fexp(float x) {
    x = fmaxf(x, -87.0f);
    float y = x * 1.4426950408889634f;
    float z = y + 12582912.0f;
    int   n = __float_as_int(z) - 0x4B400000;
    float f = y - (z - 12582912.0f);
    float p = 1.5403530e-4f;
    p = fmaf(p, f, 1.3333558e-3f);
    p = fmaf(p, f, 9.6181291e-3f);
    p = fmaf(p, f, 5.5504109e-2f);
    p = fmaf(p, f, 2.4022651e-1f);
    p = fmaf(p, f, 6.9314718e-1f);
    p = fmaf(p, f, 1.0f);
    return p * __int_as_float((n + 127) << 23);
}
__device__ __forceinline__ void fsplit(float v, __half& h, __half& l) {
    h = __float2half_rn(v);
    l = __float2half_rn(v - __half2float(h));
}
__device__ __forceinline__ void mma_f16(float* c, unsigned a0, unsigned a1,
                                        unsigned a2, unsigned a3,
                                        unsigned b0, unsigned b1) {
    asm volatile(
        "mma.sync.aligned.m16n8k16.row.col.f32.f16.f16.f32 "
        "{%0,%1,%2,%3}, {%4,%5,%6,%7}, {%8,%9}, {%0,%1,%2,%3};\n"
        : "+f"(c[0]), "+f"(c[1]), "+f"(c[2]), "+f"(c[3])
        : "r"(a0), "r"(a1), "r"(a2), "r"(a3), "r"(b0), "r"(b1));
}
__device__ __forceinline__ unsigned smem_u32(const void* p) {
    unsigned a;
    asm("{ .reg .u64 t; cvta.to.shared.u64 t, %1; cvt.u32.u64 %0, t; }" : "=r"(a) : "l"(p));
    return a;
}
__device__ __forceinline__ void cpa16(unsigned dst, const void* src) {
    asm volatile("cp.async.cg.shared.global [%0], [%1], 16;" :: "r"(dst), "l"(src));
}
#define CP_COMMIT() asm volatile("cp.async.commit_group;" ::: "memory")
#define CP_WAIT1()  asm volatile("cp.async.wait_group 1;"  ::: "memory")
#define CP_WAIT0()  asm volatile("cp.async.wait_group 0;"  ::: "memory")

/* ===== K0a: weight transposes + fp16 hi/lo split ===== */
__global__ __launch_bounds__(256) void k_trans(
    const float* __restrict__ Wenh, const float* __restrict__ Wenm,
    const float* __restrict__ Welh, const float* __restrict__ Welm,
    const float* __restrict__ benh, const float* __restrict__ benm,
    const float* __restrict__ belh, const float* __restrict__ belm,
    const float* __restrict__ baU)
{
    const int i = blockIdx.x * 256 + threadIdx.x;
    if (i < 768 * NHP) {
        const int k = i / 768, j = i % 768;
        float v = 0.f;
        if (k < NH) {
            if (j < 256)      v = Wenh[k * NEN + j];
            else if (j < 512) v = Wenm[k * NEN + j - 256];
            else if (j < 640) v = Welh[k * NEL + j - 512];
            else              v = Welm[k * NEL + j - 640];
        }
        __half h, l; fsplit(v, h, l);
        g_WTh[(size_t)j * NHP + k] = h;
        g_WTl[(size_t)j * NHP + k] = l;
        if (k == 0)
            g_biasC[j] = (j < 256) ? benh[j] : (j < 512) ? benm[j - 256]
                       : (j < 640) ? belh[j - 512] : belm[j - 640];
    } else {
        const int i2 = i - 768 * NHP;
        if (i2 < NEN * NEN) {
            const int k = i2 / NEN, n = i2 % NEN;
            __half h, l; fsplit(baU[k * NEN + n], h, l);
            g_baUTh[n * NEN + k] = h;
            g_baUTl[n * NEN + k] = l;
        }
    }
}

/* ===== K0b: lbl_U -> fp16 ===== */
__global__ __launch_bounds__(256) void k_uh(const float* __restrict__ U)
{
    const size_t base = ((size_t)blockIdx.x * 256 + threadIdx.x) * 4;
    float4 v = *(const float4*)(U + base);
    __half2 h0 = __floats2half2_rn(v.x, v.y);
    __half2 h1 = __floats2half2_rn(v.z, v.w);
    uint2 wv; wv.x = *(unsigned*)&h0; wv.y = *(unsigned*)&h1;
    *(uint2*)&g_Uh[base] = wv;
}

/* ===== K0c: [sentinel;mem] -> fp16 hi/lo ===== */
__global__ __launch_bounds__(256) void k_msplit(
    const float* __restrict__ mem, const float* __restrict__ sent)
{
    const size_t idx = (size_t)blockIdx.x * 256 + threadIdx.x;
    const int t = (int)(idx / NHP), k = (int)(idx % NHP);
    const int b = t / L1, l = t - b * L1;
    float v = 0.f;
    if (k < NH) v = (l == 0) ? sent[k] : mem[((size_t)b * NL + (l - 1)) * NH + k];
    __half h, lo; fsplit(v, h, lo);
    g_memh[idx] = h; g_meml[idx] = lo;
}

/* ===== pipelined fp16 GEMM pieces: 128x128 tile, K-chunk 32, 2 bufs.
   Warp tile 32 rows x 64 cols. ===== */
#define HSTR2 20
#define ABYTES 10240
#define BUFBYTES 40960
#define SME3_BYTES (2 * BUFBYTES)

__device__ __forceinline__ void stage_async(
    unsigned sb, int buf, int row, int h,
    const __half* aH, const __half* aL,
    const __half* bH, const __half* bL, int k0)
{
    const unsigned d = sb + buf * BUFBYTES + row * 80 + h * 32;
    const __half* s;
    s = aH + k0 + h * 16;
    cpa16(d, s); cpa16(d + 16, s + 8);
    s = aL + k0 + h * 16;
    cpa16(d + ABYTES, s); cpa16(d + ABYTES + 16, s + 8);
    s = bH + k0 + h * 16;
    cpa16(d + 2 * ABYTES, s); cpa16(d + 2 * ABYTES + 16, s + 8);
    s = bL + k0 + h * 16;
    cpa16(d + 3 * ABYTES, s); cpa16(d + 3 * ABYTES + 16, s + 8);
}
__device__ __forceinline__ void stage_async2(
    unsigned sb, int buf, int row, int h,
    const __half* aH,
    const __half* bH, const __half* bL, int k0)
{
    const unsigned d = sb + buf * BUFBYTES + row * 80 + h * 32;
    const __half* s;
    s = aH + k0 + h * 16;
    cpa16(d, s); cpa16(d + 16, s + 8);
    s = bH + k0 + h * 16;
    cpa16(d + 2 * ABYTES, s); cpa16(d + 2 * ABYTES + 16, s + 8);
    s = bL + k0 + h * 16;
    cpa16(d + 3 * ABYTES, s); cpa16(d + 3 * ABYTES + 16, s + 8);
}

/* 3-term chunk: warp tile 32x64 */
__device__ __forceinline__ void gemm3h_chunk32(
    const unsigned* base, int R, int C, int q, int oct,
    float acc0[8][4], float acc1[8][4])
{
    const unsigned* Ah = base;
    const unsigned* Al = base + ABYTES / 4;
    const unsigned* Bh = base + 2 * (ABYTES / 4);
    const unsigned* Bl = base + 3 * (ABYTES / 4);
#pragma unroll
    for (int ks = 0; ks < 2; ks++) {
        const int kw = ks * 8 + q;
        const int ra = (R + oct) * HSTR2 + kw;
        const unsigned ah0 = Ah[ra],                  ah1 = Ah[ra + 8 * HSTR2];
        const unsigned ah2 = Ah[ra + 4],              ah3 = Ah[ra + 8 * HSTR2 + 4];
        const unsigned ah4 = Ah[ra + 16 * HSTR2],     ah5 = Ah[ra + 24 * HSTR2];
        const unsigned ah6 = Ah[ra + 16 * HSTR2 + 4], ah7 = Ah[ra + 24 * HSTR2 + 4];
        const unsigned al0 = Al[ra],                  al1 = Al[ra + 8 * HSTR2];
        const unsigned al2 = Al[ra + 4],              al3 = Al[ra + 8 * HSTR2 + 4];
        const unsigned al4 = Al[ra + 16 * HSTR2],     al5 = Al[ra + 24 * HSTR2];
        const unsigned al6 = Al[ra + 16 * HSTR2 + 4], al7 = Al[ra + 24 * HSTR2 + 4];
#pragma unroll
        for (int nt = 0; nt < 8; nt++) {
            const int cb = (C + nt * 8 + oct) * HSTR2 + kw;
            const unsigned bh0 = Bh[cb], bh1 = Bh[cb + 4];
            const unsigned bl0 = Bl[cb], bl1 = Bl[cb + 4];
            mma_f16(acc0[nt], ah0, ah1, ah2, ah3, bh0, bh1);
            mma_f16(acc0[nt], ah0, ah1, ah2, ah3, bl0, bl1);
            mma_f16(acc0[nt], al0, al1, al2, al3, bh0, bh1);
            mma_f16(acc1[nt], ah4, ah5, ah6, ah7, bh0, bh1);
            mma_f16(acc1[nt], ah4, ah5, ah6, ah7, bl0, bl1);
            mma_f16(acc1[nt], al4, al5, al6, al7, bh0, bh1);
        }
    }
}
/* 2-term chunk */
__device__ __forceinline__ void gemm2h_chunk32(
    const unsigned* base, int R, int C, int q, int oct,
    float acc0[8][4], float acc1[8][4])
{
    const unsigned* Ah = base;
    const unsigned* Bh = base + 2 * (ABYTES / 4);
    const unsigned* Bl = base + 3 * (ABYTES / 4);
#pragma unroll
    for (int ks = 0; ks < 2; ks++) {
        const int kw = ks * 8 + q;
        const int ra = (R + oct) * HSTR2 + kw;
        const unsigned ah0 = Ah[ra],                  ah1 = Ah[ra + 8 * HSTR2];
        const unsigned ah2 = Ah[ra + 4],              ah3 = Ah[ra + 8 * HSTR2 + 4];
        const unsigned ah4 = Ah[ra + 16 * HSTR2],     ah5 = Ah[ra + 24 * HSTR2];
        const unsigned ah6 = Ah[ra + 16 * HSTR2 + 4], ah7 = Ah[ra + 24 * HSTR2 + 4];
#pragma unroll
        for (int nt = 0; nt < 8; nt++) {
            const int cb = (C + nt * 8 + oct) * HSTR2 + kw;
            const unsigned bh0 = Bh[cb], bh1 = Bh[cb + 4];
            const unsigned bl0 = Bl[cb], bl1 = Bl[cb + 4];
            mma_f16(acc0[nt], ah0, ah1, ah2, ah3, bh0, bh1);
            mma_f16(acc0[nt], ah0, ah1, ah2, ah3, bl0, bl1);
            mma_f16(acc1[nt], ah4, ah5, ah6, ah7, bh0, bh1);
            mma_f16(acc1[nt], ah4, ah5, ah6, ah7, bl0, bl1);
        }
    }
}

/* ===== K1: encoder GEMM + ELU, pipelined (fp16-only outputs) ===== */
__global__ __launch_bounds__(256) void k_enc_mma()
{
    extern __shared__ unsigned smu[];
    const unsigned sb = smem_u32(smu);
    const int tid = threadIdx.x, lane = tid & 31, w = tid >> 5;
    const int q = lane & 3, oct = lane >> 2;
    const int Rw = (w & 3) * 32, Cw = (w >> 2) * 64;
    const int t0 = blockIdx.x * 128;
    const int nb = blockIdx.y * 128;
    const bool full = nb < 512;
    const int row = tid >> 1, h = tid & 1;
    const int ta = t0 + row;
    const bool aval = ta < NT;
    const __half* aH = g_memh + (size_t)(aval ? ta : 0) * NHP;
    const __half* aL = g_meml + (size_t)(aval ? ta : 0) * NHP;
    const __half* bH = g_WTh + (size_t)(nb + row) * NHP;
    const __half* bL = g_WTl + (size_t)(nb + row) * NHP;

    float acc0[8][4] = {}, acc1[8][4] = {};
    if (full) stage_async(sb, 0, row, h, aH, aL, bH, bL, 0);
    else      stage_async2(sb, 0, row, h, aH, bH, bL, 0);
    CP_COMMIT();
    for (int c = 0; c < 13; c++) {
        if (c + 1 < 13) {
            if (full) stage_async(sb, (c + 1) & 1, row, h, aH, aL, bH, bL, (c + 1) * 32);
            else      stage_async2(sb, (c + 1) & 1, row, h, aH, bH, bL, (c + 1) * 32);
            CP_COMMIT();
            CP_WAIT1();
        } else CP_WAIT0();
        __syncthreads();
        if (full) gemm3h_chunk32(smu + (c & 1) * (BUFBYTES / 4), Rw, Cw, q, oct, acc0, acc1);
        else      gemm2h_chunk32(smu + (c & 1) * (BUFBYTES / 4), Rw, Cw, q, oct, acc0, acc1);
        __syncthreads();
    }

#pragma unroll
    for (int half = 0; half < 2; half++) {
        float (*A)[4] = half ? acc1 : acc0;
#pragma unroll
        for (int rr = 0; rr < 2; rr++) {
            const int t = t0 + Rw + oct + half * 16 + rr * 8;
            if (t >= NT) continue;
#pragma unroll
            for (int nt = 0; nt < 8; nt++) {
                const int c = Cw + nt * 8 + q * 2;
                const float v0 = elu1(A[nt][rr * 2 + 0] + g_biasC[nb + c]);
                const float v1 = elu1(A[nt][rr * 2 + 1] + g_biasC[nb + c + 1]);
                __half h0, l0, h1, l1;
                fsplit(v0, h0, l0); fsplit(v1, h1, l1);
                if (nb < 256) {
                    const int col = nb + c;
                    *(__half2*)&g_enhh[(size_t)t * NEN + col] = __halves2half2(h0, h1);
                    *(__half2*)&g_enhl[(size_t)t * NEN + col] = __halves2half2(l0, l1);
                } else if (nb < 512) {
                    const int col = nb - 256 + c;
                    *(__half2*)&g_enmh[(size_t)t * NEN + col] = __halves2half2(h0, h1);
                    *(__half2*)&g_enml[(size_t)t * NEN + col] = __halves2half2(l0, l1);
                } else {
                    const int col = nb - 512 + c;
                    if (col < 128)
                        *(__half2*)&g_elhh[(size_t)t * NEL + col] = __halves2half2(h0, h1);
                    else
                        *(__half2*)&g_elmh[(size_t)t * NEL + col - 128] = __halves2half2(h0, h1);
                }
            }
        }
    }
}

/* ===== K2: tmp = enh @ ba_U, pipelined 3xfp16 ===== */
__global__ __launch_bounds__(256) void k_tmp_mma()
{
    extern __shared__ unsigned smu[];
    const unsigned sb = smem_u32(smu);
    const int tid = threadIdx.x, lane = tid & 31, w = tid >> 5;
    const int q = lane & 3, oct = lane >> 2;
    const int Rw = (w & 3) * 32, Cw = (w >> 2) * 64;
    const int t0 = blockIdx.x * 128;
    const int nb = blockIdx.y * 128;
    const int row = tid >> 1, h = tid & 1;
    const int ta = t0 + row;
    const bool aval = ta < NT;
    const __half* aH = g_enhh + (size_t)(aval ? ta : 0) * NEN;
    const __half* aL = g_enhl + (size_t)(aval ? ta : 0) * NEN;
    const __half* bH = g_baUTh + (size_t)(nb + row) * NEN;
    const __half* bL = g_baUTl + (size_t)(nb + row) * NEN;

    float acc0[8][4] = {}, acc1[8][4] = {};
    stage_async(sb, 0, row, h, aH, aL, bH, bL, 0);
    CP_COMMIT();
    for (int c = 0; c < 8; c++) {
        if (c + 1 < 8) {
            stage_async(sb, (c + 1) & 1, row, h, aH, aL, bH, bL, (c + 1) * 32);
            CP_COMMIT();
            CP_WAIT1();
        } else CP_WAIT0();
        __syncthreads();
        gemm3h_chunk32(smu + (c & 1) * (BUFBYTES / 4), Rw, Cw, q, oct, acc0, acc1);
        __syncthreads();
    }

#pragma unroll
    for (int half = 0; half < 2; half++) {
        float (*A)[4] = half ? acc1 : acc0;
#pragma unroll
        for (int rr = 0; rr < 2; rr++) {
            const int t = t0 + Rw + oct + half * 16 + rr * 8;
            if (t >= NT) continue;
#pragma unroll
            for (int nt = 0; nt < 8; nt++) {
                const int c = Cw + nt * 8 + q * 2;
                __half h0, l0, h1, l1;
                fsplit(A[nt][rr * 2 + 0], h0, l0);
                fsplit(A[nt][rr * 2 + 1], h1, l1);
                *(__half2*)&g_tmph[(size_t)t * NEN + nb + c] = __halves2half2(h0, h1);
                *(__half2*)&g_tmpl[(size_t)t * NEN + nb + c] = __halves2half2(l0, l1);
            }
        }
    }
}

/* ===== K3: node scores S[b,h,m] for h,m < 512 ===== */
__global__ __launch_bounds__(256) void k_ns_mma(const float* __restrict__ bab)
{
    extern __shared__ unsigned smu[];
    const unsigned sb = smem_u32(smu);
    const int tid = threadIdx.x, lane = tid & 31, w = tid >> 5;
    const int q = lane & 3, oct = lane >> 2;
    const int Rw = (w & 3) * 32, Cw = (w >> 2) * 64;
    const int b = blockIdx.z;
    const int h0 = blockIdx.x * 128, m0 = blockIdx.y * 128;
    const int row = tid >> 1, h = tid & 1;
    const __half* aH = g_tmph + (size_t)(b * L1 + h0 + row) * NEN;
    const __half* aL = g_tmpl + (size_t)(b * L1 + h0 + row) * NEN;
    const __half* bH = g_enmh + (size_t)(b * L1 + m0 + row) * NEN;
    const __half* bL = g_enml + (size_t)(b * L1 + m0 + row) * NEN;

    float acc0[8][4] = {}, acc1[8][4] = {};
    stage_async(sb, 0, row, h, aH, aL, bH, bL, 0);
    CP_COMMIT();
    for (int c = 0; c < 8; c++) {
        if (c + 1 < 8) {
            stage_async(sb, (c + 1) & 1, row, h, aH, aL, bH, bL, (c + 1) * 32);
            CP_COMMIT();
            CP_WAIT1();
        } else CP_WAIT0();
        __syncthreads();
        gemm3h_chunk32(smu + (c & 1) * (BUFBYTES / 4), Rw, Cw, q, oct, acc0, acc1);
        __syncthreads();
    }

    const float bb0 = __ldg(bab);
    float* Sb = g_S + (size_t)b * L1 * L1;
#pragma unroll
    for (int half = 0; half < 2; half++) {
        float (*A)[4] = half ? acc1 : acc0;
#pragma unroll
        for (int rr = 0; rr < 2; rr++) {
            const int hh = h0 + Rw + oct + half * 16 + rr * 8;
            const float dh = g_dh[b * L1 + hh];
#pragma unroll
            for (int nt = 0; nt < 8; nt++) {
                const int m = m0 + Cw + nt * 8 + q * 2;
                const float em0 = g_em[b * L1 + m];
                const float em1 = g_em[b * L1 + m + 1];
                Sb[(size_t)hh * L1 + m]     = A[nt][rr * 2 + 0] + dh + em0 + bb0;
                Sb[(size_t)hh * L1 + m + 1] = A[nt][rr * 2 + 1] + dh + em1 + bb0;
            }
        }
    }
}

/* ===== K3b: boundary strips ===== */
__global__ __launch_bounds__(256) void k_strip(const float* __restrict__ bab)
{
    const int gw = (blockIdx.x * 256 + threadIdx.x) >> 5;
    const int lane = threadIdx.x & 31;
    if (gw >= NB * 1025) return;
    const int b = gw / 1025, idx = gw % 1025;
    const int h = (idx < 513) ? 512 : idx - 513;
    const int m = (idx < 513) ? idx : 512;
    const __half* th = g_tmph + (size_t)(b * L1 + h) * NEN;
    const __half* tl = g_tmpl + (size_t)(b * L1 + h) * NEN;
    const __half* eh = g_enmh + (size_t)(b * L1 + m) * NEN;
    const __half* el = g_enml + (size_t)(b * L1 + m) * NEN;
    float s = 0.f;
#pragma unroll
    for (int k = lane; k < NEN; k += 32) {
        float a = __half2float(th[k]) + __half2float(tl[k]);
        float c = __half2float(eh[k]) + __half2float(el[k]);
        s += a * c;
    }
#pragma unroll
    for (int o = 16; o; o >>= 1) s += __shfl_xor_sync(0xffffffffu, s, o);
    if (!lane)
        g_S[((size_t)b * L1 + h) * L1 + m] =
            s + g_dh[b * L1 + h] + g_em[b * L1 + m] + __ldg(bab);
}

/* ==== K2b: dh/em from fp16 hi+lo (fp32-reconstructed) ==== */
__global__ __launch_bounds__(256) void k_dotvec(
    const float* __restrict__ Wd, const float* __restrict__ We)
{
    const int gw = (blockIdx.x * blockDim.x + threadIdx.x) >> 5;
    const int lane = threadIdx.x & 31;
    if (gw >= NT) return;
    const __half2* hh = (const __half2*)(g_enhh + (size_t)gw * NEN);
    const __half2* hl = (const __half2*)(g_enhl + (size_t)gw * NEN);
    const __half2* mh = (const __half2*)(g_enmh + (size_t)gw * NEN);
    const __half2* ml = (const __half2*)(g_enml + (size_t)gw * NEN);
    float s1 = 0.f, s2 = 0.f;
#pragma unroll
    for (int i = 0; i < 4; i++) {
        const int kk = lane + i * 32;
        float2 a = __half22float2(hh[kk]);
        float2 b = __half22float2(hl[kk]);
        float2 c = __half22float2(mh[kk]);
        float2 d = __half22float2(ml[kk]);
        const float w0 = Wd[kk * 2], w1 = Wd[kk * 2 + 1];
        const float v0 = We[kk * 2], v1 = We[kk * 2 + 1];
        s1 += (a.x + b.x) * w0 + (a.y + b.y) * w1;
        s2 += (c.x + d.x) * v0 + (c.y + d.y) * v1;
    }
#pragma unroll
    for (int o = 16; o; o >>= 1) {
        s1 += __shfl_xor_sync(0xffffffffu, s1, o);
        s2 += __shfl_xor_sync(0xffffffffu, s2, o);
    }
    if (!lane) { g_dh[gw] = s1; g_em[gw] = s2; }
}

/* ==== K4: per-column logsumexp + gold pick + decode argmax ==== */
__global__ __launch_bounds__(256) void k_node_reduce(
    const int* __restrict__ eheads, const int* __restrict__ mask,
    float* __restrict__ out)
{
    const int b = blockIdx.y;
    const int m0 = blockIdx.x * 32;
    const int tid = threadIdx.x, lane = tid & 31, w = tid >> 5;
    __shared__ int mk[L1];
    __shared__ float s_max[8][32], s_sum[8][32], s_bv[8][32];
    __shared__ int s_bi[8][32];
    for (int i = tid; i < L1; i += 256) mk[i] = (i == 0) ? 0 : mask[b * NL + i - 1];
    __syncthreads();

    const int m = m0 + lane;
    const bool mv = m < L1;
    const int msafe = mv ? m : (L1 - 1);
    const int mm_ = mk[msafe];
    const float* Sb = g_S + (size_t)b * L1 * L1;

    float rmax = -1e30f, rsum = 0.f, bv = -1e30f;
    int bi = 0x7fffffff;
    for (int h = w; h < L1; h += 8) {
        float s = Sb[(size_t)h * L1 + msafe];
        int mh = mk[h];
        float x = s + logmask(mh + mm_);
        if (x > rmax) { rsum = rsum * fexp(rmax - x) + 1.f; rmax = x; }
        else            rsum += fexp(x - rmax);
        float dv = s + (1.f - (float)mh) * (-1e8f);
        if (h != msafe && dv > bv) { bv = dv; bi = h; }
    }
    s_max[w][lane] = rmax; s_sum[w][lane] = rsum;
    s_bv[w][lane] = bv;    s_bi[w][lane] = bi;
    __syncthreads();

    if (w == 0) {
        float tm = -1e30f;
#pragma unroll
        for (int i = 0; i < 8; i++) tm = fmaxf(tm, s_max[i][lane]);
        float ts = 0.f;
#pragma unroll
        for (int i = 0; i < 8; i++) ts += s_sum[i][lane] * fexp(s_max[i][lane] - tm);
        float lse = tm + logf(ts);
        int gh = (msafe == 0) ? 0 : eheads[b * NL + msafe - 1];
        float xg = Sb[(size_t)gh * L1 + msafe] + logmask(mk[gh] + mm_);
        float bbv = -1e30f; int bbi = 0x7fffffff;
#pragma unroll
        for (int i = 0; i < 8; i++) {
            float v = s_bv[i][lane]; int ix = s_bi[i][lane];
            if (v > bbv || (v == bbv && ix < bbi)) { bbv = v; bbi = ix; }
        }
        float contrib = 0.f;
        if (mv) {
            g_pred[b * L1 + m] = bbi;
            if (m >= 1) {
                out[OUT_PH + (size_t)b * NL + m - 1] = (float)bbi;
                contrib = -(xg - lse);
            }
        }
#pragma unroll
        for (int o = 16; o; o >>= 1) contrib += __shfl_xor_sync(0xffffffffu, contrib, o);
        if (lane == 0) g_partA[blockIdx.y * 17 + blockIdx.x] = contrib;
    }
}

/* ===== K5: label bilinear, fp16 m16n8k16, 16 labels per CTA ===== */
#define NBL  16
#define SW   68
#define W_AS 0
#define W_GS 8704
#define W_PS 17408
#define W_B0 26112
#define W_WL 43520
#define W_WB 45568
#define SMB2_BYTES ((45568 + 256) * 4)

__global__ __launch_bounds__(256) void k_bilin_mma(
    const float* __restrict__ Wl, const int* __restrict__ eheads)
{
    extern __shared__ unsigned smu[];
    float* Wls = (float*)(smu + W_WL);
    float* wb  = (float*)(smu + W_WB);
    const int tid = threadIdx.x, lane = tid & 31, w = tid >> 5;
    const int q = lane & 3, oct = lane >> 2;
    const int nb0 = blockIdx.y * NBL;
    const int t0 = blockIdx.x * 128;

    const int row = tid >> 1, h = tid & 1;
    const int ts = t0 + row;
    const bool tv = ts < NT;
    const int tc = tv ? ts : 0;

    {
        unsigned* dst = smu + W_AS + row * SW + h * 32;
        if (tv) {
            const uint4* src = (const uint4*)(g_elmh + (size_t)tc * NEL + h * 64);
#pragma unroll
            for (int j = 0; j < 8; j++) *(uint4*)(dst + 4 * j) = src[j];
        } else {
            uint4 z = make_uint4(0, 0, 0, 0);
#pragma unroll
            for (int j = 0; j < 8; j++) *(uint4*)(dst + 4 * j) = z;
        }
    }
    {
        const int bb = tc / L1, ll = tc - bb * L1;
        const int hr = h ? g_pred[tc] : ((ll == 0) ? 0 : eheads[bb * NL + ll - 1]);
        const uint4* src = (const uint4*)(g_elhh + (size_t)(bb * L1 + hr) * NEL);
        unsigned* dst = smu + (h ? W_PS : W_GS) + row * SW;
#pragma unroll
        for (int j = 0; j < 16; j++) *(uint4*)(dst + 4 * j) = src[j];
    }
    for (int idx = tid; idx < NBL * 128; idx += 256)
        Wls[idx] = Wl[nb0 * 128 + idx];
    {
        const uint4* src = (const uint4*)(g_Uh + ((size_t)nb0 * NEL + row) * NEL + h * 64);
        unsigned* dst = smu + W_B0 + row * SW + h * 32;
#pragma unroll
        for (int j = 0; j < 8; j++) *(uint4*)(dst + 4 * j) = src[j];
    }
    __syncthreads();

    const int r0 = w * 16 + oct;
    const unsigned* As = smu + W_AS;
    const unsigned* Gs = smu + W_GS;
    const unsigned* Ps = smu + W_PS;

    /* hoist A fragments into registers (constant across the 16 labels) */
    unsigned af[8][4];
#pragma unroll
    for (int ks = 0; ks < 8; ks++) {
        const int kw = ks * 8 + q;
        af[ks][0] = As[r0 * SW + kw];
        af[ks][1] = As[(r0 + 8) * SW + kw];
        af[ks][2] = As[r0 * SW + kw + 4];
        af[ks][3] = As[(r0 + 8) * SW + kw + 4];
    }

    for (int i = 0; i < NBL; i++) {
        uint4 pf[8];
        if (i + 1 < NBL) {
            const uint4* src = (const uint4*)(g_Uh + ((size_t)(nb0 + i + 1) * NEL + row) * NEL + h * 64);
#pragma unroll
            for (int j = 0; j < 8; j++) pf[j] = src[j];
        }
        const unsigned* Bs = smu + W_B0 + (i & 1) * 8704;

        float acc[16][4] = {};
#pragma unroll
        for (int ks = 0; ks < 8; ks++) {
            const int kw = ks * 8 + q;
#pragma unroll
            for (int nt = 0; nt < 16; nt++) {
                const int cb = (nt * 8 + oct) * SW + kw;
                mma_f16(acc[nt], af[ks][0], af[ks][1], af[ks][2], af[ks][3],
                        Bs[cb], Bs[cb + 4]);
            }
        }

        const float* Wln = Wls + i * 128;
        float sg0 = 0.f, sp0 = 0.f, sg1 = 0.f, sp1 = 0.f;
#pragma unroll
        for (int nt = 0; nt < 16; nt++) {
            const int ch = nt * 8 + 2 * q;
            const int cw = nt * 4 + q;
            const float w0 = Wln[ch], w1 = Wln[ch + 1];
            const float d00 = acc[nt][0] + w0, d01 = acc[nt][1] + w1;
            const float d10 = acc[nt][2] + w0, d11 = acc[nt][3] + w1;
            unsigned ug0 = Gs[r0 * SW + cw], ug1 = Gs[(r0 + 8) * SW + cw];
            unsigned up0 = Ps[r0 * SW + cw], up1 = Ps[(r0 + 8) * SW + cw];
            float2 g0 = __half22float2(*(__half2*)&ug0);
            float2 g1 = __half22float2(*(__half2*)&ug1);
            float2 p0 = __half22float2(*(__half2*)&up0);
            float2 p1 = __half22float2(*(__half2*)&up1);
            sg0 += d00 * g0.x + d01 * g0.y;  sp0 += d00 * p0.x + d01 * p0.y;
            sg1 += d10 * g1.x + d11 * g1.y;  sp1 += d10 * p1.x + d11 * p1.y;
        }
#pragma unroll
        for (int o = 1; o <= 2; o <<= 1) {
            sg0 += __shfl_xor_sync(0xffffffffu, sg0, o);
            sp0 += __shfl_xor_sync(0xffffffffu, sp0, o);
            sg1 += __shfl_xor_sync(0xffffffffu, sg1, o);
            sp1 += __shfl_xor_sync(0xffffffffu, sp1, o);
        }
        if (q == 0) {
            wb[w * 32 + oct * 2 + 0] = sg0;
            wb[w * 32 + oct * 2 + 1] = sp0;
            wb[w * 32 + (oct + 8) * 2 + 0] = sg1;
            wb[w * 32 + (oct + 8) * 2 + 1] = sp1;
        }
        __syncwarp();
        {
            const int rr = lane & 15;
            const int t = t0 + w * 16 + rr;
            const size_t n = (size_t)(nb0 + i);
            if (t < NT) {
                const float lin = g_lin[n * NT + t];
                if (lane < 16) g_sg[n * NT + t] = wb[w * 32 + rr * 2] + lin;
                else           g_sp[n * NT + t] = wb[w * 32 + rr * 2 + 1] + lin;
            }
        }
        __syncwarp();

        if (i + 1 < NBL) {
            unsigned* dst = smu + W_B0 + ((i + 1) & 1) * 8704 + row * SW + h * 32;
#pragma unroll
            for (int j = 0; j < 8; j++) *(uint4*)(dst + 4 * j) = pf[j];
        }
        __syncthreads();
    }
}

/* ===== K5b: lin[n,t] = elm[t] . Wr[n] + lbl_b[n] (elm fp16) ===== */
__global__ __launch_bounds__(256) void k_lin(
    const float* __restrict__ Wr, const float* __restrict__ lb)
{
    __shared__ float As[16][64];
    __shared__ float Bs[16][64];
    const int tid = threadIdx.x;
    const int t0 = blockIdx.x * 64, n0 = blockIdx.y * 64;
    const int ar = tid >> 2, ac = (tid & 3) * 4;
    const __half* arow = g_elmh + (size_t)(t0 + ar) * NEL;
    const float* brow = Wr + (size_t)(n0 + ar) * NEL;
    const int ty = tid >> 4, tx = tid & 15;
    float acc[4][4] = {};
    for (int k0 = 0; k0 < NEL; k0 += 16) {
        uint2 ua = *(const uint2*)(arow + k0 + ac);
        float2 f01 = __half22float2(*(__half2*)&ua.x);
        float2 f23 = __half22float2(*(__half2*)&ua.y);
        float4 bv = *(const float4*)(brow + k0 + ac);
        As[ac + 0][ar] = f01.x; As[ac + 1][ar] = f01.y;
        As[ac + 2][ar] = f23.x; As[ac + 3][ar] = f23.y;
        Bs[ac + 0][ar] = bv.x; Bs[ac + 1][ar] = bv.y;
        Bs[ac + 2][ar] = bv.z; Bs[ac + 3][ar] = bv.w;
        __syncthreads();
#pragma unroll
        for (int k = 0; k < 16; k++) {
            float a[4], bb[4];
#pragma unroll
            for (int i = 0; i < 4; i++) a[i]  = As[k][ty * 4 + i];
#pragma unroll
            for (int j = 0; j < 4; j++) bb[j] = Bs[k][tx * 4 + j];
#pragma unroll
            for (int i = 0; i < 4; i++)
#pragma unroll
                for (int j = 0; j < 4; j++) acc[i][j] += a[i] * bb[j];
        }
        __syncthreads();
    }
#pragma unroll
    for (int i = 0; i < 4; i++) {
        int t = t0 + ty * 4 + i;
#pragma unroll
        for (int j = 0; j < 4; j++) {
            int nn = n0 + tx * 4 + j;
            g_lin[(size_t)nn * NT + t] = acc[i][j] + lb[nn];
        }
    }
}

/* ===== K6: label log-softmax over n + max over n ===== */
__global__ __launch_bounds__(256) void k_lbl_reduce(
    const int* __restrict__ elabels, float* __restrict__ out)
{
    __shared__ float red[256];
    const int t = blockIdx.x * 256 + threadIdx.x;
    float contrib = 0.f;
    if (t < NT) {
        int b = t / L1, l = t % L1;
        int lab = (l == 0) ? 0 : elabels[b * NL + l - 1];
        float mg = -1e30f, sg = 0.f, mp = -1e30f, xlab = 0.f;
        for (int n = 0; n < NLB; n++) {
            float xg = g_sg[(size_t)n * NT + t];
            float xp = g_sp[(size_t)n * NT + t];
            if (n == lab) xlab = xg;
            if (xg > mg) { sg = sg * fexp(mg - xg) + 1.f; mg = xg; }
            else           sg += fexp(xg - mg);
            mp = fmaxf(mp, xp);
        }
        float ll = xlab - (mg + logf(sg));
        if (l >= 1) {
            contrib = -ll;
            out[OUT_PL + (size_t)b * NL + l - 1] = mp;
        }
    }
    red[threadIdx.x] = contrib;
    __syncthreads();
    for (int s = 128; s; s >>= 1) {
        if (threadIdx.x < s) red[threadIdx.x] += red[threadIdx.x + s];
        __syncthreads();
    }
    if (!threadIdx.x) g_partB[blockIdx.x] = red[0];
}

/* ===== K7: labels1 output + deterministic NLL finalize ===== */
__global__ __launch_bounds__(256) void k_final(
    const int* __restrict__ elabels, float* __restrict__ out)
{
    const int i = blockIdx.x * 256 + threadIdx.x;
    if (i < NT) {
        int b = i / L1, l = i % L1;
        out[OUT_LB + i] = (l == 0) ? 0.f : (float)elabels[b * NL + l - 1];
    }
    if (i == 0) {
        float s = 0.f;
        for (int k = 0; k < 17 * 64; k++) s += g_partA[k];
        out[OUT_NN] = s;
        float s2 = 0.f;
        for (int k = 0; k < 129; k++) s2 += g_partB[k];
        out[OUT_LN] = s2;
    }
}

extern "C" void kernel_launch(void* const* d_in, const int* in_sizes, int n_in,
                              void* d_out, int out_size)
{
    const float* mem    = (const float*)d_in[0];
    const int*   eheads = (const int*)d_in[1];
    const int*   elabs  = (const int*)d_in[2];
    const int*   mask   = (const int*)d_in[4];
    const float* sent   = (const float*)d_in[5];
    const float* Wenh = (const float*)d_in[6];  const float* benh = (const float*)d_in[7];
    const float* Wenm = (const float*)d_in[8];  const float* benm = (const float*)d_in[9];
    const float* Welh = (const float*)d_in[10]; const float* belh = (const float*)d_in[11];
    const float* Welm = (const float*)d_in[12]; const float* belm = (const float*)d_in[13];
    const float* baU  = (const float*)d_in[14];
    const float* baWd = (const float*)d_in[15];
    const float* baWe = (const float*)d_in[16];
    const float* bab  = (const float*)d_in[17];
    const float* lU   = (const float*)d_in[18];
    const float* lWl  = (const float*)d_in[19];
    const float* lWr  = (const float*)d_in[20];
    const float* lb   = (const float*)d_in[21];
    float* out = (float*)d_out;

    cudaFuncSetAttribute(k_bilin_mma, cudaFuncAttributeMaxDynamicSharedMemorySize, SMB2_BYTES);
    cudaFuncSetAttribute(k_enc_mma, cudaFuncAttributeMaxDynamicSharedMemorySize, SME3_BYTES);
    cudaFuncSetAttribute(k_tmp_mma, cudaFuncAttributeMaxDynamicSharedMemorySize, SME3_BYTES);
    cudaFuncSetAttribute(k_ns_mma,  cudaFuncAttributeMaxDynamicSharedMemorySize, SME3_BYTES);

    k_trans<<<1504, 256>>>(Wenh, Wenm, Welh, Welm, benh, benm, belh, belm, baU);
    k_uh<<<2048, 256>>>(lU);
    k_msplit<<<53352, 256>>>(mem, sent);
    k_enc_mma<<<dim3(257, 6), 256, SME3_BYTES>>>();
    k_tmp_mma<<<dim3(257, 2), 256, SME3_BYTES>>>();
    k_dotvec<<<4104, 256>>>(baWd, baWe);
    k_ns_mma<<<dim3(4, 4, 64), 256, SME3_BYTES>>>(bab);
    k_strip<<<8200, 256>>>(bab);
    k_node_reduce<<<dim3(17, 64), 256>>>(eheads, mask, out);
    k_lin<<<dim3(513, 2), 256>>>(lWr, lb);
    k_bilin_mma<<<dim3(NTILES, 8), 256, SMB2_BYTES>>>(lWl, eheads);
    k_lbl_reduce<<<129, 256>>>(elabs, out);
    k_final<<<129, 256>>>(elabs, out);
}